// round 10
// baseline (speedup 1.0000x reference)
#include <cuda_runtime.h>
#include <cuda_bf16.h>
#include <cstdint>

#define Nn 50000
#define Ee 640000
#define Dd 128

#define ASTRIDE 136              // uint16 elems per row (128 + 8 pad)
#define ROWB    (ASTRIDE * 2)    // 272 bytes per row
#define WPLANE  (128 * ASTRIDE)  // uint16 elems per W plane
#define NT_E    (Ee / 32)        // 20000 edge tiles
#define NT_N    ((Nn + 31) / 32) // 1563 node tiles
#define NBLK_E  296              // persistent edge grid (2 per SM, one wave)

// ---------------- device scratch ------------------------------------------
__device__ float g_U[Nn * 128];
__device__ float g_B[Nn * 128];
__device__ float g_CV[Nn * 256];                 // [Cx | Vx]
__device__ float g_agg[Nn * 128];
__device__ float g_stats[1024];
__device__ int g_arrive;
__device__ __align__(16) uint16_t g_Wp[5 * 2 * WPLANE]; // pre-split W hi/lo planes
__device__ int g_is64;

// ---------------- smem layout (bytes) --------------------------------------
#define SB_BIAS 0                 // 512
#define SB_IDX  512               // 64 ints
#define SB_GB   1024              // gamma 512 + beta 512
#define SB_F32  2048              // 2 x 16384 fp32 A staging (cp.async)
#define SB_BF16 34816             // hi 8704 + lo 8704
#define SB_ACC  52224             // 32 x 132 fp32 = 16896
#define S_SIZE_N 52224            // node kernel
#define S_SIZE_E 69120            // edge kernel (includes ACC)

// ---------------- PTX helpers ------------------------------------------------
__device__ __forceinline__ uint32_t smem_u32(const void* p) {
    uint32_t a;
    asm("{ .reg .u64 t; cvta.to.shared.u64 t, %1; cvt.u32.u64 %0, t; }" : "=r"(a) : "l"(p));
    return a;
}
__device__ __forceinline__ void ldsm4(uint32_t& r0, uint32_t& r1, uint32_t& r2,
                                      uint32_t& r3, uint32_t addr) {
    asm volatile("ldmatrix.sync.aligned.m8n8.x4.shared.b16 {%0,%1,%2,%3}, [%4];"
                 : "=r"(r0), "=r"(r1), "=r"(r2), "=r"(r3) : "r"(addr));
}
__device__ __forceinline__ void mma_bf16(float* d, uint32_t a0, uint32_t a1,
                                         uint32_t a2, uint32_t a3,
                                         uint32_t b0, uint32_t b1) {
    asm volatile("mma.sync.aligned.m16n8k16.row.col.f32.bf16.bf16.f32 "
        "{%0,%1,%2,%3}, {%4,%5,%6,%7}, {%8,%9}, {%0,%1,%2,%3};"
        : "+f"(d[0]), "+f"(d[1]), "+f"(d[2]), "+f"(d[3])
        : "r"(a0), "r"(a1), "r"(a2), "r"(a3), "r"(b0), "r"(b1));
}
__device__ __forceinline__ void cp_async16(uint32_t saddr, const void* gptr) {
    asm volatile("cp.async.cg.shared.global [%0], [%1], 16;" :: "r"(saddr), "l"(gptr));
}
#define CP_COMMIT() asm volatile("cp.async.commit_group;" ::: "memory")
#define CP_WAIT0()  asm volatile("cp.async.wait_group 0;" ::: "memory")

// stage a 32x128 fp32 tile via cp.async; OOB rows clamp to row 0 (guarded later)
__device__ __forceinline__ void cpa_tile(uint32_t sdst, const float* __restrict__ src,
                                         int valid_rows) {
#pragma unroll
    for (int p = 0; p < 4; p++) {
        int idx = p * 256 + threadIdx.x;
        int row = idx >> 5;
        const float4* g = (const float4*)src + (row < valid_rows ? idx : (idx & 31));
        cp_async16(sdst + idx * 16, g);
    }
}
// convert fp32 smem tile -> hi/lo bf16 planes in smem
__device__ __forceinline__ void cvt_smem(uint16_t* __restrict__ hi_dst,
                                         uint16_t* __restrict__ lo_dst,
                                         const float* __restrict__ srcf) {
#pragma unroll
    for (int p = 0; p < 4; p++) {
        int idx = p * 256 + threadIdx.x;
        int row = idx >> 5, k4 = (idx & 31) << 2;
        float4 v = ((const float4*)srcf)[idx];
        __nv_bfloat16 h0 = __float2bfloat16(v.x), h1 = __float2bfloat16(v.y);
        __nv_bfloat16 h2 = __float2bfloat16(v.z), h3 = __float2bfloat16(v.w);
        __nv_bfloat16 l0 = __float2bfloat16(v.x - __bfloat162float(h0));
        __nv_bfloat16 l1 = __float2bfloat16(v.y - __bfloat162float(h1));
        __nv_bfloat16 l2 = __float2bfloat16(v.z - __bfloat162float(h2));
        __nv_bfloat16 l3 = __float2bfloat16(v.w - __bfloat162float(h3));
        uint2 hi, lo;
        hi.x = ((uint32_t)__bfloat16_as_ushort(h1) << 16) | __bfloat16_as_ushort(h0);
        hi.y = ((uint32_t)__bfloat16_as_ushort(h3) << 16) | __bfloat16_as_ushort(h2);
        lo.x = ((uint32_t)__bfloat16_as_ushort(l1) << 16) | __bfloat16_as_ushort(l0);
        lo.y = ((uint32_t)__bfloat16_as_ushort(l3) << 16) | __bfloat16_as_ushort(l2);
        *(uint2*)(hi_dst + row * ASTRIDE + k4) = hi;
        *(uint2*)(lo_dst + row * ASTRIDE + k4) = lo;
    }
}
__device__ __forceinline__ int ld_idx(const void* p, size_t i, int is64) {
    return is64 ? (int)((const long long*)p)[i] : ((const int*)p)[i];
}

// stage W planes (one-time) and load this warp's B fragments into registers
__device__ __forceinline__ void load_breg(char* sm, uint32_t smb, int mtx,
                                          int wid, int lane,
                                          uint32_t bh[8][4], uint32_t bl[8][4]) {
    const int nb = wid * 16;
    const uint32_t woffs = smb + SB_F32
        + (uint32_t)(nb + (lane & 7) + ((lane >> 4) << 3)) * ROWB
        + (((lane >> 3) & 1) << 4);
    uint4* d = (uint4*)(sm + SB_F32);
    {
        const uint4* s = (const uint4*)(g_Wp + (size_t)mtx * 2 * WPLANE);
        for (int i = threadIdx.x; i < 2176; i += 256) d[i] = s[i];
        __syncthreads();
#pragma unroll
        for (int ks = 0; ks < 8; ks++)
            ldsm4(bh[ks][0], bh[ks][1], bh[ks][2], bh[ks][3], woffs + ks * 32);
        __syncthreads();
    }
    {
        const uint4* s = (const uint4*)(g_Wp + ((size_t)mtx * 2 + 1) * WPLANE);
        for (int i = threadIdx.x; i < 2176; i += 256) d[i] = s[i];
        __syncthreads();
#pragma unroll
        for (int ks = 0; ks < 8; ks++)
            ldsm4(bl[ks][0], bl[ks][1], bl[ks][2], bl[ks][3], woffs + ks * 32);
        __syncthreads();
    }
}

// 3-term MMA over a 32x128 tile with B cached in registers
__device__ __forceinline__ void mma_tile(uint32_t ah_base, uint32_t al_base,
                                         const uint32_t bh[8][4], const uint32_t bl[8][4],
                                         int lane, float acc[2][2][4]) {
#pragma unroll
    for (int mg = 0; mg < 2; mg++)
#pragma unroll
        for (int j = 0; j < 2; j++)
#pragma unroll
            for (int q = 0; q < 4; q++) acc[mg][j][q] = 0.f;
    const uint32_t aoff = (uint32_t)(lane & 15) * ROWB + ((lane >> 4) << 4);
#pragma unroll
    for (int ks = 0; ks < 8; ks++) {
#pragma unroll
        for (int mg = 0; mg < 2; mg++) {
            uint32_t a0, a1, a2, a3;
            ldsm4(a0, a1, a2, a3, ah_base + aoff + mg * 16 * ROWB + ks * 32);
            mma_bf16(acc[mg][0], a0, a1, a2, a3, bh[ks][0], bh[ks][1]);
            mma_bf16(acc[mg][1], a0, a1, a2, a3, bh[ks][2], bh[ks][3]);
            mma_bf16(acc[mg][0], a0, a1, a2, a3, bl[ks][0], bl[ks][1]);
            mma_bf16(acc[mg][1], a0, a1, a2, a3, bl[ks][2], bl[ks][3]);
            uint32_t c0, c1, c2, c3;
            ldsm4(c0, c1, c2, c3, al_base + aoff + mg * 16 * ROWB + ks * 32);
            mma_bf16(acc[mg][0], c0, c1, c2, c3, bh[ks][0], bh[ks][1]);
            mma_bf16(acc[mg][1], c0, c1, c2, c3, bh[ks][2], bh[ks][3]);
        }
    }
}
// dump accumulators to 32x132 smem tile
__device__ __forceinline__ void dump_acc(float* sacc, const float acc[2][2][4],
                                         int wid, int lane) {
    const int gid = lane >> 2, tig = lane & 3;
    const int nb = wid * 16;
#pragma unroll
    for (int mg = 0; mg < 2; mg++) {
        int r = mg * 16 + gid;
#pragma unroll
        for (int j = 0; j < 2; j++) {
            int c = nb + j * 8 + tig * 2;
            *(float2*)(sacc + r * 132 + c) = make_float2(acc[mg][j][0], acc[mg][j][1]);
            *(float2*)(sacc + (r + 8) * 132 + c) = make_float2(acc[mg][j][2], acc[mg][j][3]);
        }
    }
}

// ---------------- small kernels -----------------------------------------------
__global__ void detect_kernel(const unsigned* __restrict__ w) {
    __shared__ int sflag;
    if (threadIdx.x == 0) sflag = 0;
    __syncthreads();
    unsigned v = 0;
    for (int i = threadIdx.x; i < 2048; i += blockDim.x) v |= w[2 * i + 1];
    if (v) atomicOr(&sflag, 1);
    __syncthreads();
    if (threadIdx.x == 0) g_is64 = sflag ? 0 : 1;
}
__global__ void zero_kernel() {
    int i = blockIdx.x * blockDim.x + threadIdx.x;
    const int total = Nn * 128;
    for (int k = i; k < total; k += gridDim.x * blockDim.x) g_agg[k] = 0.f;
    if (i < 1024) g_stats[i] = 0.f;
    if (i == 0) g_arrive = 0;
}
__global__ void prep_w_kernel(const float* __restrict__ Wu, const float* __restrict__ Wv,
                              const float* __restrict__ WB, const float* __restrict__ WC,
                              const float* __restrict__ WA) {
    int mtx = blockIdx.x;
    const float* W = (mtx == 0) ? Wu : (mtx == 1) ? Wv : (mtx == 2) ? WB : (mtx == 3) ? WC : WA;
    uint16_t* hi = g_Wp + (size_t)mtx * 2 * WPLANE;
    uint16_t* lo = hi + WPLANE;
    for (int idx = threadIdx.x; idx < 16384; idx += blockDim.x) {
        int f = idx >> 7, k = idx & 127;
        float w = W[idx];
        __nv_bfloat16 h = __float2bfloat16(w);
        __nv_bfloat16 l = __float2bfloat16(w - __bfloat162float(h));
        hi[f * ASTRIDE + k] = __bfloat16_as_ushort(h);
        lo[f * ASTRIDE + k] = __bfloat16_as_ushort(l);
    }
}

// ---------------- node GEMMs: persistent, cp.async pipelined, B-in-regs ----------
__global__ void __launch_bounds__(256, 2) node_mma_kernel(
        const float* __restrict__ x, const float* __restrict__ bu,
        const float* __restrict__ bv, const float* __restrict__ bB,
        const float* __restrict__ bC) {
    extern __shared__ char sm[];
    uint32_t smb = smem_u32(sm);
    const int tid = threadIdx.x, wid = tid >> 5, lane = tid & 31;
    const int which = blockIdx.y;
    float* sb = (float*)(sm + SB_BIAS);
    const float* bias = (which == 0) ? bu : (which == 1) ? bv : (which == 2) ? bB : bC;
    if (tid < 128) sb[tid] = bias[tid];

    uint32_t bh[8][4], bl[8][4];
    load_breg(sm, smb, which, wid, lane, bh, bl);

    float* dst0;
    int rstride;
    if (which == 0)      { dst0 = g_U;        rstride = 128; }
    else if (which == 1) { dst0 = g_CV + 128; rstride = 256; }
    else if (which == 2) { dst0 = g_B;        rstride = 128; }
    else                 { dst0 = g_CV;       rstride = 256; }

    const int gid = lane >> 2, tig = lane & 3;
    const int nb = wid * 16;

    long t = blockIdx.x;
    if (t < NT_N) {
        int v0 = Nn - (int)t * 32; if (v0 > 32) v0 = 32;
        cpa_tile(smb + SB_F32, x + t * 4096, v0);
    }
    CP_COMMIT();
    int ib = 0;
    for (; t < NT_N; t += gridDim.x) {
        CP_WAIT0();
        __syncthreads();
        uint16_t* Ah = (uint16_t*)(sm + SB_BF16);
        cvt_smem(Ah, Ah + 4352, (const float*)(sm + SB_F32 + ib * 16384));
        long tn = t + gridDim.x;
        if (tn < NT_N) {
            int vn = Nn - (int)tn * 32; if (vn > 32) vn = 32;
            cpa_tile(smb + SB_F32 + (ib ^ 1) * 16384, x + tn * 4096, vn);
        }
        CP_COMMIT();
        __syncthreads();
        float acc[2][2][4];
        mma_tile(smb + SB_BF16, smb + SB_BF16 + 8704, bh, bl, lane, acc);
#pragma unroll
        for (int mg = 0; mg < 2; mg++) {
            const int r0 = (int)t * 32 + mg * 16 + gid;
#pragma unroll
            for (int j = 0; j < 2; j++) {
                int c = nb + j * 8 + tig * 2;
                float2 bb = *(const float2*)(sb + c);
                if (r0 < Nn)
                    *(float2*)(dst0 + (size_t)r0 * rstride + c) =
                        make_float2(acc[mg][j][0] + bb.x, acc[mg][j][1] + bb.y);
                if (r0 + 8 < Nn)
                    *(float2*)(dst0 + (size_t)(r0 + 8) * rstride + c) =
                        make_float2(acc[mg][j][2] + bb.x, acc[mg][j][3] + bb.y);
            }
        }
        ib ^= 1;
    }
}

// ---------------- fused edge kernel: phase1 stats, grid sync, phase2 output --------
__global__ void __launch_bounds__(256, 2) edge_fused_kernel(
        const float* __restrict__ ea, const void* __restrict__ eidx,
        const float* __restrict__ bA, const float* __restrict__ ge_g,
        const float* __restrict__ ge_b, float* __restrict__ out_e) {
    extern __shared__ char sm[];
    uint32_t smb = smem_u32(sm);
    const int tid = threadIdx.x, wid = tid >> 5, lane = tid & 31;
    const int is64 = g_is64;
    float* sb = (float*)(sm + SB_BIAS);
    int* sidx = (int*)(sm + SB_IDX);
    float* sgm = (float*)(sm + SB_GB);
    float* sbt = sgm + 128;
    float* sacc = (float*)(sm + SB_ACC);
    if (tid < 128) { sb[tid] = bA[tid]; sgm[tid] = ge_g[tid]; sbt[tid] = ge_b[tid]; }

    uint32_t bh[8][4], bl[8][4];
    load_breg(sm, smb, 4, wid, lane, bh, bl);   // ends with syncthreads

    const float4 bias4 = *(const float4*)(sb + lane * 4);
    float s1[4] = {0.f, 0.f, 0.f, 0.f};
    float s2[4] = {0.f, 0.f, 0.f, 0.f};

    // ---- phase 1: BN statistics only ----
    long t = blockIdx.x;
    int idxreg = 0;
    if (t < NT_E) {
        cpa_tile(smb + SB_F32, ea + t * 4096, 32);
        if (tid < 64)
            idxreg = ld_idx(eidx, (tid < 32) ? (t * 32 + tid)
                                             : ((size_t)Ee + t * 32 + (tid - 32)), is64);
    }
    CP_COMMIT();
    int ib = 0;
    for (; t < NT_E; t += gridDim.x) {
        CP_WAIT0();
        __syncthreads();
        if (tid < 64) sidx[tid] = idxreg;
        uint16_t* Ah = (uint16_t*)(sm + SB_BF16);
        cvt_smem(Ah, Ah + 4352, (const float*)(sm + SB_F32 + ib * 16384));
        long tn = t + gridDim.x;
        if (tn < NT_E) {
            cpa_tile(smb + SB_F32 + (ib ^ 1) * 16384, ea + tn * 4096, 32);
            if (tid < 64)
                idxreg = ld_idx(eidx, (tid < 32) ? (tn * 32 + tid)
                                                 : ((size_t)Ee + tn * 32 + (tid - 32)), is64);
        }
        CP_COMMIT();
        __syncthreads();
        float acc[2][2][4];
        mma_tile(smb + SB_BF16, smb + SB_BF16 + 8704, bh, bl, lane, acc);
        dump_acc(sacc, acc, wid, lane);
        __syncthreads();
#pragma unroll
        for (int k = 0; k < 4; k++) {
            int r = wid * 4 + k;
            int ridx = sidx[r], cidx = sidx[32 + r];
            float4 a = *(const float4*)(sacc + r * 132 + lane * 4);
            float4 b = *(const float4*)(g_B + (size_t)ridx * 128 + lane * 4);
            float4 cg = *(const float4*)(g_CV + (size_t)cidx * 256 + lane * 4);
            float vx = a.x + bias4.x + b.x + cg.x;
            float vy = a.y + bias4.y + b.y + cg.y;
            float vz = a.z + bias4.z + b.z + cg.z;
            float vw = a.w + bias4.w + b.w + cg.w;
            s1[0] += vx; s2[0] = fmaf(vx, vx, s2[0]);
            s1[1] += vy; s2[1] = fmaf(vy, vy, s2[1]);
            s1[2] += vz; s2[2] = fmaf(vz, vz, s2[2]);
            s1[3] += vw; s2[3] = fmaf(vw, vw, s2[3]);
        }
        ib ^= 1;
    }

    // ---- block reduce + global stats ----
    __syncthreads();
#pragma unroll
    for (int q = 0; q < 4; q++) {
        sacc[wid * 128 + lane * 4 + q] = s1[q];
        sacc[1024 + wid * 128 + lane * 4 + q] = s2[q];
    }
    __syncthreads();
    if (tid < 128) {
        float a = 0.f, b = 0.f;
#pragma unroll
        for (int w = 0; w < 8; w++) {
            a += sacc[w * 128 + tid];
            b += sacc[1024 + w * 128 + tid];
        }
        atomicAdd(&g_stats[tid], a);
        atomicAdd(&g_stats[128 + tid], b);
    }
    __syncthreads();

    // ---- grid-wide sync (all 296 blocks co-resident) ----
    if (tid == 0) {
        __threadfence();
        atomicAdd(&g_arrive, 1);
        volatile int* p = &g_arrive;
        while (*p < (int)gridDim.x) {}
    }
    __syncthreads();
    __threadfence();

    // per-thread mean/rstd for owned columns lane*4..+3
    const float invE = 1.f / (float)Ee;
    float mu_[4], rs_[4];
#pragma unroll
    for (int q = 0; q < 4; q++) {
        float s = __ldcg(&g_stats[lane * 4 + q]);
        float ss = __ldcg(&g_stats[128 + lane * 4 + q]);
        float m = s * invE;
        float var = fmaxf(ss * invE - m * m, 0.f);
        mu_[q] = m;
        rs_[q] = rsqrtf(var + 1e-5f);
    }
    const float4 gm4 = *(const float4*)(sgm + lane * 4);
    const float4 bt4 = *(const float4*)(sbt + lane * 4);

    // ---- phase 2: recompute, normalize, output, messages ----
    t = blockIdx.x;
    if (t < NT_E) {
        cpa_tile(smb + SB_F32 + ib * 16384, ea + t * 4096, 32);
        if (tid < 64)
            idxreg = ld_idx(eidx, (tid < 32) ? (t * 32 + tid)
                                             : ((size_t)Ee + t * 32 + (tid - 32)), is64);
    }
    CP_COMMIT();
    for (; t < NT_E; t += gridDim.x) {
        CP_WAIT0();
        __syncthreads();
        if (tid < 64) sidx[tid] = idxreg;
        uint16_t* Ah = (uint16_t*)(sm + SB_BF16);
        cvt_smem(Ah, Ah + 4352, (const float*)(sm + SB_F32 + ib * 16384));
        long tn = t + gridDim.x;
        if (tn < NT_E) {
            cpa_tile(smb + SB_F32 + (ib ^ 1) * 16384, ea + tn * 4096, 32);
            if (tid < 64)
                idxreg = ld_idx(eidx, (tid < 32) ? (tn * 32 + tid)
                                                 : ((size_t)Ee + tn * 32 + (tid - 32)), is64);
        }
        CP_COMMIT();
        __syncthreads();
        float acc[2][2][4];
        mma_tile(smb + SB_BF16, smb + SB_BF16 + 8704, bh, bl, lane, acc);
        dump_acc(sacc, acc, wid, lane);
        __syncthreads();
        const float* fcur = (const float*)(sm + SB_F32 + ib * 16384);
#pragma unroll
        for (int k = 0; k < 4; k++) {
            int r = wid * 4 + k;
            int ridx = sidx[r], cidx = sidx[32 + r];
            float4 a = *(const float4*)(sacc + r * 132 + lane * 4);
            float4 b = *(const float4*)(g_B + (size_t)ridx * 128 + lane * 4);
            float4 cg = *(const float4*)(g_CV + (size_t)cidx * 256 + lane * 4);
            float vx = a.x + bias4.x + b.x + cg.x;
            float vy = a.y + bias4.y + b.y + cg.y;
            float vz = a.z + bias4.z + b.z + cg.z;
            float vw = a.w + bias4.w + b.w + cg.w;
            float4 ea4 = *(const float4*)(fcur + r * 128 + lane * 4);
            float4 eo;
            eo.x = ea4.x + fmaxf(gm4.x * (vx - mu_[0]) * rs_[0] + bt4.x, 0.f);
            eo.y = ea4.y + fmaxf(gm4.y * (vy - mu_[1]) * rs_[1] + bt4.y, 0.f);
            eo.z = ea4.z + fmaxf(gm4.z * (vz - mu_[2]) * rs_[2] + bt4.z, 0.f);
            eo.w = ea4.w + fmaxf(gm4.w * (vw - mu_[3]) * rs_[3] + bt4.w, 0.f);
            *(float4*)(out_e + (t * 32 + r) * 128 + lane * 4) = eo;
            float4 vv = *(const float4*)(g_CV + (size_t)cidx * 256 + 128 + lane * 4);
            float mx = vv.x / (1.f + __expf(-eo.x));
            float my = vv.y / (1.f + __expf(-eo.y));
            float mz = vv.z / (1.f + __expf(-eo.z));
            float mw = vv.w / (1.f + __expf(-eo.w));
            float* dst = g_agg + (size_t)ridx * 128 + lane * 4;
            asm volatile("red.global.add.v4.f32 [%0], {%1, %2, %3, %4};"
                         :: "l"(dst), "f"(mx), "f"(my), "f"(mz), "f"(mw) : "memory");
        }
        ib ^= 1;
    }
}

// ---------------- finalize node BN stats ----------------------------------------
__global__ void finalize_kernel(int which, float inv) {
    int f = threadIdx.x;
    float s1 = g_stats[which * 256 + f];
    float s2 = g_stats[which * 256 + 128 + f];
    float mean = s1 * inv;
    float var = fmaxf(s2 * inv - mean * mean, 0.f);
    g_stats[512 + which * 256 + f] = mean;
    g_stats[512 + which * 256 + 128 + f] = rsqrtf(var + 1e-5f);
}

// ---------------- node stats / output ---------------------------------------------------
__global__ void node_stats_kernel() {
    int f = threadIdx.x;
    int n0 = blockIdx.x * 64;
    float s1 = 0.f, s2 = 0.f;
    for (int r = 0; r < 64; r++) {
        int n = n0 + r;
        if (n < Nn) {
            float v = g_U[(size_t)n * 128 + f] + g_agg[(size_t)n * 128 + f];
            s1 += v;
            s2 += v * v;
        }
    }
    atomicAdd(&g_stats[256 + f], s1);
    atomicAdd(&g_stats[384 + f], s2);
}
__global__ void node_out_kernel(const float* __restrict__ x, const float* __restrict__ gam,
                                const float* __restrict__ bet, float* __restrict__ out_x) {
    int i = blockIdx.x * blockDim.x + threadIdx.x;
    if (i >= Nn * 32) return;
    int c = (i & 31) * 4;
    size_t base = (size_t)i * 4;
    float4 u = *(const float4*)(g_U + base);
    float4 a = *(const float4*)(g_agg + base);
    float4 mu = *(const float4*)(g_stats + 768 + c);
    float4 rs = *(const float4*)(g_stats + 896 + c);
    float4 gm = __ldg((const float4*)(gam + c));
    float4 bt = __ldg((const float4*)(bet + c));
    float4 xv = __ldg((const float4*)(x + base));
    float4 o;
    o.x = xv.x + fmaxf(gm.x * ((u.x + a.x) - mu.x) * rs.x + bt.x, 0.f);
    o.y = xv.y + fmaxf(gm.y * ((u.y + a.y) - mu.y) * rs.y + bt.y, 0.f);
    o.z = xv.z + fmaxf(gm.z * ((u.z + a.z) - mu.z) * rs.z + bt.z, 0.f);
    o.w = xv.w + fmaxf(gm.w * ((u.w + a.w) - mu.w) * rs.w + bt.w, 0.f);
    *(float4*)(out_x + base) = o;
}

// ---------------- launch -----------------------------------------------------------------
extern "C" void kernel_launch(void* const* d_in, const int* in_sizes, int n_in,
                              void* d_out, int out_size) {
    (void)in_sizes; (void)n_in; (void)out_size;
    const float* x  = (const float*)d_in[0];
    const void*  ei = d_in[1];
    const float* ea = (const float*)d_in[2];
    const float* Wu = (const float*)d_in[3];
    const float* bu = (const float*)d_in[4];
    const float* Wv = (const float*)d_in[5];
    const float* bv = (const float*)d_in[6];
    const float* WA = (const float*)d_in[7];
    const float* bA = (const float*)d_in[8];
    const float* WB = (const float*)d_in[9];
    const float* bB = (const float*)d_in[10];
    const float* WC = (const float*)d_in[11];
    const float* bC = (const float*)d_in[12];
    const float* gn_g = (const float*)d_in[13];
    const float* gn_b = (const float*)d_in[14];
    const float* ge_g = (const float*)d_in[15];
    const float* ge_b = (const float*)d_in[16];

    float* out   = (float*)d_out;
    float* out_x = out;
    float* out_e = out + (size_t)Nn * Dd;

    cudaFuncSetAttribute(node_mma_kernel, cudaFuncAttributeMaxDynamicSharedMemorySize, S_SIZE_N);
    cudaFuncSetAttribute(edge_fused_kernel, cudaFuncAttributeMaxDynamicSharedMemorySize, S_SIZE_E);

    detect_kernel<<<1, 256>>>((const unsigned*)ei);
    zero_kernel<<<2048, 256>>>();
    prep_w_kernel<<<5, 256>>>(Wu, Wv, WB, WC, WA);
    node_mma_kernel<<<dim3(74, 4), 256, S_SIZE_N>>>(x, bu, bv, bB, bC);
    edge_fused_kernel<<<NBLK_E, 256, S_SIZE_E>>>(ea, ei, bA, ge_g, ge_b, out_e);
    node_stats_kernel<<<(Nn + 63) / 64, 128>>>();
    finalize_kernel<<<1, 128>>>(1, 1.0f / (float)Nn);
    node_out_kernel<<<(Nn * 32 + 255) / 256, 256>>>(x, gn_g, gn_b, out_x);
}

// round 11
// speedup vs baseline: 1.2897x; 1.2897x over previous
#include <cuda_runtime.h>
#include <cuda_bf16.h>
#include <cstdint>

#define Nn 50000
#define Ee 640000
#define Dd 128

#define ASTRIDE 136              // uint16 elems per row (128 + 8 pad)
#define ROWB    (ASTRIDE * 2)    // 272 bytes per row
#define WPLANE  (128 * ASTRIDE)  // uint16 elems per W plane
#define NT_E    (Ee / 32)        // 20000 edge tiles
#define NT_N    ((Nn + 31) / 32) // 1563 node tiles

// ---------------- device scratch ------------------------------------------
__device__ float g_U[Nn * 128];
__device__ float g_B[Nn * 128];
__device__ float g_CV[Nn * 256];                 // [Cx | Vx]
__device__ float g_edge_in[(size_t)Ee * 128];
__device__ float g_agg[Nn * 128];
__device__ float g_stats[1024];
__device__ __align__(16) uint16_t g_Wp[5 * 2 * WPLANE]; // pre-split W hi/lo planes
__device__ int g_is64;

// ---------------- smem layout (bytes) --------------------------------------
#define SB_BIAS 0                 // 512
#define SB_IDX  512               // 2 x 64 ints (double buffered)
#define SB_BF16 1024              // Ah 8704 + Al 8704 = 17408
#define SB_WL   18432             // W lo plane 34816 (also hi staging at startup)
#define SB_ACC  53248             // 32 x 132 fp32 = 16896 (edge only)
#define S_SIZE_E 70144
#define S_SIZE_N 53248

// ---------------- PTX helpers ------------------------------------------------
__device__ __forceinline__ uint32_t smem_u32(const void* p) {
    uint32_t a;
    asm("{ .reg .u64 t; cvta.to.shared.u64 t, %1; cvt.u32.u64 %0, t; }" : "=r"(a) : "l"(p));
    return a;
}
__device__ __forceinline__ void ldsm4(uint32_t& r0, uint32_t& r1, uint32_t& r2,
                                      uint32_t& r3, uint32_t addr) {
    asm volatile("ldmatrix.sync.aligned.m8n8.x4.shared.b16 {%0,%1,%2,%3}, [%4];"
                 : "=r"(r0), "=r"(r1), "=r"(r2), "=r"(r3) : "r"(addr));
}
__device__ __forceinline__ void mma_bf16(float* d, uint32_t a0, uint32_t a1,
                                         uint32_t a2, uint32_t a3,
                                         uint32_t b0, uint32_t b1) {
    asm volatile("mma.sync.aligned.m16n8k16.row.col.f32.bf16.bf16.f32 "
        "{%0,%1,%2,%3}, {%4,%5,%6,%7}, {%8,%9}, {%0,%1,%2,%3};"
        : "+f"(d[0]), "+f"(d[1]), "+f"(d[2]), "+f"(d[3])
        : "r"(a0), "r"(a1), "r"(a2), "r"(a3), "r"(b0), "r"(b1));
}

// prefetch a 32x128 fp32 tile into 4 float4 regs per thread (256 threads)
__device__ __forceinline__ void load_regs(float4* pre, const float* __restrict__ src,
                                          int valid_rows) {
#pragma unroll
    for (int p = 0; p < 4; p++) {
        int idx = p * 256 + threadIdx.x;
        int row = idx >> 5;
        pre[p] = (row < valid_rows) ? ((const float4*)src)[idx]
                                    : make_float4(0.f, 0.f, 0.f, 0.f);
    }
}
// convert prefetched regs -> hi/lo bf16 planes in smem
__device__ __forceinline__ void cvt_store(uint16_t* __restrict__ hi_dst,
                                          uint16_t* __restrict__ lo_dst,
                                          const float4* pre) {
#pragma unroll
    for (int p = 0; p < 4; p++) {
        int idx = p * 256 + threadIdx.x;
        int row = idx >> 5, k4 = (idx & 31) << 2;
        float4 v = pre[p];
        __nv_bfloat16 h0 = __float2bfloat16(v.x), h1 = __float2bfloat16(v.y);
        __nv_bfloat16 h2 = __float2bfloat16(v.z), h3 = __float2bfloat16(v.w);
        __nv_bfloat16 l0 = __float2bfloat16(v.x - __bfloat162float(h0));
        __nv_bfloat16 l1 = __float2bfloat16(v.y - __bfloat162float(h1));
        __nv_bfloat16 l2 = __float2bfloat16(v.z - __bfloat162float(h2));
        __nv_bfloat16 l3 = __float2bfloat16(v.w - __bfloat162float(h3));
        uint2 hi, lo;
        hi.x = ((uint32_t)__bfloat16_as_ushort(h1) << 16) | __bfloat16_as_ushort(h0);
        hi.y = ((uint32_t)__bfloat16_as_ushort(h3) << 16) | __bfloat16_as_ushort(h2);
        lo.x = ((uint32_t)__bfloat16_as_ushort(l1) << 16) | __bfloat16_as_ushort(l0);
        lo.y = ((uint32_t)__bfloat16_as_ushort(l3) << 16) | __bfloat16_as_ushort(l2);
        *(uint2*)(hi_dst + row * ASTRIDE + k4) = hi;
        *(uint2*)(lo_dst + row * ASTRIDE + k4) = lo;
    }
}
__device__ __forceinline__ int ld_idx(const void* p, size_t i, int is64) {
    return is64 ? (int)((const long long*)p)[i] : ((const int*)p)[i];
}

// Stage W hi plane into SB_WL, ldmatrix this warp's hi fragments into regs,
// then overwrite SB_WL with the lo plane (kept resident for the whole kernel).
__device__ __forceinline__ void load_w3(char* sm, uint32_t smb, int mtx,
                                        int wid, int lane, uint32_t bh[8][4]) {
    const uint32_t woffs = smb + SB_WL
        + (uint32_t)(wid * 16 + (lane & 7) + ((lane >> 4) << 3)) * ROWB
        + (((lane >> 3) & 1) << 4);
    uint4* d = (uint4*)(sm + SB_WL);
    {
        const uint4* s = (const uint4*)(g_Wp + (size_t)mtx * 2 * WPLANE);
        for (int i = threadIdx.x; i < 2176; i += 256) d[i] = s[i];
        __syncthreads();
#pragma unroll
        for (int ks = 0; ks < 8; ks++)
            ldsm4(bh[ks][0], bh[ks][1], bh[ks][2], bh[ks][3], woffs + ks * 32);
        __syncthreads();
    }
    {
        const uint4* s = (const uint4*)(g_Wp + ((size_t)mtx * 2 + 1) * WPLANE);
        for (int i = threadIdx.x; i < 2176; i += 256) d[i] = s[i];
        __syncthreads();
    }
}

// 3-term MMA over a 32x128 tile: bh in regs, bl via ldmatrix from resident smem plane
__device__ __forceinline__ void mma_tile3(uint32_t ah_base, uint32_t al_base,
                                          uint32_t wl_base, const uint32_t bh[8][4],
                                          int wid, int lane, float acc[2][2][4]) {
#pragma unroll
    for (int mg = 0; mg < 2; mg++)
#pragma unroll
        for (int j = 0; j < 2; j++)
#pragma unroll
            for (int q = 0; q < 4; q++) acc[mg][j][q] = 0.f;
    const uint32_t aoff = (uint32_t)(lane & 15) * ROWB + ((lane >> 4) << 4);
    const uint32_t wloff = wl_base
        + (uint32_t)(wid * 16 + (lane & 7) + ((lane >> 4) << 3)) * ROWB
        + (((lane >> 3) & 1) << 4);
#pragma unroll
    for (int ks = 0; ks < 8; ks++) {
        uint32_t bl0, bl1, bl2, bl3;
        ldsm4(bl0, bl1, bl2, bl3, wloff + ks * 32);
#pragma unroll
        for (int mg = 0; mg < 2; mg++) {
            uint32_t a0, a1, a2, a3;
            ldsm4(a0, a1, a2, a3, ah_base + aoff + mg * 16 * ROWB + ks * 32);
            mma_bf16(acc[mg][0], a0, a1, a2, a3, bh[ks][0], bh[ks][1]);
            mma_bf16(acc[mg][1], a0, a1, a2, a3, bh[ks][2], bh[ks][3]);
            mma_bf16(acc[mg][0], a0, a1, a2, a3, bl0, bl1);
            mma_bf16(acc[mg][1], a0, a1, a2, a3, bl2, bl3);
            uint32_t c0, c1, c2, c3;
            ldsm4(c0, c1, c2, c3, al_base + aoff + mg * 16 * ROWB + ks * 32);
            mma_bf16(acc[mg][0], c0, c1, c2, c3, bh[ks][0], bh[ks][1]);
            mma_bf16(acc[mg][1], c0, c1, c2, c3, bh[ks][2], bh[ks][3]);
        }
    }
}
// dump accumulators to 32x132 smem tile
__device__ __forceinline__ void dump_acc(float* sacc, const float acc[2][2][4],
                                         int wid, int lane) {
    const int gid = lane >> 2, tig = lane & 3;
    const int nb = wid * 16;
#pragma unroll
    for (int mg = 0; mg < 2; mg++) {
        int r = mg * 16 + gid;
#pragma unroll
        for (int j = 0; j < 2; j++) {
            int c = nb + j * 8 + tig * 2;
            *(float2*)(sacc + r * 132 + c) = make_float2(acc[mg][j][0], acc[mg][j][1]);
            *(float2*)(sacc + (r + 8) * 132 + c) = make_float2(acc[mg][j][2], acc[mg][j][3]);
        }
    }
}

// ---------------- small kernels -----------------------------------------------
__global__ void detect_kernel(const unsigned* __restrict__ w) {
    __shared__ int sflag;
    if (threadIdx.x == 0) sflag = 0;
    __syncthreads();
    unsigned v = 0;
    for (int i = threadIdx.x; i < 2048; i += blockDim.x) v |= w[2 * i + 1];
    if (v) atomicOr(&sflag, 1);
    __syncthreads();
    if (threadIdx.x == 0) g_is64 = sflag ? 0 : 1;
}
__global__ void zero_kernel() {
    int i = blockIdx.x * blockDim.x + threadIdx.x;
    const int total = Nn * 128;
    for (int k = i; k < total; k += gridDim.x * blockDim.x) g_agg[k] = 0.f;
    if (i < 1024) g_stats[i] = 0.f;
}
__global__ void prep_w_kernel(const float* __restrict__ Wu, const float* __restrict__ Wv,
                              const float* __restrict__ WB, const float* __restrict__ WC,
                              const float* __restrict__ WA) {
    int mtx = blockIdx.x;
    const float* W = (mtx == 0) ? Wu : (mtx == 1) ? Wv : (mtx == 2) ? WB : (mtx == 3) ? WC : WA;
    uint16_t* hi = g_Wp + (size_t)mtx * 2 * WPLANE;
    uint16_t* lo = hi + WPLANE;
    for (int idx = threadIdx.x; idx < 16384; idx += blockDim.x) {
        int f = idx >> 7, k = idx & 127;
        float w = W[idx];
        __nv_bfloat16 h = __float2bfloat16(w);
        __nv_bfloat16 l = __float2bfloat16(w - __bfloat162float(h));
        hi[f * ASTRIDE + k] = __bfloat16_as_ushort(h);
        lo[f * ASTRIDE + k] = __bfloat16_as_ushort(l);
    }
}

// ---------------- node GEMMs: persistent, reg-prefetch pipelined, 3 CTAs/SM ------
__global__ void __launch_bounds__(256, 3) node_mma_kernel(
        const float* __restrict__ x, const float* __restrict__ bu,
        const float* __restrict__ bv, const float* __restrict__ bB,
        const float* __restrict__ bC) {
    extern __shared__ char sm[];
    uint32_t smb = smem_u32(sm);
    const int tid = threadIdx.x, wid = tid >> 5, lane = tid & 31;
    const int which = blockIdx.y;
    float* sb = (float*)(sm + SB_BIAS);
    const float* bias = (which == 0) ? bu : (which == 1) ? bv : (which == 2) ? bB : bC;
    if (tid < 128) sb[tid] = bias[tid];

    uint32_t bh[8][4];
    load_w3(sm, smb, which, wid, lane, bh);

    float* dst0;
    int rstride;
    if (which == 0)      { dst0 = g_U;        rstride = 128; }
    else if (which == 1) { dst0 = g_CV + 128; rstride = 256; }
    else if (which == 2) { dst0 = g_B;        rstride = 128; }
    else                 { dst0 = g_CV;       rstride = 256; }

    const int gid = lane >> 2, tig = lane & 3;
    const int nb = wid * 16;

    float4 pre[4];
    long t = blockIdx.x;
    if (t < NT_N) {
        int v0 = Nn - (int)t * 32; if (v0 > 32) v0 = 32;
        load_regs(pre, x + t * 4096, v0);
    }
    for (; t < NT_N; t += gridDim.x) {
        uint16_t* Ah = (uint16_t*)(sm + SB_BF16);
        cvt_store(Ah, Ah + 4352, pre);
        __syncthreads();
        long tn = t + gridDim.x;
        if (tn < NT_N) {
            int vn = Nn - (int)tn * 32; if (vn > 32) vn = 32;
            load_regs(pre, x + tn * 4096, vn);
        }
        float acc[2][2][4];
        mma_tile3(smb + SB_BF16, smb + SB_BF16 + 8704, smb + SB_WL, bh, wid, lane, acc);
#pragma unroll
        for (int mg = 0; mg < 2; mg++) {
            const int r0 = (int)t * 32 + mg * 16 + gid;
#pragma unroll
            for (int j = 0; j < 2; j++) {
                int c = nb + j * 8 + tig * 2;
                float2 bb = *(const float2*)(sb + c);
                if (r0 < Nn)
                    *(float2*)(dst0 + (size_t)r0 * rstride + c) =
                        make_float2(acc[mg][j][0] + bb.x, acc[mg][j][1] + bb.y);
                if (r0 + 8 < Nn)
                    *(float2*)(dst0 + (size_t)(r0 + 8) * rstride + c) =
                        make_float2(acc[mg][j][2] + bb.x, acc[mg][j][3] + bb.y);
            }
        }
        __syncthreads();
    }
}

// ---------------- edge pass 1: GEMM + gathers + edge_in + BN stats, 3 CTAs/SM -----
__global__ void __launch_bounds__(256, 3) edge1_kernel(
        const float* __restrict__ ea, const void* __restrict__ eidx,
        const float* __restrict__ bA) {
    extern __shared__ char sm[];
    uint32_t smb = smem_u32(sm);
    const int tid = threadIdx.x, wid = tid >> 5, lane = tid & 31;
    const int is64 = g_is64;
    float* sb = (float*)(sm + SB_BIAS);
    int* sidx = (int*)(sm + SB_IDX);    // 2 x 64
    float* sacc = (float*)(sm + SB_ACC);
    if (tid < 128) sb[tid] = bA[tid];

    uint32_t bh[8][4];
    load_w3(sm, smb, 4, wid, lane, bh);   // ends with syncthreads

    const float4 bias4 = *(const float4*)(sb + lane * 4);
    float s1[4] = {0.f, 0.f, 0.f, 0.f};
    float s2[4] = {0.f, 0.f, 0.f, 0.f};

    float4 pre[4];
    int idxreg = 0;
    long t = blockIdx.x;
    if (t < NT_E) {
        load_regs(pre, ea + t * 4096, 32);
        if (tid < 64)
            idxreg = ld_idx(eidx, (tid < 32) ? (t * 32 + tid)
                                             : ((size_t)Ee + t * 32 + (tid - 32)), is64);
    }
    int ib = 0;
    for (; t < NT_E; t += gridDim.x) {
        uint16_t* Ah = (uint16_t*)(sm + SB_BF16);
        cvt_store(Ah, Ah + 4352, pre);
        if (tid < 64) sidx[ib * 64 + tid] = idxreg;
        __syncthreads();
        long tn = t + gridDim.x;
        if (tn < NT_E) {
            load_regs(pre, ea + tn * 4096, 32);
            if (tid < 64)
                idxreg = ld_idx(eidx, (tid < 32) ? (tn * 32 + tid)
                                                 : ((size_t)Ee + tn * 32 + (tid - 32)), is64);
        }
        float acc[2][2][4];
        mma_tile3(smb + SB_BF16, smb + SB_BF16 + 8704, smb + SB_WL, bh, wid, lane, acc);
        dump_acc(sacc, acc, wid, lane);
        __syncthreads();

        // warp wid handles edges wid*4 .. wid*4+3 with fully coalesced rows
#pragma unroll
        for (int k = 0; k < 4; k++) {
            int r = wid * 4 + k;
            int ridx = sidx[ib * 64 + r], cidx = sidx[ib * 64 + 32 + r];
            float4 a = *(const float4*)(sacc + r * 132 + lane * 4);
            float4 b = *(const float4*)(g_B + (size_t)ridx * 128 + lane * 4);
            float4 cg = *(const float4*)(g_CV + (size_t)cidx * 256 + lane * 4);
            float4 v;
            v.x = a.x + bias4.x + b.x + cg.x;
            v.y = a.y + bias4.y + b.y + cg.y;
            v.z = a.z + bias4.z + b.z + cg.z;
            v.w = a.w + bias4.w + b.w + cg.w;
            *(float4*)(g_edge_in + (t * 32 + r) * 128 + lane * 4) = v;
            s1[0] += v.x; s2[0] = fmaf(v.x, v.x, s2[0]);
            s1[1] += v.y; s2[1] = fmaf(v.y, v.y, s2[1]);
            s1[2] += v.z; s2[2] = fmaf(v.z, v.z, s2[2]);
            s1[3] += v.w; s2[3] = fmaf(v.w, v.w, s2[3]);
        }
        ib ^= 1;
    }
    // block-level stat reduction: sacc reused as scratch (2048 floats)
    __syncthreads();
#pragma unroll
    for (int q = 0; q < 4; q++) {
        sacc[wid * 128 + lane * 4 + q] = s1[q];
        sacc[1024 + wid * 128 + lane * 4 + q] = s2[q];
    }
    __syncthreads();
    if (tid < 128) {
        float a = 0.f, b = 0.f;
#pragma unroll
        for (int w = 0; w < 8; w++) {
            a += sacc[w * 128 + tid];
            b += sacc[1024 + w * 128 + tid];
        }
        atomicAdd(&g_stats[tid], a);
        atomicAdd(&g_stats[128 + tid], b);
    }
}

// ---------------- finalize BN stats (0=edge, 1=node) --------------------------------
__global__ void finalize_kernel(int which, float inv) {
    int f = threadIdx.x;
    float s1 = g_stats[which * 256 + f];
    float s2 = g_stats[which * 256 + 128 + f];
    float mean = s1 * inv;
    float var = fmaxf(s2 * inv - mean * mean, 0.f);
    g_stats[512 + which * 256 + f] = mean;
    g_stats[512 + which * 256 + 128 + f] = rsqrtf(var + 1e-5f);
}

// ---------------- edge pass 2 ----------------------------------------------------------
__global__ void edge_pass2_kernel(const float* __restrict__ ea, const void* __restrict__ eidx,
                                  const float* __restrict__ gam, const float* __restrict__ bet,
                                  float* __restrict__ out_e) {
    int e = blockIdx.x * 8 + (threadIdx.x >> 5);
    if (e >= Ee) return;
    int c = (threadIdx.x & 31) * 4;
    int row, col;
    if (g_is64) {
        const long long* p = (const long long*)eidx;
        row = (int)p[e];
        col = (int)p[(size_t)Ee + e];
    } else {
        const int* p = (const int*)eidx;
        row = p[e];
        col = p[Ee + e];
    }
    size_t base = (size_t)e * 128 + c;
    float4 ein = *(const float4*)(g_edge_in + base);
    float4 mu = *(const float4*)(g_stats + 512 + c);
    float4 rs = *(const float4*)(g_stats + 640 + c);
    float4 gm = __ldg((const float4*)(gam + c));
    float4 bt = __ldg((const float4*)(bet + c));
    float4 a4 = __ldg((const float4*)(ea + base));
    float4 eo;
    eo.x = a4.x + fmaxf(gm.x * (ein.x - mu.x) * rs.x + bt.x, 0.f);
    eo.y = a4.y + fmaxf(gm.y * (ein.y - mu.y) * rs.y + bt.y, 0.f);
    eo.z = a4.z + fmaxf(gm.z * (ein.z - mu.z) * rs.z + bt.z, 0.f);
    eo.w = a4.w + fmaxf(gm.w * (ein.w - mu.w) * rs.w + bt.w, 0.f);
    *(float4*)(out_e + base) = eo;

    float4 v4 = *(const float4*)(g_CV + (size_t)col * 256 + 128 + c);
    float mx = v4.x / (1.f + __expf(-eo.x));
    float my = v4.y / (1.f + __expf(-eo.y));
    float mz = v4.z / (1.f + __expf(-eo.z));
    float mw = v4.w / (1.f + __expf(-eo.w));
    float* dst = g_agg + (size_t)row * 128 + c;
    asm volatile("red.global.add.v4.f32 [%0], {%1, %2, %3, %4};"
                 :: "l"(dst), "f"(mx), "f"(my), "f"(mz), "f"(mw) : "memory");
}

// ---------------- node stats / output ---------------------------------------------------
__global__ void node_stats_kernel() {
    int f = threadIdx.x;
    int n0 = blockIdx.x * 64;
    float s1 = 0.f, s2 = 0.f;
    for (int r = 0; r < 64; r++) {
        int n = n0 + r;
        if (n < Nn) {
            float v = g_U[(size_t)n * 128 + f] + g_agg[(size_t)n * 128 + f];
            s1 += v;
            s2 += v * v;
        }
    }
    atomicAdd(&g_stats[256 + f], s1);
    atomicAdd(&g_stats[384 + f], s2);
}
__global__ void node_out_kernel(const float* __restrict__ x, const float* __restrict__ gam,
                                const float* __restrict__ bet, float* __restrict__ out_x) {
    int i = blockIdx.x * blockDim.x + threadIdx.x;
    if (i >= Nn * 32) return;
    int c = (i & 31) * 4;
    size_t base = (size_t)i * 4;
    float4 u = *(const float4*)(g_U + base);
    float4 a = *(const float4*)(g_agg + base);
    float4 mu = *(const float4*)(g_stats + 768 + c);
    float4 rs = *(const float4*)(g_stats + 896 + c);
    float4 gm = __ldg((const float4*)(gam + c));
    float4 bt = __ldg((const float4*)(bet + c));
    float4 xv = __ldg((const float4*)(x + base));
    float4 o;
    o.x = xv.x + fmaxf(gm.x * ((u.x + a.x) - mu.x) * rs.x + bt.x, 0.f);
    o.y = xv.y + fmaxf(gm.y * ((u.y + a.y) - mu.y) * rs.y + bt.y, 0.f);
    o.z = xv.z + fmaxf(gm.z * ((u.z + a.z) - mu.z) * rs.z + bt.z, 0.f);
    o.w = xv.w + fmaxf(gm.w * ((u.w + a.w) - mu.w) * rs.w + bt.w, 0.f);
    *(float4*)(out_x + base) = o;
}

// ---------------- launch -----------------------------------------------------------------
extern "C" void kernel_launch(void* const* d_in, const int* in_sizes, int n_in,
                              void* d_out, int out_size) {
    (void)in_sizes; (void)n_in; (void)out_size;
    const float* x  = (const float*)d_in[0];
    const void*  ei = d_in[1];
    const float* ea = (const float*)d_in[2];
    const float* Wu = (const float*)d_in[3];
    const float* bu = (const float*)d_in[4];
    const float* Wv = (const float*)d_in[5];
    const float* bv = (const float*)d_in[6];
    const float* WA = (const float*)d_in[7];
    const float* bA = (const float*)d_in[8];
    const float* WB = (const float*)d_in[9];
    const float* bB = (const float*)d_in[10];
    const float* WC = (const float*)d_in[11];
    const float* bC = (const float*)d_in[12];
    const float* gn_g = (const float*)d_in[13];
    const float* gn_b = (const float*)d_in[14];
    const float* ge_g = (const float*)d_in[15];
    const float* ge_b = (const float*)d_in[16];

    float* out   = (float*)d_out;
    float* out_x = out;
    float* out_e = out + (size_t)Nn * Dd;

    cudaFuncSetAttribute(node_mma_kernel, cudaFuncAttributeMaxDynamicSharedMemorySize, S_SIZE_N);
    cudaFuncSetAttribute(edge1_kernel, cudaFuncAttributeMaxDynamicSharedMemorySize, S_SIZE_E);

    detect_kernel<<<1, 256>>>((const unsigned*)ei);
    zero_kernel<<<2048, 256>>>();
    prep_w_kernel<<<5, 256>>>(Wu, Wv, WB, WC, WA);
    node_mma_kernel<<<dim3(111, 4), 256, S_SIZE_N>>>(x, bu, bv, bB, bC);
    edge1_kernel<<<444, 256, S_SIZE_E>>>(ea, ei, bA);
    finalize_kernel<<<1, 128>>>(0, 1.0f / (float)Ee);
    edge_pass2_kernel<<<(Ee + 7) / 8, 256>>>(ea, ei, ge_g, ge_b, out_e);
    node_stats_kernel<<<(Nn + 63) / 64, 128>>>();
    finalize_kernel<<<1, 128>>>(1, 1.0f / (float)Nn);
    node_out_kernel<<<(Nn * 32 + 255) / 256, 256>>>(x, gn_g, gn_b, out_x);
}

// round 12
// speedup vs baseline: 1.4846x; 1.1511x over previous
#include <cuda_runtime.h>
#include <cuda_fp16.h>
#include <cstdint>

#define Nn 50000
#define Ee 640000
#define Dd 128

#define ASTRIDE 136              // uint16 elems per row (128 + 8 pad)
#define ROWB    (ASTRIDE * 2)    // 272 bytes per row
#define WPLANE  (128 * ASTRIDE)  // uint16 elems per W plane
#define NT_E    (Ee / 32)        // 20000 edge tiles
#define NT_N    ((Nn + 31) / 32) // 1563 node tiles
#define ISCALE  0.0009765625f    // 1/1024

// ---------------- device scratch ------------------------------------------
__device__ float g_U[Nn * 128];
__device__ float g_B[Nn * 128];
__device__ float g_CV[Nn * 256];                 // [Cx | Vx]
__device__ float g_edge_in[(size_t)Ee * 128];
__device__ float g_agg[Nn * 128];
__device__ float g_stats[1024];
__device__ __align__(16) uint16_t g_Wp[5 * 2 * WPLANE]; // fp16 W hi + (lo*1024) planes
__device__ int g_is64;

// ---------------- smem layout (bytes) --------------------------------------
#define SB_BIAS 0                 // 512
#define SB_IDX  512               // 2 x 64 ints
#define SB_F32  2048              // 2 x 16384 fp32 A staging (cp.async)
#define SB_A    34816             // fp16 A plane 8704
#define SB_ACC  43520             // 32 x 132 fp32 = 16896 (edge only)
#define S_SIZE_N 43520
#define S_SIZE_E 60416

// ---------------- PTX helpers ------------------------------------------------
__device__ __forceinline__ uint32_t smem_u32(const void* p) {
    uint32_t a;
    asm("{ .reg .u64 t; cvta.to.shared.u64 t, %1; cvt.u32.u64 %0, t; }" : "=r"(a) : "l"(p));
    return a;
}
__device__ __forceinline__ void ldsm4(uint32_t& r0, uint32_t& r1, uint32_t& r2,
                                      uint32_t& r3, uint32_t addr) {
    asm volatile("ldmatrix.sync.aligned.m8n8.x4.shared.b16 {%0,%1,%2,%3}, [%4];"
                 : "=r"(r0), "=r"(r1), "=r"(r2), "=r"(r3) : "r"(addr));
}
__device__ __forceinline__ void mma_f16(float* d, uint32_t a0, uint32_t a1,
                                        uint32_t a2, uint32_t a3,
                                        uint32_t b0, uint32_t b1) {
    asm volatile("mma.sync.aligned.m16n8k16.row.col.f32.f16.f16.f32 "
        "{%0,%1,%2,%3}, {%4,%5,%6,%7}, {%8,%9}, {%0,%1,%2,%3};"
        : "+f"(d[0]), "+f"(d[1]), "+f"(d[2]), "+f"(d[3])
        : "r"(a0), "r"(a1), "r"(a2), "r"(a3), "r"(b0), "r"(b1));
}
__device__ __forceinline__ void cp_async16(uint32_t saddr, const void* gptr) {
    asm volatile("cp.async.cg.shared.global [%0], [%1], 16;" :: "r"(saddr), "l"(gptr));
}
#define CP_COMMIT() asm volatile("cp.async.commit_group;" ::: "memory")
#define CP_WAIT0()  asm volatile("cp.async.wait_group 0;" ::: "memory")

// stage a 32x128 fp32 tile via cp.async; OOB rows clamp to row 0 (guarded later)
__device__ __forceinline__ void cpa_tile(uint32_t sdst, const float* __restrict__ src,
                                         int valid_rows) {
#pragma unroll
    for (int p = 0; p < 4; p++) {
        int idx = p * 256 + threadIdx.x;
        int row = idx >> 5;
        const float4* g = (const float4*)src + (row < valid_rows ? idx : (idx & 31));
        cp_async16(sdst + idx * 16, g);
    }
}
// convert fp32 smem tile -> single fp16 plane in smem
__device__ __forceinline__ void cvt_half(uint16_t* __restrict__ dst,
                                         const float* __restrict__ srcf) {
#pragma unroll
    for (int p = 0; p < 4; p++) {
        int idx = p * 256 + threadIdx.x;
        int row = idx >> 5, k4 = (idx & 31) << 2;
        float4 v = ((const float4*)srcf)[idx];
        __half2 h0 = __floats2half2_rn(v.x, v.y);
        __half2 h1 = __floats2half2_rn(v.z, v.w);
        uint2 u;
        u.x = *(uint32_t*)&h0;
        u.y = *(uint32_t*)&h1;
        *(uint2*)(dst + row * ASTRIDE + k4) = u;
    }
}
__device__ __forceinline__ int ld_idx(const void* p, size_t i, int is64) {
    return is64 ? (int)((const long long*)p)[i] : ((const int*)p)[i];
}

// stage W planes (one-time, into SB_F32 scratch) and load this warp's fragments
__device__ __forceinline__ void load_wregs(char* sm, uint32_t smb, int mtx,
                                           int wid, int lane,
                                           uint32_t bh[8][4], uint32_t bl[8][4]) {
    const uint32_t woffs = smb + SB_F32
        + (uint32_t)(wid * 16 + (lane & 7) + ((lane >> 4) << 3)) * ROWB
        + (((lane >> 3) & 1) << 4);
    uint4* d = (uint4*)(sm + SB_F32);
    {
        const uint4* s = (const uint4*)(g_Wp + (size_t)mtx * 2 * WPLANE);
        for (int i = threadIdx.x; i < 2176; i += 256) d[i] = s[i];
        __syncthreads();
#pragma unroll
        for (int ks = 0; ks < 8; ks++)
            ldsm4(bh[ks][0], bh[ks][1], bh[ks][2], bh[ks][3], woffs + ks * 32);
        __syncthreads();
    }
    {
        const uint4* s = (const uint4*)(g_Wp + ((size_t)mtx * 2 + 1) * WPLANE);
        for (int i = threadIdx.x; i < 2176; i += 256) d[i] = s[i];
        __syncthreads();
#pragma unroll
        for (int ks = 0; ks < 8; ks++)
            ldsm4(bl[ks][0], bl[ks][1], bl[ks][2], bl[ks][3], woffs + ks * 32);
        __syncthreads();
    }
}

// 2-term MMA over a 32x128 fp16 A tile; W hi/lo fragments in registers.
// acc1 += A*Whi ; acc2 += A*(Wlo*1024)
__device__ __forceinline__ void mma_tile2(uint32_t a_base,
                                          const uint32_t bh[8][4], const uint32_t bl[8][4],
                                          int lane, float acc1[2][2][4], float acc2[2][2][4]) {
#pragma unroll
    for (int mg = 0; mg < 2; mg++)
#pragma unroll
        for (int j = 0; j < 2; j++)
#pragma unroll
            for (int q = 0; q < 4; q++) { acc1[mg][j][q] = 0.f; acc2[mg][j][q] = 0.f; }
    const uint32_t aoff = (uint32_t)(lane & 15) * ROWB + ((lane >> 4) << 4);
#pragma unroll
    for (int ks = 0; ks < 8; ks++) {
#pragma unroll
        for (int mg = 0; mg < 2; mg++) {
            uint32_t a0, a1, a2, a3;
            ldsm4(a0, a1, a2, a3, a_base + aoff + mg * 16 * ROWB + ks * 32);
            mma_f16(acc1[mg][0], a0, a1, a2, a3, bh[ks][0], bh[ks][1]);
            mma_f16(acc1[mg][1], a0, a1, a2, a3, bh[ks][2], bh[ks][3]);
            mma_f16(acc2[mg][0], a0, a1, a2, a3, bl[ks][0], bl[ks][1]);
            mma_f16(acc2[mg][1], a0, a1, a2, a3, bl[ks][2], bl[ks][3]);
        }
    }
}
// combine + dump accumulators to 32x132 smem tile
__device__ __forceinline__ void dump_acc2(float* sacc, const float acc1[2][2][4],
                                          const float acc2[2][2][4], int wid, int lane) {
    const int gid = lane >> 2, tig = lane & 3;
    const int nb = wid * 16;
#pragma unroll
    for (int mg = 0; mg < 2; mg++) {
        int r = mg * 16 + gid;
#pragma unroll
        for (int j = 0; j < 2; j++) {
            int c = nb + j * 8 + tig * 2;
            *(float2*)(sacc + r * 132 + c) =
                make_float2(fmaf(acc2[mg][j][0], ISCALE, acc1[mg][j][0]),
                            fmaf(acc2[mg][j][1], ISCALE, acc1[mg][j][1]));
            *(float2*)(sacc + (r + 8) * 132 + c) =
                make_float2(fmaf(acc2[mg][j][2], ISCALE, acc1[mg][j][2]),
                            fmaf(acc2[mg][j][3], ISCALE, acc1[mg][j][3]));
        }
    }
}

// ---------------- small kernels -----------------------------------------------
__global__ void detect_kernel(const unsigned* __restrict__ w) {
    __shared__ int sflag;
    if (threadIdx.x == 0) sflag = 0;
    __syncthreads();
    unsigned v = 0;
    for (int i = threadIdx.x; i < 2048; i += blockDim.x) v |= w[2 * i + 1];
    if (v) atomicOr(&sflag, 1);
    __syncthreads();
    if (threadIdx.x == 0) g_is64 = sflag ? 0 : 1;
}
__global__ void zero_kernel() {
    int i = blockIdx.x * blockDim.x + threadIdx.x;
    const int total = Nn * 128;
    for (int k = i; k < total; k += gridDim.x * blockDim.x) g_agg[k] = 0.f;
    if (i < 1024) g_stats[i] = 0.f;
}
__global__ void prep_w_kernel(const float* __restrict__ Wu, const float* __restrict__ Wv,
                              const float* __restrict__ WB, const float* __restrict__ WC,
                              const float* __restrict__ WA) {
    int mtx = blockIdx.x;
    const float* W = (mtx == 0) ? Wu : (mtx == 1) ? Wv : (mtx == 2) ? WB : (mtx == 3) ? WC : WA;
    uint16_t* hi = g_Wp + (size_t)mtx * 2 * WPLANE;
    uint16_t* lo = hi + WPLANE;
    for (int idx = threadIdx.x; idx < 16384; idx += blockDim.x) {
        int f = idx >> 7, k = idx & 127;
        float w = W[idx];
        __half h = __float2half_rn(w);
        __half l = __float2half_rn((w - __half2float(h)) * 1024.0f);
        hi[f * ASTRIDE + k] = __half_as_ushort(h);
        lo[f * ASTRIDE + k] = __half_as_ushort(l);
    }
}

// ---------------- node GEMMs: persistent, cp.async pipelined -----------------------
__global__ void __launch_bounds__(256, 2) node_mma_kernel(
        const float* __restrict__ x, const float* __restrict__ bu,
        const float* __restrict__ bv, const float* __restrict__ bB,
        const float* __restrict__ bC) {
    extern __shared__ char sm[];
    uint32_t smb = smem_u32(sm);
    const int tid = threadIdx.x, wid = tid >> 5, lane = tid & 31;
    const int which = blockIdx.y;
    float* sb = (float*)(sm + SB_BIAS);
    const float* bias = (which == 0) ? bu : (which == 1) ? bv : (which == 2) ? bB : bC;
    if (tid < 128) sb[tid] = bias[tid];

    uint32_t bh[8][4], bl[8][4];
    load_wregs(sm, smb, which, wid, lane, bh, bl);

    float* dst0;
    int rstride;
    if (which == 0)      { dst0 = g_U;        rstride = 128; }
    else if (which == 1) { dst0 = g_CV + 128; rstride = 256; }
    else if (which == 2) { dst0 = g_B;        rstride = 128; }
    else                 { dst0 = g_CV;       rstride = 256; }

    const int gid = lane >> 2, tig = lane & 3;
    const int nb = wid * 16;

    long t = blockIdx.x;
    if (t < NT_N) {
        int v0 = Nn - (int)t * 32; if (v0 > 32) v0 = 32;
        cpa_tile(smb + SB_F32, x + t * 4096, v0);
    }
    CP_COMMIT();
    int ib = 0;
    for (; t < NT_N; t += gridDim.x) {
        CP_WAIT0();
        __syncthreads();
        cvt_half((uint16_t*)(sm + SB_A), (const float*)(sm + SB_F32 + ib * 16384));
        long tn = t + gridDim.x;
        if (tn < NT_N) {
            int vn = Nn - (int)tn * 32; if (vn > 32) vn = 32;
            cpa_tile(smb + SB_F32 + (ib ^ 1) * 16384, x + tn * 4096, vn);
        }
        CP_COMMIT();
        __syncthreads();
        float acc1[2][2][4], acc2[2][2][4];
        mma_tile2(smb + SB_A, bh, bl, lane, acc1, acc2);
#pragma unroll
        for (int mg = 0; mg < 2; mg++) {
            const int r0 = (int)t * 32 + mg * 16 + gid;
#pragma unroll
            for (int j = 0; j < 2; j++) {
                int c = nb + j * 8 + tig * 2;
                float2 bb = *(const float2*)(sb + c);
                if (r0 < Nn)
                    *(float2*)(dst0 + (size_t)r0 * rstride + c) = make_float2(
                        fmaf(acc2[mg][j][0], ISCALE, acc1[mg][j][0]) + bb.x,
                        fmaf(acc2[mg][j][1], ISCALE, acc1[mg][j][1]) + bb.y);
                if (r0 + 8 < Nn)
                    *(float2*)(dst0 + (size_t)(r0 + 8) * rstride + c) = make_float2(
                        fmaf(acc2[mg][j][2], ISCALE, acc1[mg][j][2]) + bb.x,
                        fmaf(acc2[mg][j][3], ISCALE, acc1[mg][j][3]) + bb.y);
            }
        }
        ib ^= 1;
    }
}

// ---------------- edge pass 1: GEMM + gathers + edge_in + BN stats ------------------
__global__ void __launch_bounds__(256, 2) edge1_kernel(
        const float* __restrict__ ea, const void* __restrict__ eidx,
        const float* __restrict__ bA) {
    extern __shared__ char sm[];
    uint32_t smb = smem_u32(sm);
    const int tid = threadIdx.x, wid = tid >> 5, lane = tid & 31;
    const int is64 = g_is64;
    float* sb = (float*)(sm + SB_BIAS);
    int* sidx = (int*)(sm + SB_IDX);
    float* sacc = (float*)(sm + SB_ACC);
    if (tid < 128) sb[tid] = bA[tid];

    uint32_t bh[8][4], bl[8][4];
    load_wregs(sm, smb, 4, wid, lane, bh, bl);   // ends with syncthreads

    const float4 bias4 = *(const float4*)(sb + lane * 4);
    float s1[4] = {0.f, 0.f, 0.f, 0.f};
    float s2[4] = {0.f, 0.f, 0.f, 0.f};

    long t = blockIdx.x;
    int idxreg = 0;
    if (t < NT_E) {
        cpa_tile(smb + SB_F32, ea + t * 4096, 32);
        if (tid < 64)
            idxreg = ld_idx(eidx, (tid < 32) ? (t * 32 + tid)
                                             : ((size_t)Ee + t * 32 + (tid - 32)), is64);
    }
    CP_COMMIT();
    int ib = 0;
    for (; t < NT_E; t += gridDim.x) {
        CP_WAIT0();
        __syncthreads();
        if (tid < 64) sidx[tid] = idxreg;
        cvt_half((uint16_t*)(sm + SB_A), (const float*)(sm + SB_F32 + ib * 16384));
        long tn = t + gridDim.x;
        if (tn < NT_E) {
            cpa_tile(smb + SB_F32 + (ib ^ 1) * 16384, ea + tn * 4096, 32);
            if (tid < 64)
                idxreg = ld_idx(eidx, (tid < 32) ? (tn * 32 + tid)
                                                 : ((size_t)Ee + tn * 32 + (tid - 32)), is64);
        }
        CP_COMMIT();
        __syncthreads();
        float acc1[2][2][4], acc2[2][2][4];
        mma_tile2(smb + SB_A, bh, bl, lane, acc1, acc2);
        dump_acc2(sacc, acc1, acc2, wid, lane);
        __syncthreads();

        // warp wid handles edges wid*4 .. wid*4+3 with fully coalesced rows
#pragma unroll
        for (int k = 0; k < 4; k++) {
            int r = wid * 4 + k;
            int ridx = sidx[r], cidx = sidx[32 + r];
            float4 a = *(const float4*)(sacc + r * 132 + lane * 4);
            float4 b = *(const float4*)(g_B + (size_t)ridx * 128 + lane * 4);
            float4 cg = *(const float4*)(g_CV + (size_t)cidx * 256 + lane * 4);
            float4 v;
            v.x = a.x + bias4.x + b.x + cg.x;
            v.y = a.y + bias4.y + b.y + cg.y;
            v.z = a.z + bias4.z + b.z + cg.z;
            v.w = a.w + bias4.w + b.w + cg.w;
            *(float4*)(g_edge_in + (t * 32 + r) * 128 + lane * 4) = v;
            s1[0] += v.x; s2[0] = fmaf(v.x, v.x, s2[0]);
            s1[1] += v.y; s2[1] = fmaf(v.y, v.y, s2[1]);
            s1[2] += v.z; s2[2] = fmaf(v.z, v.z, s2[2]);
            s1[3] += v.w; s2[3] = fmaf(v.w, v.w, s2[3]);
        }
        ib ^= 1;
    }
    // block-level stat reduction: sacc reused as scratch (2048 floats)
    __syncthreads();
#pragma unroll
    for (int q = 0; q < 4; q++) {
        sacc[wid * 128 + lane * 4 + q] = s1[q];
        sacc[1024 + wid * 128 + lane * 4 + q] = s2[q];
    }
    __syncthreads();
    if (tid < 128) {
        float a = 0.f, b = 0.f;
#pragma unroll
        for (int w = 0; w < 8; w++) {
            a += sacc[w * 128 + tid];
            b += sacc[1024 + w * 128 + tid];
        }
        atomicAdd(&g_stats[tid], a);
        atomicAdd(&g_stats[128 + tid], b);
    }
}

// ---------------- finalize BN stats (0=edge, 1=node) --------------------------------
__global__ void finalize_kernel(int which, float inv) {
    int f = threadIdx.x;
    float s1 = g_stats[which * 256 + f];
    float s2 = g_stats[which * 256 + 128 + f];
    float mean = s1 * inv;
    float var = fmaxf(s2 * inv - mean * mean, 0.f);
    g_stats[512 + which * 256 + f] = mean;
    g_stats[512 + which * 256 + 128 + f] = rsqrtf(var + 1e-5f);
}

// ---------------- edge pass 2 ----------------------------------------------------------
__global__ void edge_pass2_kernel(const float* __restrict__ ea, const void* __restrict__ eidx,
                                  const float* __restrict__ gam, const float* __restrict__ bet,
                                  float* __restrict__ out_e) {
    int e = blockIdx.x * 8 + (threadIdx.x >> 5);
    if (e >= Ee) return;
    int c = (threadIdx.x & 31) * 4;
    int row, col;
    if (g_is64) {
        const long long* p = (const long long*)eidx;
        row = (int)p[e];
        col = (int)p[(size_t)Ee + e];
    } else {
        const int* p = (const int*)eidx;
        row = p[e];
        col = p[Ee + e];
    }
    size_t base = (size_t)e * 128 + c;
    float4 ein = *(const float4*)(g_edge_in + base);
    float4 mu = *(const float4*)(g_stats + 512 + c);
    float4 rs = *(const float4*)(g_stats + 640 + c);
    float4 gm = __ldg((const float4*)(gam + c));
    float4 bt = __ldg((const float4*)(bet + c));
    float4 a4 = __ldg((const float4*)(ea + base));
    float4 eo;
    eo.x = a4.x + fmaxf(gm.x * (ein.x - mu.x) * rs.x + bt.x, 0.f);
    eo.y = a4.y + fmaxf(gm.y * (ein.y - mu.y) * rs.y + bt.y, 0.f);
    eo.z = a4.z + fmaxf(gm.z * (ein.z - mu.z) * rs.z + bt.z, 0.f);
    eo.w = a4.w + fmaxf(gm.w * (ein.w - mu.w) * rs.w + bt.w, 0.f);
    *(float4*)(out_e + base) = eo;

    float4 v4 = *(const float4*)(g_CV + (size_t)col * 256 + 128 + c);
    float mx = v4.x / (1.f + __expf(-eo.x));
    float my = v4.y / (1.f + __expf(-eo.y));
    float mz = v4.z / (1.f + __expf(-eo.z));
    float mw = v4.w / (1.f + __expf(-eo.w));
    float* dst = g_agg + (size_t)row * 128 + c;
    asm volatile("red.global.add.v4.f32 [%0], {%1, %2, %3, %4};"
                 :: "l"(dst), "f"(mx), "f"(my), "f"(mz), "f"(mw) : "memory");
}

// ---------------- node stats / output ---------------------------------------------------
__global__ void node_stats_kernel() {
    int f = threadIdx.x;
    int n0 = blockIdx.x * 64;
    float s1 = 0.f, s2 = 0.f;
    for (int r = 0; r < 64; r++) {
        int n = n0 + r;
        if (n < Nn) {
            float v = g_U[(size_t)n * 128 + f] + g_agg[(size_t)n * 128 + f];
            s1 += v;
            s2 += v * v;
        }
    }
    atomicAdd(&g_stats[256 + f], s1);
    atomicAdd(&g_stats[384 + f], s2);
}
__global__ void node_out_kernel(const float* __restrict__ x, const float* __restrict__ gam,
                                const float* __restrict__ bet, float* __restrict__ out_x) {
    int i = blockIdx.x * blockDim.x + threadIdx.x;
    if (i >= Nn * 32) return;
    int c = (i & 31) * 4;
    size_t base = (size_t)i * 4;
    float4 u = *(const float4*)(g_U + base);
    float4 a = *(const float4*)(g_agg + base);
    float4 mu = *(const float4*)(g_stats + 768 + c);
    float4 rs = *(const float4*)(g_stats + 896 + c);
    float4 gm = __ldg((const float4*)(gam + c));
    float4 bt = __ldg((const float4*)(bet + c));
    float4 xv = __ldg((const float4*)(x + base));
    float4 o;
    o.x = xv.x + fmaxf(gm.x * ((u.x + a.x) - mu.x) * rs.x + bt.x, 0.f);
    o.y = xv.y + fmaxf(gm.y * ((u.y + a.y) - mu.y) * rs.y + bt.y, 0.f);
    o.z = xv.z + fmaxf(gm.z * ((u.z + a.z) - mu.z) * rs.z + bt.z, 0.f);
    o.w = xv.w + fmaxf(gm.w * ((u.w + a.w) - mu.w) * rs.w + bt.w, 0.f);
    *(float4*)(out_x + base) = o;
}

// ---------------- launch -----------------------------------------------------------------
extern "C" void kernel_launch(void* const* d_in, const int* in_sizes, int n_in,
                              void* d_out, int out_size) {
    (void)in_sizes; (void)n_in; (void)out_size;
    const float* x  = (const float*)d_in[0];
    const void*  ei = d_in[1];
    const float* ea = (const float*)d_in[2];
    const float* Wu = (const float*)d_in[3];
    const float* bu = (const float*)d_in[4];
    const float* Wv = (const float*)d_in[5];
    const float* bv = (const float*)d_in[6];
    const float* WA = (const float*)d_in[7];
    const float* bA = (const float*)d_in[8];
    const float* WB = (const float*)d_in[9];
    const float* bB = (const float*)d_in[10];
    const float* WC = (const float*)d_in[11];
    const float* bC = (const float*)d_in[12];
    const float* gn_g = (const float*)d_in[13];
    const float* gn_b = (const float*)d_in[14];
    const float* ge_g = (const float*)d_in[15];
    const float* ge_b = (const float*)d_in[16];

    float* out   = (float*)d_out;
    float* out_x = out;
    float* out_e = out + (size_t)Nn * Dd;

    cudaFuncSetAttribute(node_mma_kernel, cudaFuncAttributeMaxDynamicSharedMemorySize, S_SIZE_N);
    cudaFuncSetAttribute(edge1_kernel, cudaFuncAttributeMaxDynamicSharedMemorySize, S_SIZE_E);

    detect_kernel<<<1, 256>>>((const unsigned*)ei);
    zero_kernel<<<2048, 256>>>();
    prep_w_kernel<<<5, 256>>>(Wu, Wv, WB, WC, WA);
    node_mma_kernel<<<dim3(74, 4), 256, S_SIZE_N>>>(x, bu, bv, bB, bC);
    edge1_kernel<<<296, 256, S_SIZE_E>>>(ea, ei, bA);
    finalize_kernel<<<1, 128>>>(0, 1.0f / (float)Ee);
    edge_pass2_kernel<<<(Ee + 7) / 8, 256>>>(ea, ei, ge_g, ge_b, out_e);
    node_stats_kernel<<<(Nn + 63) / 64, 128>>>();
    finalize_kernel<<<1, 128>>>(1, 1.0f / (float)Nn);
    node_out_kernel<<<(Nn * 32 + 255) / 256, 256>>>(x, gn_g, gn_b, out_x);
}

// round 13
// speedup vs baseline: 1.5999x; 1.0776x over previous
#include <cuda_runtime.h>
#include <cuda_fp16.h>
#include <cstdint>

#define Nn 50000
#define Ee 640000
#define Dd 128

#define ASTRIDE 136              // uint16 elems per row (128 + 8 pad)
#define ROWB    (ASTRIDE * 2)    // 272 bytes per row
#define WPLANE  (128 * ASTRIDE)  // uint16 elems per W plane
#define NT_E    (Ee / 32)        // 20000 edge tiles
#define NT_N    ((Nn + 31) / 32) // 1563 node tiles
#define ISCALE  0.0009765625f    // 1/1024

// ---------------- device scratch ------------------------------------------
__device__ float g_U[Nn * 128];
__device__ float g_B[Nn * 128];
__device__ float g_CV[Nn * 256];                 // [Cx | Vx]
__device__ __align__(16) uint16_t g_edge_in[(size_t)Ee * 128]; // fp16 pre-BN edge acts
__device__ float g_agg[Nn * 128];
__device__ float g_stats[1024];
__device__ __align__(16) uint16_t g_Wp[5 * 2 * WPLANE]; // fp16 W hi + (lo*1024) planes
__device__ int g_is64;

// ---------------- smem layout (bytes) --------------------------------------
#define SB_BIAS 0                 // 512
#define SB_IDX  512               // 64 ints
#define SB_F32  2048              // 2 x 16384 fp32 A staging (cp.async)
#define SB_A    34816             // fp16 A plane 8704
#define SB_ACC  43520             // 32 x 132 fp32 = 16896 (edge only)
#define S_SIZE_N 43520
#define S_SIZE_E 60416

// ---------------- PTX helpers ------------------------------------------------
__device__ __forceinline__ uint32_t smem_u32(const void* p) {
    uint32_t a;
    asm("{ .reg .u64 t; cvta.to.shared.u64 t, %1; cvt.u32.u64 %0, t; }" : "=r"(a) : "l"(p));
    return a;
}
__device__ __forceinline__ void ldsm4(uint32_t& r0, uint32_t& r1, uint32_t& r2,
                                      uint32_t& r3, uint32_t addr) {
    asm volatile("ldmatrix.sync.aligned.m8n8.x4.shared.b16 {%0,%1,%2,%3}, [%4];"
                 : "=r"(r0), "=r"(r1), "=r"(r2), "=r"(r3) : "r"(addr));
}
__device__ __forceinline__ void mma_f16(float* d, uint32_t a0, uint32_t a1,
                                        uint32_t a2, uint32_t a3,
                                        uint32_t b0, uint32_t b1) {
    asm volatile("mma.sync.aligned.m16n8k16.row.col.f32.f16.f16.f32 "
        "{%0,%1,%2,%3}, {%4,%5,%6,%7}, {%8,%9}, {%0,%1,%2,%3};"
        : "+f"(d[0]), "+f"(d[1]), "+f"(d[2]), "+f"(d[3])
        : "r"(a0), "r"(a1), "r"(a2), "r"(a3), "r"(b0), "r"(b1));
}
__device__ __forceinline__ void cp_async16(uint32_t saddr, const void* gptr) {
    asm volatile("cp.async.cg.shared.global [%0], [%1], 16;" :: "r"(saddr), "l"(gptr));
}
#define CP_COMMIT() asm volatile("cp.async.commit_group;" ::: "memory")
#define CP_WAIT0()  asm volatile("cp.async.wait_group 0;" ::: "memory")

// stage a 32x128 fp32 tile via cp.async; OOB rows clamp to row 0 (guarded later)
__device__ __forceinline__ void cpa_tile(uint32_t sdst, const float* __restrict__ src,
                                         int valid_rows) {
#pragma unroll
    for (int p = 0; p < 4; p++) {
        int idx = p * 256 + threadIdx.x;
        int row = idx >> 5;
        const float4* g = (const float4*)src + (row < valid_rows ? idx : (idx & 31));
        cp_async16(sdst + idx * 16, g);
    }
}
// convert fp32 smem tile -> single fp16 plane in smem
__device__ __forceinline__ void cvt_half(uint16_t* __restrict__ dst,
                                         const float* __restrict__ srcf) {
#pragma unroll
    for (int p = 0; p < 4; p++) {
        int idx = p * 256 + threadIdx.x;
        int row = idx >> 5, k4 = (idx & 31) << 2;
        float4 v = ((const float4*)srcf)[idx];
        __half2 h0 = __floats2half2_rn(v.x, v.y);
        __half2 h1 = __floats2half2_rn(v.z, v.w);
        uint2 u;
        u.x = *(uint32_t*)&h0;
        u.y = *(uint32_t*)&h1;
        *(uint2*)(dst + row * ASTRIDE + k4) = u;
    }
}
__device__ __forceinline__ int ld_idx(const void* p, size_t i, int is64) {
    return is64 ? (int)((const long long*)p)[i] : ((const int*)p)[i];
}

// stage W planes (one-time, into SB_F32 scratch) and load this warp's fragments
__device__ __forceinline__ void load_wregs(char* sm, uint32_t smb, int mtx,
                                           int wid, int lane,
                                           uint32_t bh[8][4], uint32_t bl[8][4]) {
    const uint32_t woffs = smb + SB_F32
        + (uint32_t)(wid * 16 + (lane & 7) + ((lane >> 4) << 3)) * ROWB
        + (((lane >> 3) & 1) << 4);
    uint4* d = (uint4*)(sm + SB_F32);
    {
        const uint4* s = (const uint4*)(g_Wp + (size_t)mtx * 2 * WPLANE);
        for (int i = threadIdx.x; i < 2176; i += 256) d[i] = s[i];
        __syncthreads();
#pragma unroll
        for (int ks = 0; ks < 8; ks++)
            ldsm4(bh[ks][0], bh[ks][1], bh[ks][2], bh[ks][3], woffs + ks * 32);
        __syncthreads();
    }
    {
        const uint4* s = (const uint4*)(g_Wp + ((size_t)mtx * 2 + 1) * WPLANE);
        for (int i = threadIdx.x; i < 2176; i += 256) d[i] = s[i];
        __syncthreads();
#pragma unroll
        for (int ks = 0; ks < 8; ks++)
            ldsm4(bl[ks][0], bl[ks][1], bl[ks][2], bl[ks][3], woffs + ks * 32);
        __syncthreads();
    }
}

// 2-term MMA over a 32x128 fp16 A tile; W hi/lo fragments in registers.
__device__ __forceinline__ void mma_tile2(uint32_t a_base,
                                          const uint32_t bh[8][4], const uint32_t bl[8][4],
                                          int lane, float acc1[2][2][4], float acc2[2][2][4]) {
#pragma unroll
    for (int mg = 0; mg < 2; mg++)
#pragma unroll
        for (int j = 0; j < 2; j++)
#pragma unroll
            for (int q = 0; q < 4; q++) { acc1[mg][j][q] = 0.f; acc2[mg][j][q] = 0.f; }
    const uint32_t aoff = (uint32_t)(lane & 15) * ROWB + ((lane >> 4) << 4);
#pragma unroll
    for (int ks = 0; ks < 8; ks++) {
#pragma unroll
        for (int mg = 0; mg < 2; mg++) {
            uint32_t a0, a1, a2, a3;
            ldsm4(a0, a1, a2, a3, a_base + aoff + mg * 16 * ROWB + ks * 32);
            mma_f16(acc1[mg][0], a0, a1, a2, a3, bh[ks][0], bh[ks][1]);
            mma_f16(acc1[mg][1], a0, a1, a2, a3, bh[ks][2], bh[ks][3]);
            mma_f16(acc2[mg][0], a0, a1, a2, a3, bl[ks][0], bl[ks][1]);
            mma_f16(acc2[mg][1], a0, a1, a2, a3, bl[ks][2], bl[ks][3]);
        }
    }
}
// combine + dump accumulators to 32x132 smem tile
__device__ __forceinline__ void dump_acc2(float* sacc, const float acc1[2][2][4],
                                          const float acc2[2][2][4], int wid, int lane) {
    const int gid = lane >> 2, tig = lane & 3;
    const int nb = wid * 16;
#pragma unroll
    for (int mg = 0; mg < 2; mg++) {
        int r = mg * 16 + gid;
#pragma unroll
        for (int j = 0; j < 2; j++) {
            int c = nb + j * 8 + tig * 2;
            *(float2*)(sacc + r * 132 + c) =
                make_float2(fmaf(acc2[mg][j][0], ISCALE, acc1[mg][j][0]),
                            fmaf(acc2[mg][j][1], ISCALE, acc1[mg][j][1]));
            *(float2*)(sacc + (r + 8) * 132 + c) =
                make_float2(fmaf(acc2[mg][j][2], ISCALE, acc1[mg][j][2]),
                            fmaf(acc2[mg][j][3], ISCALE, acc1[mg][j][3]));
        }
    }
}

// ---------------- small kernels -----------------------------------------------
__global__ void detect_kernel(const unsigned* __restrict__ w) {
    __shared__ int sflag;
    if (threadIdx.x == 0) sflag = 0;
    __syncthreads();
    unsigned v = 0;
    for (int i = threadIdx.x; i < 2048; i += blockDim.x) v |= w[2 * i + 1];
    if (v) atomicOr(&sflag, 1);
    __syncthreads();
    if (threadIdx.x == 0) g_is64 = sflag ? 0 : 1;
}
__global__ void zero_kernel() {
    int i = blockIdx.x * blockDim.x + threadIdx.x;
    const int total = Nn * 128;
    for (int k = i; k < total; k += gridDim.x * blockDim.x) g_agg[k] = 0.f;
    if (i < 1024) g_stats[i] = 0.f;
}
__global__ void prep_w_kernel(const float* __restrict__ Wu, const float* __restrict__ Wv,
                              const float* __restrict__ WB, const float* __restrict__ WC,
                              const float* __restrict__ WA) {
    int mtx = blockIdx.x;
    const float* W = (mtx == 0) ? Wu : (mtx == 1) ? Wv : (mtx == 2) ? WB : (mtx == 3) ? WC : WA;
    uint16_t* hi = g_Wp + (size_t)mtx * 2 * WPLANE;
    uint16_t* lo = hi + WPLANE;
    for (int idx = threadIdx.x; idx < 16384; idx += blockDim.x) {
        int f = idx >> 7, k = idx & 127;
        float w = W[idx];
        __half h = __float2half_rn(w);
        __half l = __float2half_rn((w - __half2float(h)) * 1024.0f);
        hi[f * ASTRIDE + k] = __half_as_ushort(h);
        lo[f * ASTRIDE + k] = __half_as_ushort(l);
    }
}

// ---------------- node GEMMs: persistent, cp.async pipelined -----------------------
__global__ void __launch_bounds__(256, 2) node_mma_kernel(
        const float* __restrict__ x, const float* __restrict__ bu,
        const float* __restrict__ bv, const float* __restrict__ bB,
        const float* __restrict__ bC) {
    extern __shared__ char sm[];
    uint32_t smb = smem_u32(sm);
    const int tid = threadIdx.x, wid = tid >> 5, lane = tid & 31;
    const int which = blockIdx.y;
    float* sb = (float*)(sm + SB_BIAS);
    const float* bias = (which == 0) ? bu : (which == 1) ? bv : (which == 2) ? bB : bC;
    if (tid < 128) sb[tid] = bias[tid];

    uint32_t bh[8][4], bl[8][4];
    load_wregs(sm, smb, which, wid, lane, bh, bl);

    float* dst0;
    int rstride;
    if (which == 0)      { dst0 = g_U;        rstride = 128; }
    else if (which == 1) { dst0 = g_CV + 128; rstride = 256; }
    else if (which == 2) { dst0 = g_B;        rstride = 128; }
    else                 { dst0 = g_CV;       rstride = 256; }

    const int gid = lane >> 2, tig = lane & 3;
    const int nb = wid * 16;

    long t = blockIdx.x;
    if (t < NT_N) {
        int v0 = Nn - (int)t * 32; if (v0 > 32) v0 = 32;
        cpa_tile(smb + SB_F32, x + t * 4096, v0);
    }
    CP_COMMIT();
    int ib = 0;
    for (; t < NT_N; t += gridDim.x) {
        CP_WAIT0();
        __syncthreads();
        cvt_half((uint16_t*)(sm + SB_A), (const float*)(sm + SB_F32 + ib * 16384));
        long tn = t + gridDim.x;
        if (tn < NT_N) {
            int vn = Nn - (int)tn * 32; if (vn > 32) vn = 32;
            cpa_tile(smb + SB_F32 + (ib ^ 1) * 16384, x + tn * 4096, vn);
        }
        CP_COMMIT();
        __syncthreads();
        float acc1[2][2][4], acc2[2][2][4];
        mma_tile2(smb + SB_A, bh, bl, lane, acc1, acc2);
#pragma unroll
        for (int mg = 0; mg < 2; mg++) {
            const int r0 = (int)t * 32 + mg * 16 + gid;
#pragma unroll
            for (int j = 0; j < 2; j++) {
                int c = nb + j * 8 + tig * 2;
                float2 bb = *(const float2*)(sb + c);
                if (r0 < Nn)
                    *(float2*)(dst0 + (size_t)r0 * rstride + c) = make_float2(
                        fmaf(acc2[mg][j][0], ISCALE, acc1[mg][j][0]) + bb.x,
                        fmaf(acc2[mg][j][1], ISCALE, acc1[mg][j][1]) + bb.y);
                if (r0 + 8 < Nn)
                    *(float2*)(dst0 + (size_t)(r0 + 8) * rstride + c) = make_float2(
                        fmaf(acc2[mg][j][2], ISCALE, acc1[mg][j][2]) + bb.x,
                        fmaf(acc2[mg][j][3], ISCALE, acc1[mg][j][3]) + bb.y);
            }
        }
        ib ^= 1;
    }
}

// ---------------- edge pass 1: GEMM + gathers + fp16 edge_in + BN stats -------------
__global__ void __launch_bounds__(256, 2) edge1_kernel(
        const float* __restrict__ ea, const void* __restrict__ eidx,
        const float* __restrict__ bA) {
    extern __shared__ char sm[];
    uint32_t smb = smem_u32(sm);
    const int tid = threadIdx.x, wid = tid >> 5, lane = tid & 31;
    const int is64 = g_is64;
    float* sb = (float*)(sm + SB_BIAS);
    int* sidx = (int*)(sm + SB_IDX);
    float* sacc = (float*)(sm + SB_ACC);
    if (tid < 128) sb[tid] = bA[tid];

    uint32_t bh[8][4], bl[8][4];
    load_wregs(sm, smb, 4, wid, lane, bh, bl);   // ends with syncthreads

    const float4 bias4 = *(const float4*)(sb + lane * 4);
    float s1[4] = {0.f, 0.f, 0.f, 0.f};
    float s2[4] = {0.f, 0.f, 0.f, 0.f};

    long t = blockIdx.x;
    int idxreg = 0;
    if (t < NT_E) {
        cpa_tile(smb + SB_F32, ea + t * 4096, 32);
        if (tid < 64)
            idxreg = ld_idx(eidx, (tid < 32) ? (t * 32 + tid)
                                             : ((size_t)Ee + t * 32 + (tid - 32)), is64);
    }
    CP_COMMIT();
    int ib = 0;
    for (; t < NT_E; t += gridDim.x) {
        CP_WAIT0();
        __syncthreads();
        if (tid < 64) sidx[tid] = idxreg;
        cvt_half((uint16_t*)(sm + SB_A), (const float*)(sm + SB_F32 + ib * 16384));
        long tn = t + gridDim.x;
        if (tn < NT_E) {
            cpa_tile(smb + SB_F32 + (ib ^ 1) * 16384, ea + tn * 4096, 32);
            if (tid < 64)
                idxreg = ld_idx(eidx, (tid < 32) ? (tn * 32 + tid)
                                                 : ((size_t)Ee + tn * 32 + (tid - 32)), is64);
        }
        CP_COMMIT();
        __syncthreads();
        float acc1[2][2][4], acc2[2][2][4];
        mma_tile2(smb + SB_A, bh, bl, lane, acc1, acc2);
        dump_acc2(sacc, acc1, acc2, wid, lane);
        __syncthreads();

        // warp wid handles edges wid*4 .. wid*4+3 with fully coalesced rows
#pragma unroll
        for (int k = 0; k < 4; k++) {
            int r = wid * 4 + k;
            int ridx = sidx[r], cidx = sidx[32 + r];
            float4 a = *(const float4*)(sacc + r * 132 + lane * 4);
            float4 b = *(const float4*)(g_B + (size_t)ridx * 128 + lane * 4);
            float4 cg = *(const float4*)(g_CV + (size_t)cidx * 256 + lane * 4);
            float4 v;
            v.x = a.x + bias4.x + b.x + cg.x;
            v.y = a.y + bias4.y + b.y + cg.y;
            v.z = a.z + bias4.z + b.z + cg.z;
            v.w = a.w + bias4.w + b.w + cg.w;
            __half2 p0 = __floats2half2_rn(v.x, v.y);
            __half2 p1 = __floats2half2_rn(v.z, v.w);
            uint2 pk;
            pk.x = *(uint32_t*)&p0;
            pk.y = *(uint32_t*)&p1;
            *(uint2*)(g_edge_in + (t * 32 + r) * 128 + lane * 4) = pk;
            s1[0] += v.x; s2[0] = fmaf(v.x, v.x, s2[0]);
            s1[1] += v.y; s2[1] = fmaf(v.y, v.y, s2[1]);
            s1[2] += v.z; s2[2] = fmaf(v.z, v.z, s2[2]);
            s1[3] += v.w; s2[3] = fmaf(v.w, v.w, s2[3]);
        }
        ib ^= 1;
    }
    // block-level stat reduction: sacc reused as scratch (2048 floats)
    __syncthreads();
#pragma unroll
    for (int q = 0; q < 4; q++) {
        sacc[wid * 128 + lane * 4 + q] = s1[q];
        sacc[1024 + wid * 128 + lane * 4 + q] = s2[q];
    }
    __syncthreads();
    if (tid < 128) {
        float a = 0.f, b = 0.f;
#pragma unroll
        for (int w = 0; w < 8; w++) {
            a += sacc[w * 128 + tid];
            b += sacc[1024 + w * 128 + tid];
        }
        atomicAdd(&g_stats[tid], a);
        atomicAdd(&g_stats[128 + tid], b);
    }
}

// ---------------- finalize BN stats (0=edge, 1=node) --------------------------------
__global__ void finalize_kernel(int which, float inv) {
    int f = threadIdx.x;
    float s1 = g_stats[which * 256 + f];
    float s2 = g_stats[which * 256 + 128 + f];
    float mean = s1 * inv;
    float var = fmaxf(s2 * inv - mean * mean, 0.f);
    g_stats[512 + which * 256 + f] = mean;
    g_stats[512 + which * 256 + 128 + f] = rsqrtf(var + 1e-5f);
}

// ---------------- edge pass 2 ----------------------------------------------------------
__global__ void edge_pass2_kernel(const float* __restrict__ ea, const void* __restrict__ eidx,
                                  const float* __restrict__ gam, const float* __restrict__ bet,
                                  float* __restrict__ out_e) {
    int e = blockIdx.x * 8 + (threadIdx.x >> 5);
    if (e >= Ee) return;
    int c = (threadIdx.x & 31) * 4;
    int row, col;
    if (g_is64) {
        const long long* p = (const long long*)eidx;
        row = (int)p[e];
        col = (int)p[(size_t)Ee + e];
    } else {
        const int* p = (const int*)eidx;
        row = p[e];
        col = p[Ee + e];
    }
    size_t base = (size_t)e * 128 + c;
    uint2 pk = *(const uint2*)(g_edge_in + base);
    __half2 p0 = *(__half2*)&pk.x;
    __half2 p1 = *(__half2*)&pk.y;
    float2 e01 = __half22float2(p0);
    float2 e23 = __half22float2(p1);
    float4 ein = make_float4(e01.x, e01.y, e23.x, e23.y);
    float4 mu = *(const float4*)(g_stats + 512 + c);
    float4 rs = *(const float4*)(g_stats + 640 + c);
    float4 gm = __ldg((const float4*)(gam + c));
    float4 bt = __ldg((const float4*)(bet + c));
    float4 a4 = __ldg((const float4*)(ea + base));
    float4 eo;
    eo.x = a4.x + fmaxf(gm.x * (ein.x - mu.x) * rs.x + bt.x, 0.f);
    eo.y = a4.y + fmaxf(gm.y * (ein.y - mu.y) * rs.y + bt.y, 0.f);
    eo.z = a4.z + fmaxf(gm.z * (ein.z - mu.z) * rs.z + bt.z, 0.f);
    eo.w = a4.w + fmaxf(gm.w * (ein.w - mu.w) * rs.w + bt.w, 0.f);
    *(float4*)(out_e + base) = eo;

    float4 v4 = *(const float4*)(g_CV + (size_t)col * 256 + 128 + c);
    float mx = v4.x / (1.f + __expf(-eo.x));
    float my = v4.y / (1.f + __expf(-eo.y));
    float mz = v4.z / (1.f + __expf(-eo.z));
    float mw = v4.w / (1.f + __expf(-eo.w));
    float* dst = g_agg + (size_t)row * 128 + c;
    asm volatile("red.global.add.v4.f32 [%0], {%1, %2, %3, %4};"
                 :: "l"(dst), "f"(mx), "f"(my), "f"(mz), "f"(mw) : "memory");
}

// ---------------- node stats / output ---------------------------------------------------
__global__ void node_stats_kernel() {
    int f = threadIdx.x;
    int n0 = blockIdx.x * 64;
    float s1 = 0.f, s2 = 0.f;
    for (int r = 0; r < 64; r++) {
        int n = n0 + r;
        if (n < Nn) {
            float v = g_U[(size_t)n * 128 + f] + g_agg[(size_t)n * 128 + f];
            s1 += v;
            s2 += v * v;
        }
    }
    atomicAdd(&g_stats[256 + f], s1);
    atomicAdd(&g_stats[384 + f], s2);
}
__global__ void node_out_kernel(const float* __restrict__ x, const float* __restrict__ gam,
                                const float* __restrict__ bet, float* __restrict__ out_x) {
    int i = blockIdx.x * blockDim.x + threadIdx.x;
    if (i >= Nn * 32) return;
    int c = (i & 31) * 4;
    size_t base = (size_t)i * 4;
    float4 u = *(const float4*)(g_U + base);
    float4 a = *(const float4*)(g_agg + base);
    float4 mu = *(const float4*)(g_stats + 768 + c);
    float4 rs = *(const float4*)(g_stats + 896 + c);
    float4 gm = __ldg((const float4*)(gam + c));
    float4 bt = __ldg((const float4*)(bet + c));
    float4 xv = __ldg((const float4*)(x + base));
    float4 o;
    o.x = xv.x + fmaxf(gm.x * ((u.x + a.x) - mu.x) * rs.x + bt.x, 0.f);
    o.y = xv.y + fmaxf(gm.y * ((u.y + a.y) - mu.y) * rs.y + bt.y, 0.f);
    o.z = xv.z + fmaxf(gm.z * ((u.z + a.z) - mu.z) * rs.z + bt.z, 0.f);
    o.w = xv.w + fmaxf(gm.w * ((u.w + a.w) - mu.w) * rs.w + bt.w, 0.f);
    *(float4*)(out_x + base) = o;
}

// ---------------- launch -----------------------------------------------------------------
extern "C" void kernel_launch(void* const* d_in, const int* in_sizes, int n_in,
                              void* d_out, int out_size) {
    (void)in_sizes; (void)n_in; (void)out_size;
    const float* x  = (const float*)d_in[0];
    const void*  ei = d_in[1];
    const float* ea = (const float*)d_in[2];
    const float* Wu = (const float*)d_in[3];
    const float* bu = (const float*)d_in[4];
    const float* Wv = (const float*)d_in[5];
    const float* bv = (const float*)d_in[6];
    const float* WA = (const float*)d_in[7];
    const float* bA = (const float*)d_in[8];
    const float* WB = (const float*)d_in[9];
    const float* bB = (const float*)d_in[10];
    const float* WC = (const float*)d_in[11];
    const float* bC = (const float*)d_in[12];
    const float* gn_g = (const float*)d_in[13];
    const float* gn_b = (const float*)d_in[14];
    const float* ge_g = (const float*)d_in[15];
    const float* ge_b = (const float*)d_in[16];

    float* out   = (float*)d_out;
    float* out_x = out;
    float* out_e = out + (size_t)Nn * Dd;

    cudaFuncSetAttribute(node_mma_kernel, cudaFuncAttributeMaxDynamicSharedMemorySize, S_SIZE_N);
    cudaFuncSetAttribute(edge1_kernel, cudaFuncAttributeMaxDynamicSharedMemorySize, S_SIZE_E);

    detect_kernel<<<1, 256>>>((const unsigned*)ei);
    zero_kernel<<<2048, 256>>>();
    prep_w_kernel<<<5, 256>>>(Wu, Wv, WB, WC, WA);
    node_mma_kernel<<<dim3(74, 4), 256, S_SIZE_N>>>(x, bu, bv, bB, bC);
    edge1_kernel<<<296, 256, S_SIZE_E>>>(ea, ei, bA);
    finalize_kernel<<<1, 128>>>(0, 1.0f / (float)Ee);
    edge_pass2_kernel<<<(Ee + 7) / 8, 256>>>(ea, ei, ge_g, ge_b, out_e);
    node_stats_kernel<<<(Nn + 63) / 64, 128>>>();
    finalize_kernel<<<1, 128>>>(1, 1.0f / (float)Nn);
    node_out_kernel<<<(Nn * 32 + 255) / 256, 256>>>(x, gn_g, gn_b, out_x);
}

// round 14
// speedup vs baseline: 1.6659x; 1.0413x over previous
#include <cuda_runtime.h>
#include <cuda_fp16.h>
#include <cstdint>

#define Nn 50000
#define Ee 640000
#define Dd 128

#define ASTRIDE 136              // uint16 elems per row (128 + 8 pad)
#define ROWB    (ASTRIDE * 2)    // 272 bytes per row
#define WPLANE  (128 * ASTRIDE)  // uint16 elems per W plane
#define NT_E    (Ee / 32)        // 20000 edge tiles
#define NT_N    ((Nn + 31) / 32) // 1563 node tiles
#define ISCALE  0.0009765625f    // 1/1024

// ---------------- device scratch ------------------------------------------
__device__ float g_U[Nn * 128];
__device__ __align__(16) uint16_t g_B[Nn * 128];     // fp16 Bx table
__device__ __align__(16) uint16_t g_CV[Nn * 256];    // fp16 [Cx | Vx] table
__device__ __align__(16) uint16_t g_edge_in[(size_t)Ee * 128]; // fp16 pre-BN edge acts
__device__ float g_agg[Nn * 128];
__device__ float g_stats[1024];
__device__ __align__(16) uint16_t g_Wp[5 * 2 * WPLANE]; // fp16 W hi + (lo*1024) planes
__device__ int g_is64;

// ---------------- smem layout (bytes) --------------------------------------
#define SB_BIAS 0                 // 512
#define SB_IDX  512               // 64 ints
#define SB_F32  2048              // 2 x 16384 fp32 A staging (cp.async)
#define SB_A    34816             // fp16 A plane 8704
#define SB_ACC  43520             // 32 x 132 fp32 = 16896 (edge only)
#define S_SIZE_N 43520
#define S_SIZE_E 60416

// ---------------- PTX helpers ------------------------------------------------
__device__ __forceinline__ uint32_t smem_u32(const void* p) {
    uint32_t a;
    asm("{ .reg .u64 t; cvta.to.shared.u64 t, %1; cvt.u32.u64 %0, t; }" : "=r"(a) : "l"(p));
    return a;
}
__device__ __forceinline__ void ldsm4(uint32_t& r0, uint32_t& r1, uint32_t& r2,
                                      uint32_t& r3, uint32_t addr) {
    asm volatile("ldmatrix.sync.aligned.m8n8.x4.shared.b16 {%0,%1,%2,%3}, [%4];"
                 : "=r"(r0), "=r"(r1), "=r"(r2), "=r"(r3) : "r"(addr));
}
__device__ __forceinline__ void mma_f16(float* d, uint32_t a0, uint32_t a1,
                                        uint32_t a2, uint32_t a3,
                                        uint32_t b0, uint32_t b1) {
    asm volatile("mma.sync.aligned.m16n8k16.row.col.f32.f16.f16.f32 "
        "{%0,%1,%2,%3}, {%4,%5,%6,%7}, {%8,%9}, {%0,%1,%2,%3};"
        : "+f"(d[0]), "+f"(d[1]), "+f"(d[2]), "+f"(d[3])
        : "r"(a0), "r"(a1), "r"(a2), "r"(a3), "r"(b0), "r"(b1));
}
__device__ __forceinline__ void cp_async16(uint32_t saddr, const void* gptr) {
    asm volatile("cp.async.cg.shared.global [%0], [%1], 16;" :: "r"(saddr), "l"(gptr));
}
#define CP_COMMIT() asm volatile("cp.async.commit_group;" ::: "memory")
#define CP_WAIT0()  asm volatile("cp.async.wait_group 0;" ::: "memory")

// unpack 4 halves (uint2) -> float4
__device__ __forceinline__ float4 h4_to_f4(uint2 pk) {
    float2 a = __half22float2(*(__half2*)&pk.x);
    float2 b = __half22float2(*(__half2*)&pk.y);
    return make_float4(a.x, a.y, b.x, b.y);
}

// stage a 32x128 fp32 tile via cp.async; OOB rows clamp to row 0 (guarded later)
__device__ __forceinline__ void cpa_tile(uint32_t sdst, const float* __restrict__ src,
                                         int valid_rows) {
#pragma unroll
    for (int p = 0; p < 4; p++) {
        int idx = p * 256 + threadIdx.x;
        int row = idx >> 5;
        const float4* g = (const float4*)src + (row < valid_rows ? idx : (idx & 31));
        cp_async16(sdst + idx * 16, g);
    }
}
// convert fp32 smem tile -> single fp16 plane in smem
__device__ __forceinline__ void cvt_half(uint16_t* __restrict__ dst,
                                         const float* __restrict__ srcf) {
#pragma unroll
    for (int p = 0; p < 4; p++) {
        int idx = p * 256 + threadIdx.x;
        int row = idx >> 5, k4 = (idx & 31) << 2;
        float4 v = ((const float4*)srcf)[idx];
        __half2 h0 = __floats2half2_rn(v.x, v.y);
        __half2 h1 = __floats2half2_rn(v.z, v.w);
        uint2 u;
        u.x = *(uint32_t*)&h0;
        u.y = *(uint32_t*)&h1;
        *(uint2*)(dst + row * ASTRIDE + k4) = u;
    }
}
__device__ __forceinline__ int ld_idx(const void* p, size_t i, int is64) {
    return is64 ? (int)((const long long*)p)[i] : ((const int*)p)[i];
}

// stage W planes (one-time, into SB_F32 scratch) and load this warp's fragments
__device__ __forceinline__ void load_wregs(char* sm, uint32_t smb, int mtx,
                                           int wid, int lane,
                                           uint32_t bh[8][4], uint32_t bl[8][4]) {
    const uint32_t woffs = smb + SB_F32
        + (uint32_t)(wid * 16 + (lane & 7) + ((lane >> 4) << 3)) * ROWB
        + (((lane >> 3) & 1) << 4);
    uint4* d = (uint4*)(sm + SB_F32);
    {
        const uint4* s = (const uint4*)(g_Wp + (size_t)mtx * 2 * WPLANE);
        for (int i = threadIdx.x; i < 2176; i += 256) d[i] = s[i];
        __syncthreads();
#pragma unroll
        for (int ks = 0; ks < 8; ks++)
            ldsm4(bh[ks][0], bh[ks][1], bh[ks][2], bh[ks][3], woffs + ks * 32);
        __syncthreads();
    }
    {
        const uint4* s = (const uint4*)(g_Wp + ((size_t)mtx * 2 + 1) * WPLANE);
        for (int i = threadIdx.x; i < 2176; i += 256) d[i] = s[i];
        __syncthreads();
#pragma unroll
        for (int ks = 0; ks < 8; ks++)
            ldsm4(bl[ks][0], bl[ks][1], bl[ks][2], bl[ks][3], woffs + ks * 32);
        __syncthreads();
    }
}

// 2-term MMA over a 32x128 fp16 A tile; W hi/lo fragments in registers.
__device__ __forceinline__ void mma_tile2(uint32_t a_base,
                                          const uint32_t bh[8][4], const uint32_t bl[8][4],
                                          int lane, float acc1[2][2][4], float acc2[2][2][4]) {
#pragma unroll
    for (int mg = 0; mg < 2; mg++)
#pragma unroll
        for (int j = 0; j < 2; j++)
#pragma unroll
            for (int q = 0; q < 4; q++) { acc1[mg][j][q] = 0.f; acc2[mg][j][q] = 0.f; }
    const uint32_t aoff = (uint32_t)(lane & 15) * ROWB + ((lane >> 4) << 4);
#pragma unroll
    for (int ks = 0; ks < 8; ks++) {
#pragma unroll
        for (int mg = 0; mg < 2; mg++) {
            uint32_t a0, a1, a2, a3;
            ldsm4(a0, a1, a2, a3, a_base + aoff + mg * 16 * ROWB + ks * 32);
            mma_f16(acc1[mg][0], a0, a1, a2, a3, bh[ks][0], bh[ks][1]);
            mma_f16(acc1[mg][1], a0, a1, a2, a3, bh[ks][2], bh[ks][3]);
            mma_f16(acc2[mg][0], a0, a1, a2, a3, bl[ks][0], bl[ks][1]);
            mma_f16(acc2[mg][1], a0, a1, a2, a3, bl[ks][2], bl[ks][3]);
        }
    }
}
// combine + dump accumulators to 32x132 smem tile
__device__ __forceinline__ void dump_acc2(float* sacc, const float acc1[2][2][4],
                                          const float acc2[2][2][4], int wid, int lane) {
    const int gid = lane >> 2, tig = lane & 3;
    const int nb = wid * 16;
#pragma unroll
    for (int mg = 0; mg < 2; mg++) {
        int r = mg * 16 + gid;
#pragma unroll
        for (int j = 0; j < 2; j++) {
            int c = nb + j * 8 + tig * 2;
            *(float2*)(sacc + r * 132 + c) =
                make_float2(fmaf(acc2[mg][j][0], ISCALE, acc1[mg][j][0]),
                            fmaf(acc2[mg][j][1], ISCALE, acc1[mg][j][1]));
            *(float2*)(sacc + (r + 8) * 132 + c) =
                make_float2(fmaf(acc2[mg][j][2], ISCALE, acc1[mg][j][2]),
                            fmaf(acc2[mg][j][3], ISCALE, acc1[mg][j][3]));
        }
    }
}

// ---------------- small kernels -----------------------------------------------
__global__ void detect_kernel(const unsigned* __restrict__ w) {
    __shared__ int sflag;
    if (threadIdx.x == 0) sflag = 0;
    __syncthreads();
    unsigned v = 0;
    for (int i = threadIdx.x; i < 2048; i += blockDim.x) v |= w[2 * i + 1];
    if (v) atomicOr(&sflag, 1);
    __syncthreads();
    if (threadIdx.x == 0) g_is64 = sflag ? 0 : 1;
}
__global__ void zero_kernel() {
    int i = blockIdx.x * blockDim.x + threadIdx.x;
    const int total = Nn * 128;
    for (int k = i; k < total; k += gridDim.x * blockDim.x) g_agg[k] = 0.f;
    if (i < 1024) g_stats[i] = 0.f;
}
__global__ void prep_w_kernel(const float* __restrict__ Wu, const float* __restrict__ Wv,
                              const float* __restrict__ WB, const float* __restrict__ WC,
                              const float* __restrict__ WA) {
    int mtx = blockIdx.x;
    const float* W = (mtx == 0) ? Wu : (mtx == 1) ? Wv : (mtx == 2) ? WB : (mtx == 3) ? WC : WA;
    uint16_t* hi = g_Wp + (size_t)mtx * 2 * WPLANE;
    uint16_t* lo = hi + WPLANE;
    for (int idx = threadIdx.x; idx < 16384; idx += blockDim.x) {
        int f = idx >> 7, k = idx & 127;
        float w = W[idx];
        __half h = __float2half_rn(w);
        __half l = __float2half_rn((w - __half2float(h)) * 1024.0f);
        hi[f * ASTRIDE + k] = __half_as_ushort(h);
        lo[f * ASTRIDE + k] = __half_as_ushort(l);
    }
}

// ---------------- node GEMMs: persistent, cp.async pipelined -----------------------
__global__ void __launch_bounds__(256, 2) node_mma_kernel(
        const float* __restrict__ x, const float* __restrict__ bu,
        const float* __restrict__ bv, const float* __restrict__ bB,
        const float* __restrict__ bC) {
    extern __shared__ char sm[];
    uint32_t smb = smem_u32(sm);
    const int tid = threadIdx.x, wid = tid >> 5, lane = tid & 31;
    const int which = blockIdx.y;
    float* sb = (float*)(sm + SB_BIAS);
    const float* bias = (which == 0) ? bu : (which == 1) ? bv : (which == 2) ? bB : bC;
    if (tid < 128) sb[tid] = bias[tid];

    uint32_t bh[8][4], bl[8][4];
    load_wregs(sm, smb, which, wid, lane, bh, bl);

    uint16_t* dsth = (which == 1) ? g_CV + 128 : (which == 2) ? g_B : g_CV;
    const int rstride = (which == 0 || which == 2) ? 128 : 256;

    const int gid = lane >> 2, tig = lane & 3;
    const int nb = wid * 16;

    long t = blockIdx.x;
    if (t < NT_N) {
        int v0 = Nn - (int)t * 32; if (v0 > 32) v0 = 32;
        cpa_tile(smb + SB_F32, x + t * 4096, v0);
    }
    CP_COMMIT();
    int ib = 0;
    for (; t < NT_N; t += gridDim.x) {
        CP_WAIT0();
        __syncthreads();
        cvt_half((uint16_t*)(sm + SB_A), (const float*)(sm + SB_F32 + ib * 16384));
        long tn = t + gridDim.x;
        if (tn < NT_N) {
            int vn = Nn - (int)tn * 32; if (vn > 32) vn = 32;
            cpa_tile(smb + SB_F32 + (ib ^ 1) * 16384, x + tn * 4096, vn);
        }
        CP_COMMIT();
        __syncthreads();
        float acc1[2][2][4], acc2[2][2][4];
        mma_tile2(smb + SB_A, bh, bl, lane, acc1, acc2);
#pragma unroll
        for (int mg = 0; mg < 2; mg++) {
            const int r0 = (int)t * 32 + mg * 16 + gid;
#pragma unroll
            for (int j = 0; j < 2; j++) {
                int c = nb + j * 8 + tig * 2;
                float2 bb = *(const float2*)(sb + c);
                float v0x = fmaf(acc2[mg][j][0], ISCALE, acc1[mg][j][0]) + bb.x;
                float v0y = fmaf(acc2[mg][j][1], ISCALE, acc1[mg][j][1]) + bb.y;
                float v1x = fmaf(acc2[mg][j][2], ISCALE, acc1[mg][j][2]) + bb.x;
                float v1y = fmaf(acc2[mg][j][3], ISCALE, acc1[mg][j][3]) + bb.y;
                if (which == 0) {
                    if (r0 < Nn)
                        *(float2*)(g_U + (size_t)r0 * 128 + c) = make_float2(v0x, v0y);
                    if (r0 + 8 < Nn)
                        *(float2*)(g_U + (size_t)(r0 + 8) * 128 + c) = make_float2(v1x, v1y);
                } else {
                    if (r0 < Nn) {
                        __half2 h = __floats2half2_rn(v0x, v0y);
                        *(uint32_t*)(dsth + (size_t)r0 * rstride + c) = *(uint32_t*)&h;
                    }
                    if (r0 + 8 < Nn) {
                        __half2 h = __floats2half2_rn(v1x, v1y);
                        *(uint32_t*)(dsth + (size_t)(r0 + 8) * rstride + c) = *(uint32_t*)&h;
                    }
                }
            }
        }
        ib ^= 1;
    }
}

// ---------------- edge pass 1: GEMM + fp16 gathers + fp16 edge_in + BN stats --------
__global__ void __launch_bounds__(256, 2) edge1_kernel(
        const float* __restrict__ ea, const void* __restrict__ eidx,
        const float* __restrict__ bA) {
    extern __shared__ char sm[];
    uint32_t smb = smem_u32(sm);
    const int tid = threadIdx.x, wid = tid >> 5, lane = tid & 31;
    const int is64 = g_is64;
    float* sb = (float*)(sm + SB_BIAS);
    int* sidx = (int*)(sm + SB_IDX);
    float* sacc = (float*)(sm + SB_ACC);
    if (tid < 128) sb[tid] = bA[tid];

    uint32_t bh[8][4], bl[8][4];
    load_wregs(sm, smb, 4, wid, lane, bh, bl);   // ends with syncthreads

    const float4 bias4 = *(const float4*)(sb + lane * 4);
    float s1[4] = {0.f, 0.f, 0.f, 0.f};
    float s2[4] = {0.f, 0.f, 0.f, 0.f};

    long t = blockIdx.x;
    int idxreg = 0;
    if (t < NT_E) {
        cpa_tile(smb + SB_F32, ea + t * 4096, 32);
        if (tid < 64)
            idxreg = ld_idx(eidx, (tid < 32) ? (t * 32 + tid)
                                             : ((size_t)Ee + t * 32 + (tid - 32)), is64);
    }
    CP_COMMIT();
    int ib = 0;
    for (; t < NT_E; t += gridDim.x) {
        CP_WAIT0();
        __syncthreads();
        if (tid < 64) sidx[tid] = idxreg;
        cvt_half((uint16_t*)(sm + SB_A), (const float*)(sm + SB_F32 + ib * 16384));
        long tn = t + gridDim.x;
        if (tn < NT_E) {
            cpa_tile(smb + SB_F32 + (ib ^ 1) * 16384, ea + tn * 4096, 32);
            if (tid < 64)
                idxreg = ld_idx(eidx, (tid < 32) ? (tn * 32 + tid)
                                                 : ((size_t)Ee + tn * 32 + (tid - 32)), is64);
        }
        CP_COMMIT();
        __syncthreads();
        float acc1[2][2][4], acc2[2][2][4];
        mma_tile2(smb + SB_A, bh, bl, lane, acc1, acc2);
        dump_acc2(sacc, acc1, acc2, wid, lane);
        __syncthreads();

        // warp wid handles edges wid*4 .. wid*4+3 with fully coalesced fp16 rows
#pragma unroll
        for (int k = 0; k < 4; k++) {
            int r = wid * 4 + k;
            int ridx = sidx[r], cidx = sidx[32 + r];
            float4 a = *(const float4*)(sacc + r * 132 + lane * 4);
            float4 b = h4_to_f4(*(const uint2*)(g_B + (size_t)ridx * 128 + lane * 4));
            float4 cg = h4_to_f4(*(const uint2*)(g_CV + (size_t)cidx * 256 + lane * 4));
            float4 v;
            v.x = a.x + bias4.x + b.x + cg.x;
            v.y = a.y + bias4.y + b.y + cg.y;
            v.z = a.z + bias4.z + b.z + cg.z;
            v.w = a.w + bias4.w + b.w + cg.w;
            __half2 p0 = __floats2half2_rn(v.x, v.y);
            __half2 p1 = __floats2half2_rn(v.z, v.w);
            uint2 pk;
            pk.x = *(uint32_t*)&p0;
            pk.y = *(uint32_t*)&p1;
            *(uint2*)(g_edge_in + (t * 32 + r) * 128 + lane * 4) = pk;
            s1[0] += v.x; s2[0] = fmaf(v.x, v.x, s2[0]);
            s1[1] += v.y; s2[1] = fmaf(v.y, v.y, s2[1]);
            s1[2] += v.z; s2[2] = fmaf(v.z, v.z, s2[2]);
            s1[3] += v.w; s2[3] = fmaf(v.w, v.w, s2[3]);
        }
        ib ^= 1;
    }
    // block-level stat reduction: sacc reused as scratch (2048 floats)
    __syncthreads();
#pragma unroll
    for (int q = 0; q < 4; q++) {
        sacc[wid * 128 + lane * 4 + q] = s1[q];
        sacc[1024 + wid * 128 + lane * 4 + q] = s2[q];
    }
    __syncthreads();
    if (tid < 128) {
        float a = 0.f, b = 0.f;
#pragma unroll
        for (int w = 0; w < 8; w++) {
            a += sacc[w * 128 + tid];
            b += sacc[1024 + w * 128 + tid];
        }
        atomicAdd(&g_stats[tid], a);
        atomicAdd(&g_stats[128 + tid], b);
    }
}

// ---------------- finalize BN stats (0=edge, 1=node) --------------------------------
__global__ void finalize_kernel(int which, float inv) {
    int f = threadIdx.x;
    float s1 = g_stats[which * 256 + f];
    float s2 = g_stats[which * 256 + 128 + f];
    float mean = s1 * inv;
    float var = fmaxf(s2 * inv - mean * mean, 0.f);
    g_stats[512 + which * 256 + f] = mean;
    g_stats[512 + which * 256 + 128 + f] = rsqrtf(var + 1e-5f);
}

// ---------------- edge pass 2 ----------------------------------------------------------
__global__ void edge_pass2_kernel(const float* __restrict__ ea, const void* __restrict__ eidx,
                                  const float* __restrict__ gam, const float* __restrict__ bet,
                                  float* __restrict__ out_e) {
    int e = blockIdx.x * 8 + (threadIdx.x >> 5);
    if (e >= Ee) return;
    int c = (threadIdx.x & 31) * 4;
    int row, col;
    if (g_is64) {
        const long long* p = (const long long*)eidx;
        row = (int)p[e];
        col = (int)p[(size_t)Ee + e];
    } else {
        const int* p = (const int*)eidx;
        row = p[e];
        col = p[Ee + e];
    }
    size_t base = (size_t)e * 128 + c;
    float4 ein = h4_to_f4(*(const uint2*)(g_edge_in + base));
    float4 mu = *(const float4*)(g_stats + 512 + c);
    float4 rs = *(const float4*)(g_stats + 640 + c);
    float4 gm = __ldg((const float4*)(gam + c));
    float4 bt = __ldg((const float4*)(bet + c));
    float4 a4 = __ldg((const float4*)(ea + base));
    float4 eo;
    eo.x = a4.x + fmaxf(gm.x * (ein.x - mu.x) * rs.x + bt.x, 0.f);
    eo.y = a4.y + fmaxf(gm.y * (ein.y - mu.y) * rs.y + bt.y, 0.f);
    eo.z = a4.z + fmaxf(gm.z * (ein.z - mu.z) * rs.z + bt.z, 0.f);
    eo.w = a4.w + fmaxf(gm.w * (ein.w - mu.w) * rs.w + bt.w, 0.f);
    *(float4*)(out_e + base) = eo;

    float4 v4 = h4_to_f4(*(const uint2*)(g_CV + (size_t)col * 256 + 128 + c));
    float mx = v4.x / (1.f + __expf(-eo.x));
    float my = v4.y / (1.f + __expf(-eo.y));
    float mz = v4.z / (1.f + __expf(-eo.z));
    float mw = v4.w / (1.f + __expf(-eo.w));
    float* dst = g_agg + (size_t)row * 128 + c;
    asm volatile("red.global.add.v4.f32 [%0], {%1, %2, %3, %4};"
                 :: "l"(dst), "f"(mx), "f"(my), "f"(mz), "f"(mw) : "memory");
}

// ---------------- node stats / output ---------------------------------------------------
__global__ void node_stats_kernel() {
    int f = threadIdx.x;
    int n0 = blockIdx.x * 64;
    float s1 = 0.f, s2 = 0.f;
    for (int r = 0; r < 64; r++) {
        int n = n0 + r;
        if (n < Nn) {
            float v = g_U[(size_t)n * 128 + f] + g_agg[(size_t)n * 128 + f];
            s1 += v;
            s2 += v * v;
        }
    }
    atomicAdd(&g_stats[256 + f], s1);
    atomicAdd(&g_stats[384 + f], s2);
}
__global__ void node_out_kernel(const float* __restrict__ x, const float* __restrict__ gam,
                                const float* __restrict__ bet, float* __restrict__ out_x) {
    int i = blockIdx.x * blockDim.x + threadIdx.x;
    if (i >= Nn * 32) return;
    int c = (i & 31) * 4;
    size_t base = (size_t)i * 4;
    float4 u = *(const float4*)(g_U + base);
    float4 a = *(const float4*)(g_agg + base);
    float4 mu = *(const float4*)(g_stats + 768 + c);
    float4 rs = *(const float4*)(g_stats + 896 + c);
    float4 gm = __ldg((const float4*)(gam + c));
    float4 bt = __ldg((const float4*)(bet + c));
    float4 xv = __ldg((const float4*)(x + base));
    float4 o;
    o.x = xv.x + fmaxf(gm.x * ((u.x + a.x) - mu.x) * rs.x + bt.x, 0.f);
    o.y = xv.y + fmaxf(gm.y * ((u.y + a.y) - mu.y) * rs.y + bt.y, 0.f);
    o.z = xv.z + fmaxf(gm.z * ((u.z + a.z) - mu.z) * rs.z + bt.z, 0.f);
    o.w = xv.w + fmaxf(gm.w * ((u.w + a.w) - mu.w) * rs.w + bt.w, 0.f);
    *(float4*)(out_x + base) = o;
}

// ---------------- launch -----------------------------------------------------------------
extern "C" void kernel_launch(void* const* d_in, const int* in_sizes, int n_in,
                              void* d_out, int out_size) {
    (void)in_sizes; (void)n_in; (void)out_size;
    const float* x  = (const float*)d_in[0];
    const void*  ei = d_in[1];
    const float* ea = (const float*)d_in[2];
    const float* Wu = (const float*)d_in[3];
    const float* bu = (const float*)d_in[4];
    const float* Wv = (const float*)d_in[5];
    const float* bv = (const float*)d_in[6];
    const float* WA = (const float*)d_in[7];
    const float* bA = (const float*)d_in[8];
    const float* WB = (const float*)d_in[9];
    const float* bB = (const float*)d_in[10];
    const float* WC = (const float*)d_in[11];
    const float* bC = (const float*)d_in[12];
    const float* gn_g = (const float*)d_in[13];
    const float* gn_b = (const float*)d_in[14];
    const float* ge_g = (const float*)d_in[15];
    const float* ge_b = (const float*)d_in[16];

    float* out   = (float*)d_out;
    float* out_x = out;
    float* out_e = out + (size_t)Nn * Dd;

    cudaFuncSetAttribute(node_mma_kernel, cudaFuncAttributeMaxDynamicSharedMemorySize, S_SIZE_N);
    cudaFuncSetAttribute(edge1_kernel, cudaFuncAttributeMaxDynamicSharedMemorySize, S_SIZE_E);

    detect_kernel<<<1, 256>>>((const unsigned*)ei);
    zero_kernel<<<2048, 256>>>();
    prep_w_kernel<<<5, 256>>>(Wu, Wv, WB, WC, WA);
    node_mma_kernel<<<dim3(74, 4), 256, S_SIZE_N>>>(x, bu, bv, bB, bC);
    edge1_kernel<<<296, 256, S_SIZE_E>>>(ea, ei, bA);
    finalize_kernel<<<1, 128>>>(0, 1.0f / (float)Ee);
    edge_pass2_kernel<<<(Ee + 7) / 8, 256>>>(ea, ei, ge_g, ge_b, out_e);
    node_stats_kernel<<<(Nn + 63) / 64, 128>>>();
    finalize_kernel<<<1, 128>>>(1, 1.0f / (float)Nn);
    node_out_kernel<<<(Nn * 32 + 255) / 256, 256>>>(x, gn_g, gn_b, out_x);
}

// round 15
// speedup vs baseline: 1.7953x; 1.0777x over previous
#include <cuda_runtime.h>
#include <cuda_fp16.h>
#include <cstdint>

#define Nn 50000
#define Ee 640000
#define Dd 128

#define ASTRIDE 136              // uint16 elems per row (128 + 8 pad)
#define ROWB    (ASTRIDE * 2)    // 272 bytes per row
#define WPLANE  (128 * ASTRIDE)  // uint16 elems per W plane
#define NT_E    (Ee / 32)        // 20000 edge tiles
#define NT_N    ((Nn + 31) / 32) // 1563 node tiles
#define ISCALE  0.0009765625f    // 1/1024

// ---------------- device scratch ------------------------------------------
__device__ float g_U[Nn * 128];
__device__ __align__(16) uint16_t g_B[Nn * 128];     // fp16 Bx table
__device__ __align__(16) uint16_t g_CV[Nn * 256];    // fp16 [Cx | Vx] table
__device__ __align__(16) uint16_t g_edge_in[(size_t)Ee * 128]; // fp16 pre-BN edge acts
__device__ float g_agg[Nn * 128];
__device__ float g_stats[1024];
__device__ __align__(16) uint16_t g_Wp[5 * 2 * WPLANE]; // fp16 W hi + (lo*1024) planes
__device__ int g_is64;

// ---------------- smem layout (bytes) --------------------------------------
#define SB_BIAS 0                 // 512
#define SB_IDX  512               // 64 ints
#define SB_F32  2048              // 2 x 16384 fp32 A staging (cp.async)
#define SB_A    34816             // fp16 A plane 8704
#define SB_ACC  43520             // 32 x 132 fp32 = 16896 (edge only)
#define S_SIZE_N 43520
#define S_SIZE_E 60416

// ---------------- PTX helpers ------------------------------------------------
__device__ __forceinline__ uint32_t smem_u32(const void* p) {
    uint32_t a;
    asm("{ .reg .u64 t; cvta.to.shared.u64 t, %1; cvt.u32.u64 %0, t; }" : "=r"(a) : "l"(p));
    return a;
}
__device__ __forceinline__ void ldsm4(uint32_t& r0, uint32_t& r1, uint32_t& r2,
                                      uint32_t& r3, uint32_t addr) {
    asm volatile("ldmatrix.sync.aligned.m8n8.x4.shared.b16 {%0,%1,%2,%3}, [%4];"
                 : "=r"(r0), "=r"(r1), "=r"(r2), "=r"(r3) : "r"(addr));
}
__device__ __forceinline__ void mma_f16(float* d, uint32_t a0, uint32_t a1,
                                        uint32_t a2, uint32_t a3,
                                        uint32_t b0, uint32_t b1) {
    asm volatile("mma.sync.aligned.m16n8k16.row.col.f32.f16.f16.f32 "
        "{%0,%1,%2,%3}, {%4,%5,%6,%7}, {%8,%9}, {%0,%1,%2,%3};"
        : "+f"(d[0]), "+f"(d[1]), "+f"(d[2]), "+f"(d[3])
        : "r"(a0), "r"(a1), "r"(a2), "r"(a3), "r"(b0), "r"(b1));
}
__device__ __forceinline__ void cp_async16(uint32_t saddr, const void* gptr) {
    asm volatile("cp.async.cg.shared.global [%0], [%1], 16;" :: "r"(saddr), "l"(gptr));
}
#define CP_COMMIT() asm volatile("cp.async.commit_group;" ::: "memory")
#define CP_WAIT0()  asm volatile("cp.async.wait_group 0;" ::: "memory")

// unpack 4 halves (uint2) -> float4
__device__ __forceinline__ float4 h4_to_f4(uint2 pk) {
    float2 a = __half22float2(*(__half2*)&pk.x);
    float2 b = __half22float2(*(__half2*)&pk.y);
    return make_float4(a.x, a.y, b.x, b.y);
}

// stage a 32x128 fp32 tile via cp.async; OOB rows clamp to row 0 (guarded later)
__device__ __forceinline__ void cpa_tile(uint32_t sdst, const float* __restrict__ src,
                                         int valid_rows) {
#pragma unroll
    for (int p = 0; p < 4; p++) {
        int idx = p * 256 + threadIdx.x;
        int row = idx >> 5;
        const float4* g = (const float4*)src + (row < valid_rows ? idx : (idx & 31));
        cp_async16(sdst + idx * 16, g);
    }
}
// convert fp32 smem tile -> single fp16 plane in smem
__device__ __forceinline__ void cvt_half(uint16_t* __restrict__ dst,
                                         const float* __restrict__ srcf) {
#pragma unroll
    for (int p = 0; p < 4; p++) {
        int idx = p * 256 + threadIdx.x;
        int row = idx >> 5, k4 = (idx & 31) << 2;
        float4 v = ((const float4*)srcf)[idx];
        __half2 h0 = __floats2half2_rn(v.x, v.y);
        __half2 h1 = __floats2half2_rn(v.z, v.w);
        uint2 u;
        u.x = *(uint32_t*)&h0;
        u.y = *(uint32_t*)&h1;
        *(uint2*)(dst + row * ASTRIDE + k4) = u;
    }
}
__device__ __forceinline__ int ld_idx(const void* p, size_t i, int is64) {
    return is64 ? (int)((const long long*)p)[i] : ((const int*)p)[i];
}

// stage W hi plane (one-time) into SB_F32 scratch; load this warp's hi fragments
__device__ __forceinline__ void load_wregs_hi(char* sm, uint32_t smb, int mtx,
                                              int wid, int lane, uint32_t bh[8][4]) {
    const uint32_t woffs = smb + SB_F32
        + (uint32_t)(wid * 16 + (lane & 7) + ((lane >> 4) << 3)) * ROWB
        + (((lane >> 3) & 1) << 4);
    uint4* d = (uint4*)(sm + SB_F32);
    const uint4* s = (const uint4*)(g_Wp + (size_t)mtx * 2 * WPLANE);
    for (int i = threadIdx.x; i < 2176; i += 256) d[i] = s[i];
    __syncthreads();
#pragma unroll
    for (int ks = 0; ks < 8; ks++)
        ldsm4(bh[ks][0], bh[ks][1], bh[ks][2], bh[ks][3], woffs + ks * 32);
    __syncthreads();
}
// stage both W planes; load hi+lo fragments (node kernel, 2-term)
__device__ __forceinline__ void load_wregs(char* sm, uint32_t smb, int mtx,
                                           int wid, int lane,
                                           uint32_t bh[8][4], uint32_t bl[8][4]) {
    const uint32_t woffs = smb + SB_F32
        + (uint32_t)(wid * 16 + (lane & 7) + ((lane >> 4) << 3)) * ROWB
        + (((lane >> 3) & 1) << 4);
    uint4* d = (uint4*)(sm + SB_F32);
    {
        const uint4* s = (const uint4*)(g_Wp + (size_t)mtx * 2 * WPLANE);
        for (int i = threadIdx.x; i < 2176; i += 256) d[i] = s[i];
        __syncthreads();
#pragma unroll
        for (int ks = 0; ks < 8; ks++)
            ldsm4(bh[ks][0], bh[ks][1], bh[ks][2], bh[ks][3], woffs + ks * 32);
        __syncthreads();
    }
    {
        const uint4* s = (const uint4*)(g_Wp + ((size_t)mtx * 2 + 1) * WPLANE);
        for (int i = threadIdx.x; i < 2176; i += 256) d[i] = s[i];
        __syncthreads();
#pragma unroll
        for (int ks = 0; ks < 8; ks++)
            ldsm4(bl[ks][0], bl[ks][1], bl[ks][2], bl[ks][3], woffs + ks * 32);
        __syncthreads();
    }
}

// 2-term MMA over a 32x128 fp16 A tile (node kernel)
__device__ __forceinline__ void mma_tile2(uint32_t a_base,
                                          const uint32_t bh[8][4], const uint32_t bl[8][4],
                                          int lane, float acc1[2][2][4], float acc2[2][2][4]) {
#pragma unroll
    for (int mg = 0; mg < 2; mg++)
#pragma unroll
        for (int j = 0; j < 2; j++)
#pragma unroll
            for (int q = 0; q < 4; q++) { acc1[mg][j][q] = 0.f; acc2[mg][j][q] = 0.f; }
    const uint32_t aoff = (uint32_t)(lane & 15) * ROWB + ((lane >> 4) << 4);
#pragma unroll
    for (int ks = 0; ks < 8; ks++) {
#pragma unroll
        for (int mg = 0; mg < 2; mg++) {
            uint32_t a0, a1, a2, a3;
            ldsm4(a0, a1, a2, a3, a_base + aoff + mg * 16 * ROWB + ks * 32);
            mma_f16(acc1[mg][0], a0, a1, a2, a3, bh[ks][0], bh[ks][1]);
            mma_f16(acc1[mg][1], a0, a1, a2, a3, bh[ks][2], bh[ks][3]);
            mma_f16(acc2[mg][0], a0, a1, a2, a3, bl[ks][0], bl[ks][1]);
            mma_f16(acc2[mg][1], a0, a1, a2, a3, bl[ks][2], bl[ks][3]);
        }
    }
}
// 1-term MMA over a 32x128 fp16 A tile (edge kernel)
__device__ __forceinline__ void mma_tile1(uint32_t a_base, const uint32_t bh[8][4],
                                          int lane, float acc1[2][2][4]) {
#pragma unroll
    for (int mg = 0; mg < 2; mg++)
#pragma unroll
        for (int j = 0; j < 2; j++)
#pragma unroll
            for (int q = 0; q < 4; q++) acc1[mg][j][q] = 0.f;
    const uint32_t aoff = (uint32_t)(lane & 15) * ROWB + ((lane >> 4) << 4);
#pragma unroll
    for (int ks = 0; ks < 8; ks++) {
#pragma unroll
        for (int mg = 0; mg < 2; mg++) {
            uint32_t a0, a1, a2, a3;
            ldsm4(a0, a1, a2, a3, a_base + aoff + mg * 16 * ROWB + ks * 32);
            mma_f16(acc1[mg][0], a0, a1, a2, a3, bh[ks][0], bh[ks][1]);
            mma_f16(acc1[mg][1], a0, a1, a2, a3, bh[ks][2], bh[ks][3]);
        }
    }
}
// dump single-term accumulators to 32x132 smem tile
__device__ __forceinline__ void dump_acc1(float* sacc, const float acc[2][2][4],
                                          int wid, int lane) {
    const int gid = lane >> 2, tig = lane & 3;
    const int nb = wid * 16;
#pragma unroll
    for (int mg = 0; mg < 2; mg++) {
        int r = mg * 16 + gid;
#pragma unroll
        for (int j = 0; j < 2; j++) {
            int c = nb + j * 8 + tig * 2;
            *(float2*)(sacc + r * 132 + c) = make_float2(acc[mg][j][0], acc[mg][j][1]);
            *(float2*)(sacc + (r + 8) * 132 + c) = make_float2(acc[mg][j][2], acc[mg][j][3]);
        }
    }
}

// ---------------- small kernels -----------------------------------------------
__global__ void detect_kernel(const unsigned* __restrict__ w) {
    __shared__ int sflag;
    if (threadIdx.x == 0) sflag = 0;
    __syncthreads();
    unsigned v = 0;
    for (int i = threadIdx.x; i < 2048; i += blockDim.x) v |= w[2 * i + 1];
    if (v) atomicOr(&sflag, 1);
    __syncthreads();
    if (threadIdx.x == 0) g_is64 = sflag ? 0 : 1;
}
__global__ void zero_kernel() {
    int i = blockIdx.x * blockDim.x + threadIdx.x;
    const int total = Nn * 128;
    for (int k = i; k < total; k += gridDim.x * blockDim.x) g_agg[k] = 0.f;
    if (i < 1024) g_stats[i] = 0.f;
}
__global__ void prep_w_kernel(const float* __restrict__ Wu, const float* __restrict__ Wv,
                              const float* __restrict__ WB, const float* __restrict__ WC,
                              const float* __restrict__ WA) {
    int mtx = blockIdx.x;
    const float* W = (mtx == 0) ? Wu : (mtx == 1) ? Wv : (mtx == 2) ? WB : (mtx == 3) ? WC : WA;
    uint16_t* hi = g_Wp + (size_t)mtx * 2 * WPLANE;
    uint16_t* lo = hi + WPLANE;
    for (int idx = threadIdx.x; idx < 16384; idx += blockDim.x) {
        int f = idx >> 7, k = idx & 127;
        float w = W[idx];
        __half h = __float2half_rn(w);
        __half l = __float2half_rn((w - __half2float(h)) * 1024.0f);
        hi[f * ASTRIDE + k] = __half_as_ushort(h);
        lo[f * ASTRIDE + k] = __half_as_ushort(l);
    }
}

// ---------------- node GEMMs: persistent, cp.async pipelined, 2-term ----------------
__global__ void __launch_bounds__(256, 2) node_mma_kernel(
        const float* __restrict__ x, const float* __restrict__ bu,
        const float* __restrict__ bv, const float* __restrict__ bB,
        const float* __restrict__ bC) {
    extern __shared__ char sm[];
    uint32_t smb = smem_u32(sm);
    const int tid = threadIdx.x, wid = tid >> 5, lane = tid & 31;
    const int which = blockIdx.y;
    float* sb = (float*)(sm + SB_BIAS);
    const float* bias = (which == 0) ? bu : (which == 1) ? bv : (which == 2) ? bB : bC;
    if (tid < 128) sb[tid] = bias[tid];

    uint32_t bh[8][4], bl[8][4];
    load_wregs(sm, smb, which, wid, lane, bh, bl);

    uint16_t* dsth = (which == 1) ? g_CV + 128 : (which == 2) ? g_B : g_CV;
    const int rstride = (which == 0 || which == 2) ? 128 : 256;

    const int gid = lane >> 2, tig = lane & 3;
    const int nb = wid * 16;

    long t = blockIdx.x;
    if (t < NT_N) {
        int v0 = Nn - (int)t * 32; if (v0 > 32) v0 = 32;
        cpa_tile(smb + SB_F32, x + t * 4096, v0);
    }
    CP_COMMIT();
    int ib = 0;
    for (; t < NT_N; t += gridDim.x) {
        CP_WAIT0();
        __syncthreads();
        cvt_half((uint16_t*)(sm + SB_A), (const float*)(sm + SB_F32 + ib * 16384));
        long tn = t + gridDim.x;
        if (tn < NT_N) {
            int vn = Nn - (int)tn * 32; if (vn > 32) vn = 32;
            cpa_tile(smb + SB_F32 + (ib ^ 1) * 16384, x + tn * 4096, vn);
        }
        CP_COMMIT();
        __syncthreads();
        float acc1[2][2][4], acc2[2][2][4];
        mma_tile2(smb + SB_A, bh, bl, lane, acc1, acc2);
#pragma unroll
        for (int mg = 0; mg < 2; mg++) {
            const int r0 = (int)t * 32 + mg * 16 + gid;
#pragma unroll
            for (int j = 0; j < 2; j++) {
                int c = nb + j * 8 + tig * 2;
                float2 bb = *(const float2*)(sb + c);
                float v0x = fmaf(acc2[mg][j][0], ISCALE, acc1[mg][j][0]) + bb.x;
                float v0y = fmaf(acc2[mg][j][1], ISCALE, acc1[mg][j][1]) + bb.y;
                float v1x = fmaf(acc2[mg][j][2], ISCALE, acc1[mg][j][2]) + bb.x;
                float v1y = fmaf(acc2[mg][j][3], ISCALE, acc1[mg][j][3]) + bb.y;
                if (which == 0) {
                    if (r0 < Nn)
                        *(float2*)(g_U + (size_t)r0 * 128 + c) = make_float2(v0x, v0y);
                    if (r0 + 8 < Nn)
                        *(float2*)(g_U + (size_t)(r0 + 8) * 128 + c) = make_float2(v1x, v1y);
                } else {
                    if (r0 < Nn) {
                        __half2 h = __floats2half2_rn(v0x, v0y);
                        *(uint32_t*)(dsth + (size_t)r0 * rstride + c) = *(uint32_t*)&h;
                    }
                    if (r0 + 8 < Nn) {
                        __half2 h = __floats2half2_rn(v1x, v1y);
                        *(uint32_t*)(dsth + (size_t)(r0 + 8) * rstride + c) = *(uint32_t*)&h;
                    }
                }
            }
        }
        ib ^= 1;
    }
}

// ---------------- edge pass 1: single-term GEMM + fp16 gathers + BN stats ------------
__global__ void __launch_bounds__(256, 2) edge1_kernel(
        const float* __restrict__ ea, const void* __restrict__ eidx,
        const float* __restrict__ bA) {
    extern __shared__ char sm[];
    uint32_t smb = smem_u32(sm);
    const int tid = threadIdx.x, wid = tid >> 5, lane = tid & 31;
    const int is64 = g_is64;
    float* sb = (float*)(sm + SB_BIAS);
    int* sidx = (int*)(sm + SB_IDX);
    float* sacc = (float*)(sm + SB_ACC);
    if (tid < 128) sb[tid] = bA[tid];

    uint32_t bh[8][4];
    load_wregs_hi(sm, smb, 4, wid, lane, bh);   // ends with syncthreads

    const float4 bias4 = *(const float4*)(sb + lane * 4);
    float s1[4] = {0.f, 0.f, 0.f, 0.f};
    float s2[4] = {0.f, 0.f, 0.f, 0.f};

    long t = blockIdx.x;
    int idxreg = 0;
    if (t < NT_E) {
        cpa_tile(smb + SB_F32, ea + t * 4096, 32);
        if (tid < 64)
            idxreg = ld_idx(eidx, (tid < 32) ? (t * 32 + tid)
                                             : ((size_t)Ee + t * 32 + (tid - 32)), is64);
    }
    CP_COMMIT();
    int ib = 0;
    for (; t < NT_E; t += gridDim.x) {
        CP_WAIT0();
        __syncthreads();
        if (tid < 64) sidx[tid] = idxreg;
        cvt_half((uint16_t*)(sm + SB_A), (const float*)(sm + SB_F32 + ib * 16384));
        long tn = t + gridDim.x;
        if (tn < NT_E) {
            cpa_tile(smb + SB_F32 + (ib ^ 1) * 16384, ea + tn * 4096, 32);
            if (tid < 64)
                idxreg = ld_idx(eidx, (tid < 32) ? (tn * 32 + tid)
                                                 : ((size_t)Ee + tn * 32 + (tid - 32)), is64);
        }
        CP_COMMIT();
        __syncthreads();
        float acc1[2][2][4];
        mma_tile1(smb + SB_A, bh, lane, acc1);
        dump_acc1(sacc, acc1, wid, lane);
        __syncthreads();

        // warp wid handles edges wid*4 .. wid*4+3 with fully coalesced fp16 rows
#pragma unroll
        for (int k = 0; k < 4; k++) {
            int r = wid * 4 + k;
            int ridx = sidx[r], cidx = sidx[32 + r];
            float4 a = *(const float4*)(sacc + r * 132 + lane * 4);
            float4 b = h4_to_f4(*(const uint2*)(g_B + (size_t)ridx * 128 + lane * 4));
            float4 cg = h4_to_f4(*(const uint2*)(g_CV + (size_t)cidx * 256 + lane * 4));
            float4 v;
            v.x = a.x + bias4.x + b.x + cg.x;
            v.y = a.y + bias4.y + b.y + cg.y;
            v.z = a.z + bias4.z + b.z + cg.z;
            v.w = a.w + bias4.w + b.w + cg.w;
            __half2 p0 = __floats2half2_rn(v.x, v.y);
            __half2 p1 = __floats2half2_rn(v.z, v.w);
            uint2 pk;
            pk.x = *(uint32_t*)&p0;
            pk.y = *(uint32_t*)&p1;
            *(uint2*)(g_edge_in + (t * 32 + r) * 128 + lane * 4) = pk;
            s1[0] += v.x; s2[0] = fmaf(v.x, v.x, s2[0]);
            s1[1] += v.y; s2[1] = fmaf(v.y, v.y, s2[1]);
            s1[2] += v.z; s2[2] = fmaf(v.z, v.z, s2[2]);
            s1[3] += v.w; s2[3] = fmaf(v.w, v.w, s2[3]);
        }
        ib ^= 1;
    }
    // block-level stat reduction: sacc reused as scratch (2048 floats)
    __syncthreads();
#pragma unroll
    for (int q = 0; q < 4; q++) {
        sacc[wid * 128 + lane * 4 + q] = s1[q];
        sacc[1024 + wid * 128 + lane * 4 + q] = s2[q];
    }
    __syncthreads();
    if (tid < 128) {
        float a = 0.f, b = 0.f;
#pragma unroll
        for (int w = 0; w < 8; w++) {
            a += sacc[w * 128 + tid];
            b += sacc[1024 + w * 128 + tid];
        }
        atomicAdd(&g_stats[tid], a);
        atomicAdd(&g_stats[128 + tid], b);
    }
}

// ---------------- finalize BN stats (0=edge, 1=node) --------------------------------
__global__ void finalize_kernel(int which, float inv) {
    int f = threadIdx.x;
    float s1 = g_stats[which * 256 + f];
    float s2 = g_stats[which * 256 + 128 + f];
    float mean = s1 * inv;
    float var = fmaxf(s2 * inv - mean * mean, 0.f);
    g_stats[512 + which * 256 + f] = mean;
    g_stats[512 + which * 256 + 128 + f] = rsqrtf(var + 1e-5f);
}

// ---------------- edge pass 2 ----------------------------------------------------------
__global__ void edge_pass2_kernel(const float* __restrict__ ea, const void* __restrict__ eidx,
                                  const float* __restrict__ gam, const float* __restrict__ bet,
                                  float* __restrict__ out_e) {
    int e = blockIdx.x * 8 + (threadIdx.x >> 5);
    if (e >= Ee) return;
    int c = (threadIdx.x & 31) * 4;
    int row, col;
    if (g_is64) {
        const long long* p = (const long long*)eidx;
        row = (int)p[e];
        col = (int)p[(size_t)Ee + e];
    } else {
        const int* p = (const int*)eidx;
        row = p[e];
        col = p[Ee + e];
    }
    size_t base = (size_t)e * 128 + c;
    uint2 pk;
    asm("ld.global.cs.v2.u32 {%0, %1}, [%2];"
        : "=r"(pk.x), "=r"(pk.y) : "l"(g_edge_in + base));
    float4 ein = h4_to_f4(pk);
    float4 mu = *(const float4*)(g_stats + 512 + c);
    float4 rs = *(const float4*)(g_stats + 640 + c);
    float4 gm = __ldg((const float4*)(gam + c));
    float4 bt = __ldg((const float4*)(bet + c));
    float4 a4;
    asm("ld.global.cs.v4.f32 {%0, %1, %2, %3}, [%4];"
        : "=f"(a4.x), "=f"(a4.y), "=f"(a4.z), "=f"(a4.w) : "l"(ea + base));
    float4 eo;
    eo.x = a4.x + fmaxf(gm.x * (ein.x - mu.x) * rs.x + bt.x, 0.f);
    eo.y = a4.y + fmaxf(gm.y * (ein.y - mu.y) * rs.y + bt.y, 0.f);
    eo.z = a4.z + fmaxf(gm.z * (ein.z - mu.z) * rs.z + bt.z, 0.f);
    eo.w = a4.w + fmaxf(gm.w * (ein.w - mu.w) * rs.w + bt.w, 0.f);
    asm volatile("st.global.cs.v4.f32 [%0], {%1, %2, %3, %4};"
                 :: "l"(out_e + base), "f"(eo.x), "f"(eo.y), "f"(eo.z), "f"(eo.w) : "memory");

    float4 v4 = h4_to_f4(*(const uint2*)(g_CV + (size_t)col * 256 + 128 + c));
    float mx = v4.x / (1.f + __expf(-eo.x));
    float my = v4.y / (1.f + __expf(-eo.y));
    float mz = v4.z / (1.f + __expf(-eo.z));
    float mw = v4.w / (1.f + __expf(-eo.w));
    float* dst = g_agg + (size_t)row * 128 + c;
    asm volatile("red.global.add.v4.f32 [%0], {%1, %2, %3, %4};"
                 :: "l"(dst), "f"(mx), "f"(my), "f"(mz), "f"(mw) : "memory");
}

// ---------------- node stats / output ---------------------------------------------------
__global__ void node_stats_kernel() {
    int f = threadIdx.x;
    int n0 = blockIdx.x * 64;
    float s1 = 0.f, s2 = 0.f;
    for (int r = 0; r < 64; r++) {
        int n = n0 + r;
        if (n < Nn) {
            float v = g_U[(size_t)n * 128 + f] + g_agg[(size_t)n * 128 + f];
            s1 += v;
            s2 += v * v;
        }
    }
    atomicAdd(&g_stats[256 + f], s1);
    atomicAdd(&g_stats[384 + f], s2);
}
__global__ void node_out_kernel(const float* __restrict__ x, const float* __restrict__ gam,
                                const float* __restrict__ bet, float* __restrict__ out_x) {
    int i = blockIdx.x * blockDim.x + threadIdx.x;
    if (i >= Nn * 32) return;
    int c = (i & 31) * 4;
    size_t base = (size_t)i * 4;
    float4 u = *(const float4*)(g_U + base);
    float4 a = *(const float4*)(g_agg + base);
    float4 mu = *(const float4*)(g_stats + 768 + c);
    float4 rs = *(const float4*)(g_stats + 896 + c);
    float4 gm = __ldg((const float4*)(gam + c));
    float4 bt = __ldg((const float4*)(bet + c));
    float4 xv = __ldg((const float4*)(x + base));
    float4 o;
    o.x = xv.x + fmaxf(gm.x * ((u.x + a.x) - mu.x) * rs.x + bt.x, 0.f);
    o.y = xv.y + fmaxf(gm.y * ((u.y + a.y) - mu.y) * rs.y + bt.y, 0.f);
    o.z = xv.z + fmaxf(gm.z * ((u.z + a.z) - mu.z) * rs.z + bt.z, 0.f);
    o.w = xv.w + fmaxf(gm.w * ((u.w + a.w) - mu.w) * rs.w + bt.w, 0.f);
    *(float4*)(out_x + base) = o;
}

// ---------------- launch -----------------------------------------------------------------
extern "C" void kernel_launch(void* const* d_in, const int* in_sizes, int n_in,
                              void* d_out, int out_size) {
    (void)in_sizes; (void)n_in; (void)out_size;
    const float* x  = (const float*)d_in[0];
    const void*  ei = d_in[1];
    const float* ea = (const float*)d_in[2];
    const float* Wu = (const float*)d_in[3];
    const float* bu = (const float*)d_in[4];
    const float* Wv = (const float*)d_in[5];
    const float* bv = (const float*)d_in[6];
    const float* WA = (const float*)d_in[7];
    const float* bA = (const float*)d_in[8];
    const float* WB = (const float*)d_in[9];
    const float* bB = (const float*)d_in[10];
    const float* WC = (const float*)d_in[11];
    const float* bC = (const float*)d_in[12];
    const float* gn_g = (const float*)d_in[13];
    const float* gn_b = (const float*)d_in[14];
    const float* ge_g = (const float*)d_in[15];
    const float* ge_b = (const float*)d_in[16];

    float* out   = (float*)d_out;
    float* out_x = out;
    float* out_e = out + (size_t)Nn * Dd;

    cudaFuncSetAttribute(node_mma_kernel, cudaFuncAttributeMaxDynamicSharedMemorySize, S_SIZE_N);
    cudaFuncSetAttribute(edge1_kernel, cudaFuncAttributeMaxDynamicSharedMemorySize, S_SIZE_E);

    detect_kernel<<<1, 256>>>((const unsigned*)ei);
    zero_kernel<<<2048, 256>>>();
    prep_w_kernel<<<5, 256>>>(Wu, Wv, WB, WC, WA);
    node_mma_kernel<<<dim3(74, 4), 256, S_SIZE_N>>>(x, bu, bv, bB, bC);
    edge1_kernel<<<296, 256, S_SIZE_E>>>(ea, ei, bA);
    finalize_kernel<<<1, 128>>>(0, 1.0f / (float)Ee);
    edge_pass2_kernel<<<(Ee + 7) / 8, 256>>>(ea, ei, ge_g, ge_b, out_e);
    node_stats_kernel<<<(Nn + 63) / 64, 128>>>();
    finalize_kernel<<<1, 128>>>(1, 1.0f / (float)Nn);
    node_out_kernel<<<(Nn * 32 + 255) / 256, 256>>>(x, gn_g, gn_b, out_x);
}

// round 16
// speedup vs baseline: 1.9209x; 1.0699x over previous
#include <cuda_runtime.h>
#include <cuda_fp16.h>
#include <cstdint>

#define Nn 50000
#define Ee 640000
#define Dd 128

#define ASTRIDE 136              // uint16 elems per row (128 + 8 pad)
#define ROWB    (ASTRIDE * 2)    // 272 bytes per row
#define WPLANE  (128 * ASTRIDE)  // uint16 elems per W plane
#define NT_E    (Ee / 32)        // 20000 edge tiles
#define NT_N    ((Nn + 31) / 32) // 1563 node tiles

// ---------------- device scratch ------------------------------------------
__device__ float g_U[Nn * 128];
__device__ __align__(16) uint16_t g_B[Nn * 128];     // fp16 Bx table
__device__ __align__(16) uint16_t g_CV[Nn * 256];    // fp16 [Cx | Vx] table
__device__ __align__(16) uint16_t g_edge_in[(size_t)Ee * 128]; // fp16 pre-BN edge acts
__device__ float g_agg[Nn * 128];
__device__ float g_stats[1024];
__device__ __align__(16) uint16_t g_Wp[5 * WPLANE];  // fp16 W planes
__device__ int g_is64;

// ---------------- smem layout (bytes) --------------------------------------
#define SB_BIAS 0                 // 512
#define SB_IDX  512               // 64 ints
#define SB_F32  2048              // 2 x 16384 fp32 A staging (cp.async)
#define SB_A    34816             // fp16 A plane 8704
#define SB_ACC  43520             // 32 x 132 fp32 = 16896 (edge only)
#define S_SIZE_N 43520
#define S_SIZE_E 60416

// ---------------- PTX helpers ------------------------------------------------
__device__ __forceinline__ uint32_t smem_u32(const void* p) {
    uint32_t a;
    asm("{ .reg .u64 t; cvta.to.shared.u64 t, %1; cvt.u32.u64 %0, t; }" : "=r"(a) : "l"(p));
    return a;
}
__device__ __forceinline__ void ldsm4(uint32_t& r0, uint32_t& r1, uint32_t& r2,
                                      uint32_t& r3, uint32_t addr) {
    asm volatile("ldmatrix.sync.aligned.m8n8.x4.shared.b16 {%0,%1,%2,%3}, [%4];"
                 : "=r"(r0), "=r"(r1), "=r"(r2), "=r"(r3) : "r"(addr));
}
__device__ __forceinline__ void mma_f16(float* d, uint32_t a0, uint32_t a1,
                                        uint32_t a2, uint32_t a3,
                                        uint32_t b0, uint32_t b1) {
    asm volatile("mma.sync.aligned.m16n8k16.row.col.f32.f16.f16.f32 "
        "{%0,%1,%2,%3}, {%4,%5,%6,%7}, {%8,%9}, {%0,%1,%2,%3};"
        : "+f"(d[0]), "+f"(d[1]), "+f"(d[2]), "+f"(d[3])
        : "r"(a0), "r"(a1), "r"(a2), "r"(a3), "r"(b0), "r"(b1));
}
__device__ __forceinline__ void cp_async16(uint32_t saddr, const void* gptr) {
    asm volatile("cp.async.cg.shared.global [%0], [%1], 16;" :: "r"(saddr), "l"(gptr));
}
#define CP_COMMIT() asm volatile("cp.async.commit_group;" ::: "memory")
#define CP_WAIT0()  asm volatile("cp.async.wait_group 0;" ::: "memory")

// unpack 4 halves (uint2) -> float4
__device__ __forceinline__ float4 h4_to_f4(uint2 pk) {
    float2 a = __half22float2(*(__half2*)&pk.x);
    float2 b = __half22float2(*(__half2*)&pk.y);
    return make_float4(a.x, a.y, b.x, b.y);
}

// stage a 32x128 fp32 tile via cp.async; OOB rows clamp to row 0 (guarded later)
__device__ __forceinline__ void cpa_tile(uint32_t sdst, const float* __restrict__ src,
                                         int valid_rows) {
#pragma unroll
    for (int p = 0; p < 4; p++) {
        int idx = p * 256 + threadIdx.x;
        int row = idx >> 5;
        const float4* g = (const float4*)src + (row < valid_rows ? idx : (idx & 31));
        cp_async16(sdst + idx * 16, g);
    }
}
// convert fp32 smem tile -> single fp16 plane in smem
__device__ __forceinline__ void cvt_half(uint16_t* __restrict__ dst,
                                         const float* __restrict__ srcf) {
#pragma unroll
    for (int p = 0; p < 4; p++) {
        int idx = p * 256 + threadIdx.x;
        int row = idx >> 5, k4 = (idx & 31) << 2;
        float4 v = ((const float4*)srcf)[idx];
        __half2 h0 = __floats2half2_rn(v.x, v.y);
        __half2 h1 = __floats2half2_rn(v.z, v.w);
        uint2 u;
        u.x = *(uint32_t*)&h0;
        u.y = *(uint32_t*)&h1;
        *(uint2*)(dst + row * ASTRIDE + k4) = u;
    }
}
__device__ __forceinline__ int ld_idx(const void* p, size_t i, int is64) {
    return is64 ? (int)((const long long*)p)[i] : ((const int*)p)[i];
}

// stage W plane (one-time) into SB_F32 scratch; load this warp's fragments
__device__ __forceinline__ void load_wregs_hi(char* sm, uint32_t smb, int mtx,
                                              int wid, int lane, uint32_t bh[8][4]) {
    const uint32_t woffs = smb + SB_F32
        + (uint32_t)(wid * 16 + (lane & 7) + ((lane >> 4) << 3)) * ROWB
        + (((lane >> 3) & 1) << 4);
    uint4* d = (uint4*)(sm + SB_F32);
    const uint4* s = (const uint4*)(g_Wp + (size_t)mtx * WPLANE);
    for (int i = threadIdx.x; i < 2176; i += 256) d[i] = s[i];
    __syncthreads();
#pragma unroll
    for (int ks = 0; ks < 8; ks++)
        ldsm4(bh[ks][0], bh[ks][1], bh[ks][2], bh[ks][3], woffs + ks * 32);
    __syncthreads();
}

// 1-term MMA over a 32x128 fp16 A tile
__device__ __forceinline__ void mma_tile1(uint32_t a_base, const uint32_t bh[8][4],
                                          int lane, float acc1[2][2][4]) {
#pragma unroll
    for (int mg = 0; mg < 2; mg++)
#pragma unroll
        for (int j = 0; j < 2; j++)
#pragma unroll
            for (int q = 0; q < 4; q++) acc1[mg][j][q] = 0.f;
    const uint32_t aoff = (uint32_t)(lane & 15) * ROWB + ((lane >> 4) << 4);
#pragma unroll
    for (int ks = 0; ks < 8; ks++) {
#pragma unroll
        for (int mg = 0; mg < 2; mg++) {
            uint32_t a0, a1, a2, a3;
            ldsm4(a0, a1, a2, a3, a_base + aoff + mg * 16 * ROWB + ks * 32);
            mma_f16(acc1[mg][0], a0, a1, a2, a3, bh[ks][0], bh[ks][1]);
            mma_f16(acc1[mg][1], a0, a1, a2, a3, bh[ks][2], bh[ks][3]);
        }
    }
}
// dump accumulators to 32x132 smem tile
__device__ __forceinline__ void dump_acc1(float* sacc, const float acc[2][2][4],
                                          int wid, int lane) {
    const int gid = lane >> 2, tig = lane & 3;
    const int nb = wid * 16;
#pragma unroll
    for (int mg = 0; mg < 2; mg++) {
        int r = mg * 16 + gid;
#pragma unroll
        for (int j = 0; j < 2; j++) {
            int c = nb + j * 8 + tig * 2;
            *(float2*)(sacc + r * 132 + c) = make_float2(acc[mg][j][0], acc[mg][j][1]);
            *(float2*)(sacc + (r + 8) * 132 + c) = make_float2(acc[mg][j][2], acc[mg][j][3]);
        }
    }
}

// ---------------- small kernels -----------------------------------------------
__global__ void detect_kernel(const unsigned* __restrict__ w) {
    __shared__ int sflag;
    if (threadIdx.x == 0) sflag = 0;
    __syncthreads();
    unsigned v = 0;
    for (int i = threadIdx.x; i < 2048; i += blockDim.x) v |= w[2 * i + 1];
    if (v) atomicOr(&sflag, 1);
    __syncthreads();
    if (threadIdx.x == 0) g_is64 = sflag ? 0 : 1;
}
__global__ void zero_kernel() {
    int i = blockIdx.x * blockDim.x + threadIdx.x;
    const int total = Nn * 128;
    for (int k = i; k < total; k += gridDim.x * blockDim.x) g_agg[k] = 0.f;
    if (i < 1024) g_stats[i] = 0.f;
}
__global__ void prep_w_kernel(const float* __restrict__ Wu, const float* __restrict__ Wv,
                              const float* __restrict__ WB, const float* __restrict__ WC,
                              const float* __restrict__ WA) {
    int mtx = blockIdx.x;
    const float* W = (mtx == 0) ? Wu : (mtx == 1) ? Wv : (mtx == 2) ? WB : (mtx == 3) ? WC : WA;
    uint16_t* hi = g_Wp + (size_t)mtx * WPLANE;
    for (int idx = threadIdx.x; idx < 16384; idx += blockDim.x) {
        int f = idx >> 7, k = idx & 127;
        hi[f * ASTRIDE + k] = __half_as_ushort(__float2half_rn(W[idx]));
    }
}

// ---------------- node GEMMs: persistent, cp.async pipelined, 1-term ----------------
__global__ void __launch_bounds__(256, 2) node_mma_kernel(
        const float* __restrict__ x, const float* __restrict__ bu,
        const float* __restrict__ bv, const float* __restrict__ bB,
        const float* __restrict__ bC) {
    extern __shared__ char sm[];
    uint32_t smb = smem_u32(sm);
    const int tid = threadIdx.x, wid = tid >> 5, lane = tid & 31;
    const int which = blockIdx.y;
    float* sb = (float*)(sm + SB_BIAS);
    const float* bias = (which == 0) ? bu : (which == 1) ? bv : (which == 2) ? bB : bC;
    if (tid < 128) sb[tid] = bias[tid];

    uint32_t bh[8][4];
    load_wregs_hi(sm, smb, which, wid, lane, bh);

    uint16_t* dsth = (which == 1) ? g_CV + 128 : (which == 2) ? g_B : g_CV;
    const int rstride = (which == 0 || which == 2) ? 128 : 256;

    const int gid = lane >> 2, tig = lane & 3;
    const int nb = wid * 16;

    long t = blockIdx.x;
    if (t < NT_N) {
        int v0 = Nn - (int)t * 32; if (v0 > 32) v0 = 32;
        cpa_tile(smb + SB_F32, x + t * 4096, v0);
    }
    CP_COMMIT();
    int ib = 0;
    for (; t < NT_N; t += gridDim.x) {
        CP_WAIT0();
        __syncthreads();
        cvt_half((uint16_t*)(sm + SB_A), (const float*)(sm + SB_F32 + ib * 16384));
        long tn = t + gridDim.x;
        if (tn < NT_N) {
            int vn = Nn - (int)tn * 32; if (vn > 32) vn = 32;
            cpa_tile(smb + SB_F32 + (ib ^ 1) * 16384, x + tn * 4096, vn);
        }
        CP_COMMIT();
        __syncthreads();
        float acc1[2][2][4];
        mma_tile1(smb + SB_A, bh, lane, acc1);
#pragma unroll
        for (int mg = 0; mg < 2; mg++) {
            const int r0 = (int)t * 32 + mg * 16 + gid;
#pragma unroll
            for (int j = 0; j < 2; j++) {
                int c = nb + j * 8 + tig * 2;
                float2 bb = *(const float2*)(sb + c);
                float v0x = acc1[mg][j][0] + bb.x;
                float v0y = acc1[mg][j][1] + bb.y;
                float v1x = acc1[mg][j][2] + bb.x;
                float v1y = acc1[mg][j][3] + bb.y;
                if (which == 0) {
                    if (r0 < Nn)
                        *(float2*)(g_U + (size_t)r0 * 128 + c) = make_float2(v0x, v0y);
                    if (r0 + 8 < Nn)
                        *(float2*)(g_U + (size_t)(r0 + 8) * 128 + c) = make_float2(v1x, v1y);
                } else {
                    if (r0 < Nn) {
                        __half2 h = __floats2half2_rn(v0x, v0y);
                        *(uint32_t*)(dsth + (size_t)r0 * rstride + c) = *(uint32_t*)&h;
                    }
                    if (r0 + 8 < Nn) {
                        __half2 h = __floats2half2_rn(v1x, v1y);
                        *(uint32_t*)(dsth + (size_t)(r0 + 8) * rstride + c) = *(uint32_t*)&h;
                    }
                }
            }
        }
        ib ^= 1;
    }
}

// ---------------- edge pass 1: 1-term GEMM + fp16 gathers + BN stats, 3 CTAs/SM ------
__global__ void __launch_bounds__(256, 3) edge1_kernel(
        const float* __restrict__ ea, const void* __restrict__ eidx,
        const float* __restrict__ bA) {
    extern __shared__ char sm[];
    uint32_t smb = smem_u32(sm);
    const int tid = threadIdx.x, wid = tid >> 5, lane = tid & 31;
    const int is64 = g_is64;
    float* sb = (float*)(sm + SB_BIAS);
    int* sidx = (int*)(sm + SB_IDX);
    float* sacc = (float*)(sm + SB_ACC);
    if (tid < 128) sb[tid] = bA[tid];

    uint32_t bh[8][4];
    load_wregs_hi(sm, smb, 4, wid, lane, bh);   // ends with syncthreads

    const float4 bias4 = *(const float4*)(sb + lane * 4);
    float s1[4] = {0.f, 0.f, 0.f, 0.f};
    float s2[4] = {0.f, 0.f, 0.f, 0.f};

    long t = blockIdx.x;
    int idxreg = 0;
    if (t < NT_E) {
        cpa_tile(smb + SB_F32, ea + t * 4096, 32);
        if (tid < 64)
            idxreg = ld_idx(eidx, (tid < 32) ? (t * 32 + tid)
                                             : ((size_t)Ee + t * 32 + (tid - 32)), is64);
    }
    CP_COMMIT();
    int ib = 0;
    for (; t < NT_E; t += gridDim.x) {
        CP_WAIT0();
        __syncthreads();
        if (tid < 64) sidx[tid] = idxreg;
        cvt_half((uint16_t*)(sm + SB_A), (const float*)(sm + SB_F32 + ib * 16384));
        long tn = t + gridDim.x;
        if (tn < NT_E) {
            cpa_tile(smb + SB_F32 + (ib ^ 1) * 16384, ea + tn * 4096, 32);
            if (tid < 64)
                idxreg = ld_idx(eidx, (tid < 32) ? (tn * 32 + tid)
                                                 : ((size_t)Ee + tn * 32 + (tid - 32)), is64);
        }
        CP_COMMIT();
        __syncthreads();
        float acc1[2][2][4];
        mma_tile1(smb + SB_A, bh, lane, acc1);
        dump_acc1(sacc, acc1, wid, lane);
        __syncthreads();

        // warp wid handles edges wid*4 .. wid*4+3 with fully coalesced fp16 rows
#pragma unroll
        for (int k = 0; k < 4; k++) {
            int r = wid * 4 + k;
            int ridx = sidx[r], cidx = sidx[32 + r];
            float4 a = *(const float4*)(sacc + r * 132 + lane * 4);
            float4 b = h4_to_f4(*(const uint2*)(g_B + (size_t)ridx * 128 + lane * 4));
            float4 cg = h4_to_f4(*(const uint2*)(g_CV + (size_t)cidx * 256 + lane * 4));
            float4 v;
            v.x = a.x + bias4.x + b.x + cg.x;
            v.y = a.y + bias4.y + b.y + cg.y;
            v.z = a.z + bias4.z + b.z + cg.z;
            v.w = a.w + bias4.w + b.w + cg.w;
            __half2 p0 = __floats2half2_rn(v.x, v.y);
            __half2 p1 = __floats2half2_rn(v.z, v.w);
            uint2 pk;
            pk.x = *(uint32_t*)&p0;
            pk.y = *(uint32_t*)&p1;
            *(uint2*)(g_edge_in + (t * 32 + r) * 128 + lane * 4) = pk;
            s1[0] += v.x; s2[0] = fmaf(v.x, v.x, s2[0]);
            s1[1] += v.y; s2[1] = fmaf(v.y, v.y, s2[1]);
            s1[2] += v.z; s2[2] = fmaf(v.z, v.z, s2[2]);
            s1[3] += v.w; s2[3] = fmaf(v.w, v.w, s2[3]);
        }
        ib ^= 1;
    }
    // block-level stat reduction: sacc reused as scratch (2048 floats)
    __syncthreads();
#pragma unroll
    for (int q = 0; q < 4; q++) {
        sacc[wid * 128 + lane * 4 + q] = s1[q];
        sacc[1024 + wid * 128 + lane * 4 + q] = s2[q];
    }
    __syncthreads();
    if (tid < 128) {
        float a = 0.f, b = 0.f;
#pragma unroll
        for (int w = 0; w < 8; w++) {
            a += sacc[w * 128 + tid];
            b += sacc[1024 + w * 128 + tid];
        }
        atomicAdd(&g_stats[tid], a);
        atomicAdd(&g_stats[128 + tid], b);
    }
}

// ---------------- finalize BN stats (0=edge, 1=node) --------------------------------
__global__ void finalize_kernel(int which, float inv) {
    int f = threadIdx.x;
    float s1 = g_stats[which * 256 + f];
    float s2 = g_stats[which * 256 + 128 + f];
    float mean = s1 * inv;
    float var = fmaxf(s2 * inv - mean * mean, 0.f);
    g_stats[512 + which * 256 + f] = mean;
    g_stats[512 + which * 256 + 128 + f] = rsqrtf(var + 1e-5f);
}

// ---------------- edge pass 2 ----------------------------------------------------------
__global__ void edge_pass2_kernel(const float* __restrict__ ea, const void* __restrict__ eidx,
                                  const float* __restrict__ gam, const float* __restrict__ bet,
                                  float* __restrict__ out_e) {
    int e = blockIdx.x * 8 + (threadIdx.x >> 5);
    if (e >= Ee) return;
    int c = (threadIdx.x & 31) * 4;
    int row, col;
    if (g_is64) {
        const long long* p = (const long long*)eidx;
        row = (int)p[e];
        col = (int)p[(size_t)Ee + e];
    } else {
        const int* p = (const int*)eidx;
        row = p[e];
        col = p[Ee + e];
    }
    size_t base = (size_t)e * 128 + c;
    uint2 pk;
    asm("ld.global.cs.v2.u32 {%0, %1}, [%2];"
        : "=r"(pk.x), "=r"(pk.y) : "l"(g_edge_in + base));
    float4 ein = h4_to_f4(pk);
    float4 mu = *(const float4*)(g_stats + 512 + c);
    float4 rs = *(const float4*)(g_stats + 640 + c);
    float4 gm = __ldg((const float4*)(gam + c));
    float4 bt = __ldg((const float4*)(bet + c));
    float4 a4;
    asm("ld.global.cs.v4.f32 {%0, %1, %2, %3}, [%4];"
        : "=f"(a4.x), "=f"(a4.y), "=f"(a4.z), "=f"(a4.w) : "l"(ea + base));
    float4 eo;
    eo.x = a4.x + fmaxf(gm.x * (ein.x - mu.x) * rs.x + bt.x, 0.f);
    eo.y = a4.y + fmaxf(gm.y * (ein.y - mu.y) * rs.y + bt.y, 0.f);
    eo.z = a4.z + fmaxf(gm.z * (ein.z - mu.z) * rs.z + bt.z, 0.f);
    eo.w = a4.w + fmaxf(gm.w * (ein.w - mu.w) * rs.w + bt.w, 0.f);
    asm volatile("st.global.cs.v4.f32 [%0], {%1, %2, %3, %4};"
                 :: "l"(out_e + base), "f"(eo.x), "f"(eo.y), "f"(eo.z), "f"(eo.w) : "memory");

    float4 v4 = h4_to_f4(*(const uint2*)(g_CV + (size_t)col * 256 + 128 + c));
    float mx = v4.x / (1.f + __expf(-eo.x));
    float my = v4.y / (1.f + __expf(-eo.y));
    float mz = v4.z / (1.f + __expf(-eo.z));
    float mw = v4.w / (1.f + __expf(-eo.w));
    float* dst = g_agg + (size_t)row * 128 + c;
    asm volatile("red.global.add.v4.f32 [%0], {%1, %2, %3, %4};"
                 :: "l"(dst), "f"(mx), "f"(my), "f"(mz), "f"(mw) : "memory");
}

// ---------------- node stats / output ---------------------------------------------------
__global__ void node_stats_kernel() {
    int f = threadIdx.x;
    int n0 = blockIdx.x * 64;
    float s1 = 0.f, s2 = 0.f;
    for (int r = 0; r < 64; r++) {
        int n = n0 + r;
        if (n < Nn) {
            float v = g_U[(size_t)n * 128 + f] + g_agg[(size_t)n * 128 + f];
            s1 += v;
            s2 += v * v;
        }
    }
    atomicAdd(&g_stats[256 + f], s1);
    atomicAdd(&g_stats[384 + f], s2);
}
__global__ void node_out_kernel(const float* __restrict__ x, const float* __restrict__ gam,
                                const float* __restrict__ bet, float* __restrict__ out_x) {
    int i = blockIdx.x * blockDim.x + threadIdx.x;
    if (i >= Nn * 32) return;
    int c = (i & 31) * 4;
    size_t base = (size_t)i * 4;
    float4 u = *(const float4*)(g_U + base);
    float4 a = *(const float4*)(g_agg + base);
    float4 mu = *(const float4*)(g_stats + 768 + c);
    float4 rs = *(const float4*)(g_stats + 896 + c);
    float4 gm = __ldg((const float4*)(gam + c));
    float4 bt = __ldg((const float4*)(bet + c));
    float4 xv = __ldg((const float4*)(x + base));
    float4 o;
    o.x = xv.x + fmaxf(gm.x * ((u.x + a.x) - mu.x) * rs.x + bt.x, 0.f);
    o.y = xv.y + fmaxf(gm.y * ((u.y + a.y) - mu.y) * rs.y + bt.y, 0.f);
    o.z = xv.z + fmaxf(gm.z * ((u.z + a.z) - mu.z) * rs.z + bt.z, 0.f);
    o.w = xv.w + fmaxf(gm.w * ((u.w + a.w) - mu.w) * rs.w + bt.w, 0.f);
    *(float4*)(out_x + base) = o;
}

// ---------------- launch -----------------------------------------------------------------
extern "C" void kernel_launch(void* const* d_in, const int* in_sizes, int n_in,
                              void* d_out, int out_size) {
    (void)in_sizes; (void)n_in; (void)out_size;
    const float* x  = (const float*)d_in[0];
    const void*  ei = d_in[1];
    const float* ea = (const float*)d_in[2];
    const float* Wu = (const float*)d_in[3];
    const float* bu = (const float*)d_in[4];
    const float* Wv = (const float*)d_in[5];
    const float* bv = (const float*)d_in[6];
    const float* WA = (const float*)d_in[7];
    const float* bA = (const float*)d_in[8];
    const float* WB = (const float*)d_in[9];
    const float* bB = (const float*)d_in[10];
    const float* WC = (const float*)d_in[11];
    const float* bC = (const float*)d_in[12];
    const float* gn_g = (const float*)d_in[13];
    const float* gn_b = (const float*)d_in[14];
    const float* ge_g = (const float*)d_in[15];
    const float* ge_b = (const float*)d_in[16];

    float* out   = (float*)d_out;
    float* out_x = out;
    float* out_e = out + (size_t)Nn * Dd;

    cudaFuncSetAttribute(node_mma_kernel, cudaFuncAttributeMaxDynamicSharedMemorySize, S_SIZE_N);
    cudaFuncSetAttribute(edge1_kernel, cudaFuncAttributeMaxDynamicSharedMemorySize, S_SIZE_E);

    detect_kernel<<<1, 256>>>((const unsigned*)ei);
    zero_kernel<<<2048, 256>>>();
    prep_w_kernel<<<5, 256>>>(Wu, Wv, WB, WC, WA);
    node_mma_kernel<<<dim3(74, 4), 256, S_SIZE_N>>>(x, bu, bv, bB, bC);
    edge1_kernel<<<444, 256, S_SIZE_E>>>(ea, ei, bA);
    finalize_kernel<<<1, 128>>>(0, 1.0f / (float)Ee);
    edge_pass2_kernel<<<(Ee + 7) / 8, 256>>>(ea, ei, ge_g, ge_b, out_e);
    node_stats_kernel<<<(Nn + 63) / 64, 128>>>();
    finalize_kernel<<<1, 128>>>(1, 1.0f / (float)Nn);
    node_out_kernel<<<(Nn * 32 + 255) / 256, 256>>>(x, gn_g, gn_b, out_x);
}

// round 17
// speedup vs baseline: 1.9592x; 1.0199x over previous
#include <cuda_runtime.h>
#include <cuda_fp16.h>
#include <cstdint>

#define Nn 50000
#define Ee 640000
#define Dd 128

#define ASTRIDE 136              // uint16 elems per row (128 + 8 pad)
#define ROWB    (ASTRIDE * 2)    // 272 bytes per row
#define WPLANE  (128 * ASTRIDE)  // uint16 elems per W plane
#define NT_E    (Ee / 32)        // 20000 edge tiles
#define NT_N    ((Nn + 31) / 32) // 1563 node tiles

// ---------------- device scratch ------------------------------------------
__device__ float g_U[Nn * 128];
__device__ __align__(16) uint16_t g_B[Nn * 128];     // fp16 Bx table
__device__ __align__(16) uint16_t g_CV[Nn * 256];    // fp16 [Cx | Vx] table
__device__ __align__(16) uint16_t g_edge_in[(size_t)Ee * 128]; // fp16 pre-BN edge acts
__device__ float g_agg[Nn * 128];
__device__ float g_stats[1024];
__device__ int g_arrive;
__device__ __align__(16) uint16_t g_Wp[5 * WPLANE];  // fp16 W planes
__device__ int g_is64;

// ---------------- smem layout (bytes) --------------------------------------
#define SB_BIAS 0                 // 512
#define SB_IDX  512               // 64 ints
#define SB_F32  2048              // 2 x 16384 fp32 A staging (cp.async)
#define SB_A    34816             // fp16 A plane 8704
#define SB_ACC  43520             // 32 x 132 fp32 = 16896 (edge only)
#define S_SIZE_N 43520
#define S_SIZE_E 60416

// ---------------- PTX helpers ------------------------------------------------
__device__ __forceinline__ uint32_t smem_u32(const void* p) {
    uint32_t a;
    asm("{ .reg .u64 t; cvta.to.shared.u64 t, %1; cvt.u32.u64 %0, t; }" : "=r"(a) : "l"(p));
    return a;
}
__device__ __forceinline__ void ldsm4(uint32_t& r0, uint32_t& r1, uint32_t& r2,
                                      uint32_t& r3, uint32_t addr) {
    asm volatile("ldmatrix.sync.aligned.m8n8.x4.shared.b16 {%0,%1,%2,%3}, [%4];"
                 : "=r"(r0), "=r"(r1), "=r"(r2), "=r"(r3) : "r"(addr));
}
__device__ __forceinline__ void mma_f16(float* d, uint32_t a0, uint32_t a1,
                                        uint32_t a2, uint32_t a3,
                                        uint32_t b0, uint32_t b1) {
    asm volatile("mma.sync.aligned.m16n8k16.row.col.f32.f16.f16.f32 "
        "{%0,%1,%2,%3}, {%4,%5,%6,%7}, {%8,%9}, {%0,%1,%2,%3};"
        : "+f"(d[0]), "+f"(d[1]), "+f"(d[2]), "+f"(d[3])
        : "r"(a0), "r"(a1), "r"(a2), "r"(a3), "r"(b0), "r"(b1));
}
__device__ __forceinline__ void cp_async16(uint32_t saddr, const void* gptr) {
    asm volatile("cp.async.cg.shared.global [%0], [%1], 16;" :: "r"(saddr), "l"(gptr));
}
#define CP_COMMIT() asm volatile("cp.async.commit_group;" ::: "memory")
#define CP_WAIT0()  asm volatile("cp.async.wait_group 0;" ::: "memory")

__device__ __forceinline__ float4 h4_to_f4(uint2 pk) {
    float2 a = __half22float2(*(__half2*)&pk.x);
    float2 b = __half22float2(*(__half2*)&pk.y);
    return make_float4(a.x, a.y, b.x, b.y);
}

__device__ __forceinline__ void cpa_tile(uint32_t sdst, const float* __restrict__ src,
                                         int valid_rows) {
#pragma unroll
    for (int p = 0; p < 4; p++) {
        int idx = p * 256 + threadIdx.x;
        int row = idx >> 5;
        const float4* g = (const float4*)src + (row < valid_rows ? idx : (idx & 31));
        cp_async16(sdst + idx * 16, g);
    }
}
__device__ __forceinline__ void cvt_half(uint16_t* __restrict__ dst,
                                         const float* __restrict__ srcf) {
#pragma unroll
    for (int p = 0; p < 4; p++) {
        int idx = p * 256 + threadIdx.x;
        int row = idx >> 5, k4 = (idx & 31) << 2;
        float4 v = ((const float4*)srcf)[idx];
        __half2 h0 = __floats2half2_rn(v.x, v.y);
        __half2 h1 = __floats2half2_rn(v.z, v.w);
        uint2 u;
        u.x = *(uint32_t*)&h0;
        u.y = *(uint32_t*)&h1;
        *(uint2*)(dst + row * ASTRIDE + k4) = u;
    }
}
__device__ __forceinline__ int ld_idx(const void* p, size_t i, int is64) {
    return is64 ? (int)((const long long*)p)[i] : ((const int*)p)[i];
}

__device__ __forceinline__ void load_wregs_hi(char* sm, uint32_t smb, int mtx,
                                              int wid, int lane, uint32_t bh[8][4]) {
    const uint32_t woffs = smb + SB_F32
        + (uint32_t)(wid * 16 + (lane & 7) + ((lane >> 4) << 3)) * ROWB
        + (((lane >> 3) & 1) << 4);
    uint4* d = (uint4*)(sm + SB_F32);
    const uint4* s = (const uint4*)(g_Wp + (size_t)mtx * WPLANE);
    for (int i = threadIdx.x; i < 2176; i += 256) d[i] = s[i];
    __syncthreads();
#pragma unroll
    for (int ks = 0; ks < 8; ks++)
        ldsm4(bh[ks][0], bh[ks][1], bh[ks][2], bh[ks][3], woffs + ks * 32);
    __syncthreads();
}

__device__ __forceinline__ void mma_tile1(uint32_t a_base, const uint32_t bh[8][4],
                                          int lane, float acc1[2][2][4]) {
#pragma unroll
    for (int mg = 0; mg < 2; mg++)
#pragma unroll
        for (int j = 0; j < 2; j++)
#pragma unroll
            for (int q = 0; q < 4; q++) acc1[mg][j][q] = 0.f;
    const uint32_t aoff = (uint32_t)(lane & 15) * ROWB + ((lane >> 4) << 4);
#pragma unroll
    for (int ks = 0; ks < 8; ks++) {
#pragma unroll
        for (int mg = 0; mg < 2; mg++) {
            uint32_t a0, a1, a2, a3;
            ldsm4(a0, a1, a2, a3, a_base + aoff + mg * 16 * ROWB + ks * 32);
            mma_f16(acc1[mg][0], a0, a1, a2, a3, bh[ks][0], bh[ks][1]);
            mma_f16(acc1[mg][1], a0, a1, a2, a3, bh[ks][2], bh[ks][3]);
        }
    }
}
__device__ __forceinline__ void dump_acc1(float* sacc, const float acc[2][2][4],
                                          int wid, int lane) {
    const int gid = lane >> 2, tig = lane & 3;
    const int nb = wid * 16;
#pragma unroll
    for (int mg = 0; mg < 2; mg++) {
        int r = mg * 16 + gid;
#pragma unroll
        for (int j = 0; j < 2; j++) {
            int c = nb + j * 8 + tig * 2;
            *(float2*)(sacc + r * 132 + c) = make_float2(acc[mg][j][0], acc[mg][j][1]);
            *(float2*)(sacc + (r + 8) * 132 + c) = make_float2(acc[mg][j][2], acc[mg][j][3]);
        }
    }
}

// ---------------- small kernels -----------------------------------------------
__global__ void detect_kernel(const unsigned* __restrict__ w) {
    __shared__ int sflag;
    if (threadIdx.x == 0) sflag = 0;
    __syncthreads();
    unsigned v = 0;
    for (int i = threadIdx.x; i < 2048; i += blockDim.x) v |= w[2 * i + 1];
    if (v) atomicOr(&sflag, 1);
    __syncthreads();
    if (threadIdx.x == 0) g_is64 = sflag ? 0 : 1;
}
__global__ void zero_kernel() {
    int i = blockIdx.x * blockDim.x + threadIdx.x;
    const int total = Nn * 128;
    for (int k = i; k < total; k += gridDim.x * blockDim.x) g_agg[k] = 0.f;
    if (i < 1024) g_stats[i] = 0.f;
    if (i == 0) g_arrive = 0;
}
__global__ void prep_w_kernel(const float* __restrict__ Wu, const float* __restrict__ Wv,
                              const float* __restrict__ WB, const float* __restrict__ WC,
                              const float* __restrict__ WA) {
    int mtx = blockIdx.x;
    const float* W = (mtx == 0) ? Wu : (mtx == 1) ? Wv : (mtx == 2) ? WB : (mtx == 3) ? WC : WA;
    uint16_t* hi = g_Wp + (size_t)mtx * WPLANE;
    for (int idx = threadIdx.x; idx < 16384; idx += blockDim.x) {
        int f = idx >> 7, k = idx & 127;
        hi[f * ASTRIDE + k] = __half_as_ushort(__float2half_rn(W[idx]));
    }
}

// ---------------- node GEMMs: persistent, cp.async pipelined, 1-term ----------------
__global__ void __launch_bounds__(256, 2) node_mma_kernel(
        const float* __restrict__ x, const float* __restrict__ bu,
        const float* __restrict__ bv, const float* __restrict__ bB,
        const float* __restrict__ bC) {
    extern __shared__ char sm[];
    uint32_t smb = smem_u32(sm);
    const int tid = threadIdx.x, wid = tid >> 5, lane = tid & 31;
    const int which = blockIdx.y;
    float* sb = (float*)(sm + SB_BIAS);
    const float* bias = (which == 0) ? bu : (which == 1) ? bv : (which == 2) ? bB : bC;
    if (tid < 128) sb[tid] = bias[tid];

    uint32_t bh[8][4];
    load_wregs_hi(sm, smb, which, wid, lane, bh);

    uint16_t* dsth = (which == 1) ? g_CV + 128 : (which == 2) ? g_B : g_CV;
    const int rstride = (which == 0 || which == 2) ? 128 : 256;

    const int gid = lane >> 2, tig = lane & 3;
    const int nb = wid * 16;

    long t = blockIdx.x;
    if (t < NT_N) {
        int v0 = Nn - (int)t * 32; if (v0 > 32) v0 = 32;
        cpa_tile(smb + SB_F32, x + t * 4096, v0);
    }
    CP_COMMIT();
    int ib = 0;
    for (; t < NT_N; t += gridDim.x) {
        CP_WAIT0();
        __syncthreads();
        cvt_half((uint16_t*)(sm + SB_A), (const float*)(sm + SB_F32 + ib * 16384));
        long tn = t + gridDim.x;
        if (tn < NT_N) {
            int vn = Nn - (int)tn * 32; if (vn > 32) vn = 32;
            cpa_tile(smb + SB_F32 + (ib ^ 1) * 16384, x + tn * 4096, vn);
        }
        CP_COMMIT();
        __syncthreads();
        float acc1[2][2][4];
        mma_tile1(smb + SB_A, bh, lane, acc1);
#pragma unroll
        for (int mg = 0; mg < 2; mg++) {
            const int r0 = (int)t * 32 + mg * 16 + gid;
#pragma unroll
            for (int j = 0; j < 2; j++) {
                int c = nb + j * 8 + tig * 2;
                float2 bb = *(const float2*)(sb + c);
                float v0x = acc1[mg][j][0] + bb.x;
                float v0y = acc1[mg][j][1] + bb.y;
                float v1x = acc1[mg][j][2] + bb.x;
                float v1y = acc1[mg][j][3] + bb.y;
                if (which == 0) {
                    if (r0 < Nn)
                        *(float2*)(g_U + (size_t)r0 * 128 + c) = make_float2(v0x, v0y);
                    if (r0 + 8 < Nn)
                        *(float2*)(g_U + (size_t)(r0 + 8) * 128 + c) = make_float2(v1x, v1y);
                } else {
                    if (r0 < Nn) {
                        __half2 h = __floats2half2_rn(v0x, v0y);
                        *(uint32_t*)(dsth + (size_t)r0 * rstride + c) = *(uint32_t*)&h;
                    }
                    if (r0 + 8 < Nn) {
                        __half2 h = __floats2half2_rn(v1x, v1y);
                        *(uint32_t*)(dsth + (size_t)(r0 + 8) * rstride + c) = *(uint32_t*)&h;
                    }
                }
            }
        }
        ib ^= 1;
    }
}

// ---------------- edge pass 1: 1-term GEMM + fp16 gathers + BN stats, 3 CTAs/SM ------
__global__ void __launch_bounds__(256, 3) edge1_kernel(
        const float* __restrict__ ea, const void* __restrict__ eidx,
        const float* __restrict__ bA) {
    extern __shared__ char sm[];
    uint32_t smb = smem_u32(sm);
    const int tid = threadIdx.x, wid = tid >> 5, lane = tid & 31;
    const int is64 = g_is64;
    float* sb = (float*)(sm + SB_BIAS);
    int* sidx = (int*)(sm + SB_IDX);
    float* sacc = (float*)(sm + SB_ACC);
    if (tid < 128) sb[tid] = bA[tid];

    uint32_t bh[8][4];
    load_wregs_hi(sm, smb, 4, wid, lane, bh);   // ends with syncthreads

    const float4 bias4 = *(const float4*)(sb + lane * 4);
    float s1[4] = {0.f, 0.f, 0.f, 0.f};
    float s2[4] = {0.f, 0.f, 0.f, 0.f};

    long t = blockIdx.x;
    int idxreg = 0;
    if (t < NT_E) {
        cpa_tile(smb + SB_F32, ea + t * 4096, 32);
        if (tid < 64)
            idxreg = ld_idx(eidx, (tid < 32) ? (t * 32 + tid)
                                             : ((size_t)Ee + t * 32 + (tid - 32)), is64);
    }
    CP_COMMIT();
    int ib = 0;
    for (; t < NT_E; t += gridDim.x) {
        CP_WAIT0();
        __syncthreads();
        if (tid < 64) sidx[tid] = idxreg;
        cvt_half((uint16_t*)(sm + SB_A), (const float*)(sm + SB_F32 + ib * 16384));
        long tn = t + gridDim.x;
        if (tn < NT_E) {
            cpa_tile(smb + SB_F32 + (ib ^ 1) * 16384, ea + tn * 4096, 32);
            if (tid < 64)
                idxreg = ld_idx(eidx, (tid < 32) ? (tn * 32 + tid)
                                                 : ((size_t)Ee + tn * 32 + (tid - 32)), is64);
        }
        CP_COMMIT();
        __syncthreads();
        float acc1[2][2][4];
        mma_tile1(smb + SB_A, bh, lane, acc1);
        dump_acc1(sacc, acc1, wid, lane);
        __syncthreads();

#pragma unroll
        for (int k = 0; k < 4; k++) {
            int r = wid * 4 + k;
            int ridx = sidx[r], cidx = sidx[32 + r];
            float4 a = *(const float4*)(sacc + r * 132 + lane * 4);
            float4 b = h4_to_f4(*(const uint2*)(g_B + (size_t)ridx * 128 + lane * 4));
            float4 cg = h4_to_f4(*(const uint2*)(g_CV + (size_t)cidx * 256 + lane * 4));
            float4 v;
            v.x = a.x + bias4.x + b.x + cg.x;
            v.y = a.y + bias4.y + b.y + cg.y;
            v.z = a.z + bias4.z + b.z + cg.z;
            v.w = a.w + bias4.w + b.w + cg.w;
            __half2 p0 = __floats2half2_rn(v.x, v.y);
            __half2 p1 = __floats2half2_rn(v.z, v.w);
            uint2 pk;
            pk.x = *(uint32_t*)&p0;
            pk.y = *(uint32_t*)&p1;
            *(uint2*)(g_edge_in + (t * 32 + r) * 128 + lane * 4) = pk;
            s1[0] += v.x; s2[0] = fmaf(v.x, v.x, s2[0]);
            s1[1] += v.y; s2[1] = fmaf(v.y, v.y, s2[1]);
            s1[2] += v.z; s2[2] = fmaf(v.z, v.z, s2[2]);
            s1[3] += v.w; s2[3] = fmaf(v.w, v.w, s2[3]);
        }
        ib ^= 1;
    }
    __syncthreads();
#pragma unroll
    for (int q = 0; q < 4; q++) {
        sacc[wid * 128 + lane * 4 + q] = s1[q];
        sacc[1024 + wid * 128 + lane * 4 + q] = s2[q];
    }
    __syncthreads();
    if (tid < 128) {
        float a = 0.f, b = 0.f;
#pragma unroll
        for (int w = 0; w < 8; w++) {
            a += sacc[w * 128 + tid];
            b += sacc[1024 + w * 128 + tid];
        }
        atomicAdd(&g_stats[tid], a);
        atomicAdd(&g_stats[128 + tid], b);
    }
}

// ---------------- finalize edge BN stats --------------------------------------------
__global__ void finalize_kernel(int which, float inv) {
    int f = threadIdx.x;
    float s1 = g_stats[which * 256 + f];
    float s2 = g_stats[which * 256 + 128 + f];
    float mean = s1 * inv;
    float var = fmaxf(s2 * inv - mean * mean, 0.f);
    g_stats[512 + which * 256 + f] = mean;
    g_stats[512 + which * 256 + 128 + f] = rsqrtf(var + 1e-5f);
}

// ---------------- edge pass 2: 2 edges per warp ---------------------------------------
__global__ void __launch_bounds__(256) edge_pass2_kernel(
        const float* __restrict__ ea, const void* __restrict__ eidx,
        const float* __restrict__ gam, const float* __restrict__ bet,
        float* __restrict__ out_e) {
    const int e0 = blockIdx.x * 16 + (threadIdx.x >> 5) * 2;
    const int c = (threadIdx.x & 31) * 4;
    int row0, col0, row1, col1;
    if (g_is64) {
        const long long* p = (const long long*)eidx;
        row0 = (int)p[e0];          row1 = (int)p[e0 + 1];
        col0 = (int)p[(size_t)Ee + e0]; col1 = (int)p[(size_t)Ee + e0 + 1];
    } else {
        const int* p = (const int*)eidx;
        row0 = p[e0];      row1 = p[e0 + 1];
        col0 = p[Ee + e0]; col1 = p[Ee + e0 + 1];
    }
    size_t b0 = (size_t)e0 * 128 + c, b1 = b0 + 128;
    uint2 pk0, pk1;
    asm("ld.global.cs.v2.u32 {%0, %1}, [%2];" : "=r"(pk0.x), "=r"(pk0.y) : "l"(g_edge_in + b0));
    asm("ld.global.cs.v2.u32 {%0, %1}, [%2];" : "=r"(pk1.x), "=r"(pk1.y) : "l"(g_edge_in + b1));
    float4 a0, a1;
    asm("ld.global.cs.v4.f32 {%0, %1, %2, %3}, [%4];"
        : "=f"(a0.x), "=f"(a0.y), "=f"(a0.z), "=f"(a0.w) : "l"(ea + b0));
    asm("ld.global.cs.v4.f32 {%0, %1, %2, %3}, [%4];"
        : "=f"(a1.x), "=f"(a1.y), "=f"(a1.z), "=f"(a1.w) : "l"(ea + b1));
    float4 ein0 = h4_to_f4(pk0), ein1 = h4_to_f4(pk1);
    float4 mu = *(const float4*)(g_stats + 512 + c);
    float4 rs = *(const float4*)(g_stats + 640 + c);
    float4 gm = __ldg((const float4*)(gam + c));
    float4 bt = __ldg((const float4*)(bet + c));
    float4 eo0, eo1;
    eo0.x = a0.x + fmaxf(gm.x * (ein0.x - mu.x) * rs.x + bt.x, 0.f);
    eo0.y = a0.y + fmaxf(gm.y * (ein0.y - mu.y) * rs.y + bt.y, 0.f);
    eo0.z = a0.z + fmaxf(gm.z * (ein0.z - mu.z) * rs.z + bt.z, 0.f);
    eo0.w = a0.w + fmaxf(gm.w * (ein0.w - mu.w) * rs.w + bt.w, 0.f);
    eo1.x = a1.x + fmaxf(gm.x * (ein1.x - mu.x) * rs.x + bt.x, 0.f);
    eo1.y = a1.y + fmaxf(gm.y * (ein1.y - mu.y) * rs.y + bt.y, 0.f);
    eo1.z = a1.z + fmaxf(gm.z * (ein1.z - mu.z) * rs.z + bt.z, 0.f);
    eo1.w = a1.w + fmaxf(gm.w * (ein1.w - mu.w) * rs.w + bt.w, 0.f);
    asm volatile("st.global.cs.v4.f32 [%0], {%1, %2, %3, %4};"
                 :: "l"(out_e + b0), "f"(eo0.x), "f"(eo0.y), "f"(eo0.z), "f"(eo0.w) : "memory");
    asm volatile("st.global.cs.v4.f32 [%0], {%1, %2, %3, %4};"
                 :: "l"(out_e + b1), "f"(eo1.x), "f"(eo1.y), "f"(eo1.z), "f"(eo1.w) : "memory");

    float4 v0 = h4_to_f4(*(const uint2*)(g_CV + (size_t)col0 * 256 + 128 + c));
    float4 v1 = h4_to_f4(*(const uint2*)(g_CV + (size_t)col1 * 256 + 128 + c));
    float m0x = v0.x / (1.f + __expf(-eo0.x));
    float m0y = v0.y / (1.f + __expf(-eo0.y));
    float m0z = v0.z / (1.f + __expf(-eo0.z));
    float m0w = v0.w / (1.f + __expf(-eo0.w));
    float m1x = v1.x / (1.f + __expf(-eo1.x));
    float m1y = v1.y / (1.f + __expf(-eo1.y));
    float m1z = v1.z / (1.f + __expf(-eo1.z));
    float m1w = v1.w / (1.f + __expf(-eo1.w));
    asm volatile("red.global.add.v4.f32 [%0], {%1, %2, %3, %4};"
                 :: "l"(g_agg + (size_t)row0 * 128 + c), "f"(m0x), "f"(m0y), "f"(m0z), "f"(m0w) : "memory");
    asm volatile("red.global.add.v4.f32 [%0], {%1, %2, %3, %4};"
                 :: "l"(g_agg + (size_t)row1 * 128 + c), "f"(m1x), "f"(m1y), "f"(m1z), "f"(m1w) : "memory");
}

// ---------------- fused node epilogue: stats + grid sync + output ---------------------
__global__ void __launch_bounds__(256, 2) node_fin_kernel(
        const float* __restrict__ x, const float* __restrict__ gam,
        const float* __restrict__ bet, float* __restrict__ out_x) {
    __shared__ float sred[2048];
    const int tid = threadIdx.x, wid = tid >> 5, lane = tid & 31;
    const int c = lane * 4;
    float s1[4] = {0.f, 0.f, 0.f, 0.f};
    float s2[4] = {0.f, 0.f, 0.f, 0.f};
    for (long r = blockIdx.x * 8 + wid; r < Nn; r += (long)gridDim.x * 8) {
        float4 u = *(const float4*)(g_U + r * 128 + c);
        float4 a = *(const float4*)(g_agg + r * 128 + c);
        float vx = u.x + a.x, vy = u.y + a.y, vz = u.z + a.z, vw = u.w + a.w;
        s1[0] += vx; s2[0] = fmaf(vx, vx, s2[0]);
        s1[1] += vy; s2[1] = fmaf(vy, vy, s2[1]);
        s1[2] += vz; s2[2] = fmaf(vz, vz, s2[2]);
        s1[3] += vw; s2[3] = fmaf(vw, vw, s2[3]);
    }
#pragma unroll
    for (int q = 0; q < 4; q++) {
        sred[wid * 128 + c + q] = s1[q];
        sred[1024 + wid * 128 + c + q] = s2[q];
    }
    __syncthreads();
    if (tid < 128) {
        float a = 0.f, b = 0.f;
#pragma unroll
        for (int w = 0; w < 8; w++) {
            a += sred[w * 128 + tid];
            b += sred[1024 + w * 128 + tid];
        }
        atomicAdd(&g_stats[256 + tid], a);
        atomicAdd(&g_stats[384 + tid], b);
    }
    __syncthreads();
    // grid sync (all 296 blocks co-resident: 2/SM, tiny footprint)
    if (tid == 0) {
        __threadfence();
        atomicAdd(&g_arrive, 1);
        volatile int* p = &g_arrive;
        while (*p < (int)gridDim.x) {}
    }
    __syncthreads();
    __threadfence();
    const float invN = 1.f / (float)Nn;
    float mu_[4], rs_[4];
#pragma unroll
    for (int q = 0; q < 4; q++) {
        float s = __ldcg(&g_stats[256 + c + q]);
        float ss = __ldcg(&g_stats[384 + c + q]);
        float m = s * invN;
        float var = fmaxf(ss * invN - m * m, 0.f);
        mu_[q] = m;
        rs_[q] = rsqrtf(var + 1e-5f);
    }
    float4 gm = __ldg((const float4*)(gam + c));
    float4 bt = __ldg((const float4*)(bet + c));
    for (long r = blockIdx.x * 8 + wid; r < Nn; r += (long)gridDim.x * 8) {
        float4 u = *(const float4*)(g_U + r * 128 + c);
        float4 a = *(const float4*)(g_agg + r * 128 + c);
        float4 xv = __ldg((const float4*)(x + r * 128 + c));
        float4 o;
        o.x = xv.x + fmaxf(gm.x * ((u.x + a.x) - mu_[0]) * rs_[0] + bt.x, 0.f);
        o.y = xv.y + fmaxf(gm.y * ((u.y + a.y) - mu_[1]) * rs_[1] + bt.y, 0.f);
        o.z = xv.z + fmaxf(gm.z * ((u.z + a.z) - mu_[2]) * rs_[2] + bt.z, 0.f);
        o.w = xv.w + fmaxf(gm.w * ((u.w + a.w) - mu_[3]) * rs_[3] + bt.w, 0.f);
        *(float4*)(out_x + r * 128 + c) = o;
    }
}

// ---------------- launch -----------------------------------------------------------------
extern "C" void kernel_launch(void* const* d_in, const int* in_sizes, int n_in,
                              void* d_out, int out_size) {
    (void)in_sizes; (void)n_in; (void)out_size;
    const float* x  = (const float*)d_in[0];
    const void*  ei = d_in[1];
    const float* ea = (const float*)d_in[2];
    const float* Wu = (const float*)d_in[3];
    const float* bu = (const float*)d_in[4];
    const float* Wv = (const float*)d_in[5];
    const float* bv = (const float*)d_in[6];
    const float* WA = (const float*)d_in[7];
    const float* bA = (const float*)d_in[8];
    const float* WB = (const float*)d_in[9];
    const float* bB = (const float*)d_in[10];
    const float* WC = (const float*)d_in[11];
    const float* bC = (const float*)d_in[12];
    const float* gn_g = (const float*)d_in[13];
    const float* gn_b = (const float*)d_in[14];
    const float* ge_g = (const float*)d_in[15];
    const float* ge_b = (const float*)d_in[16];

    float* out   = (float*)d_out;
    float* out_x = out;
    float* out_e = out + (size_t)Nn * Dd;

    cudaFuncSetAttribute(node_mma_kernel, cudaFuncAttributeMaxDynamicSharedMemorySize, S_SIZE_N);
    cudaFuncSetAttribute(edge1_kernel, cudaFuncAttributeMaxDynamicSharedMemorySize, S_SIZE_E);

    detect_kernel<<<1, 256>>>((const unsigned*)ei);
    zero_kernel<<<2048, 256>>>();
    prep_w_kernel<<<5, 256>>>(Wu, Wv, WB, WC, WA);
    node_mma_kernel<<<dim3(74, 4), 256, S_SIZE_N>>>(x, bu, bv, bB, bC);
    edge1_kernel<<<444, 256, S_SIZE_E>>>(ea, ei, bA);
    finalize_kernel<<<1, 128>>>(0, 1.0f / (float)Ee);
    edge_pass2_kernel<<<Ee / 16, 256>>>(ea, ei, ge_g, ge_b, out_e);
    node_fin_kernel<<<296, 256>>>(x, gn_g, gn_b, out_x);
}